// round 5
// baseline (speedup 1.0000x reference)
#include <cuda_runtime.h>
#include <math.h>

#define NPOS 32768
#define NB 2

// ---------------- scratch (device globals) ----------------
__device__ __align__(16) float g_xt [NB*64*NPOS];   // x transposed [B][64][N]; later reused for y2
__device__ __align__(16) float g_qkv[NB*192*NPOS];
__device__ __align__(16) float g_x5 [NB*64*NPOS];   // shortcut
__device__ __align__(16) float g_u  [NB*64*NPOS];
__device__ __align__(16) float g_a  [NB*64*NPOS];
__device__ __align__(16) float g_b  [NB*64*NPOS];
__device__ __align__(16) float g_off[NB*81*NPOS];
__device__ float g_scale[256];
__device__ float g_attn[NB*4*16*16];
__device__ float g_attnsm[NB*4*16*16];
__device__ __align__(16) float g_qkvT[64*192];
__device__ __align__(16) float g_p1T[64*64];
__device__ __align__(16) float g_c1T[64*64];
__device__ __align__(16) float g_p2T[64*64];
__device__ __align__(16) float g_oT [64*64];
__device__ __align__(16) float g_offT[27*64*84];    // [tap][cin][84] (81 padded to 84)
__device__ __align__(16) float g_dwT [27*64*64];    // [tap][cin][cout]

// ---------------- prep ----------------
__global__ void k_trans(const float* __restrict__ w, float* __restrict__ wT, int O) {
    int i = blockIdx.x * 256 + threadIdx.x;
    if (i < O * 64) { int o = i / 64, c = i % 64; wT[c * O + o] = w[i]; }
}
__global__ void k_prep_offT(const float* __restrict__ w) {
    int i = blockIdx.x * 256 + threadIdx.x;
    if (i < 27 * 64 * 84) {
        int j = i % 84, kc = i / 84, c = kc % 64, k = kc / 64;
        g_offT[i] = (j < 81) ? w[(j * 64 + c) * 27 + k] : 0.f;
    }
}
__global__ void k_prep_dwT(const float* __restrict__ w) {
    int i = blockIdx.x * 256 + threadIdx.x;
    if (i < 27 * 64 * 64) {
        int o = i % 64, kc = i / 64, c = kc % 64, k = kc / 64;
        g_dwT[i] = w[(o * 64 + c) * 27 + k];
    }
}
__global__ void k_zero_attn() {
    int i = blockIdx.x * 256 + threadIdx.x;
    if (i < NB * 4 * 16 * 16) g_attn[i] = 0.f;
}

// ---------------- transpose x [B,N,64] -> [B,64,N] ----------------
__global__ void k_transpose_x(const float* __restrict__ x) {
    __shared__ float tile[64][65];
    int b = blockIdx.y; int n0 = blockIdx.x * 64;
    #pragma unroll
    for (int it = 0; it < 16; it++) {
        int idx = it * 256 + threadIdx.x;
        int r = idx >> 6, c = idx & 63;
        tile[c][r] = x[((size_t)b * NPOS + n0 + r) * 64 + c];
    }
    __syncthreads();
    #pragma unroll
    for (int it = 0; it < 16; it++) {
        int idx = it * 256 + threadIdx.x;
        int c = idx >> 6, r = idx & 63;
        g_xt[((size_t)b * 64 + c) * NPOS + n0 + r] = tile[c][r];
    }
}

// ---------------- 1x1 channel conv: in [B,64,N] -> out [B,O,N] ----------------
// EPI: 0 none, 1 gelu, 2 multiply by extra, 3 add extra
template<int O, int EPI>
__global__ void __launch_bounds__(128) k_pointwise(
        const float* __restrict__ in, const float* __restrict__ wT,
        const float* __restrict__ bias, const float* __restrict__ extra,
        float* __restrict__ out) {
    int b = blockIdx.y;
    int n = blockIdx.x * 128 + threadIdx.x;
    const float* inb = in + (size_t)b * 64 * NPOS + n;
    float xv[64];
    #pragma unroll
    for (int c = 0; c < 64; c++) xv[c] = inb[(size_t)c * NPOS];
    #pragma unroll 1
    for (int oc = 0; oc < O / 16; oc++) {
        float acc[16];
        #pragma unroll
        for (int j = 0; j < 16; j++) acc[j] = bias ? bias[oc * 16 + j] : 0.f;
        #pragma unroll
        for (int c = 0; c < 64; c++) {
            float xc = xv[c];
            const float4* w4 = (const float4*)(wT + c * O + oc * 16);
            #pragma unroll
            for (int q = 0; q < 4; q++) {
                float4 w = w4[q];
                acc[q*4+0] += w.x * xc; acc[q*4+1] += w.y * xc;
                acc[q*4+2] += w.z * xc; acc[q*4+3] += w.w * xc;
            }
        }
        #pragma unroll
        for (int j = 0; j < 16; j++) {
            float v = acc[j];
            int o = oc * 16 + j;
            if (EPI == 1) v = 0.5f * v * (1.f + erff(v * 0.70710678118654752f));
            else if (EPI == 2) v *= extra[((size_t)b * 64 + o) * NPOS + n];
            else if (EPI == 3) v += extra[((size_t)b * 64 + o) * NPOS + n];
            out[((size_t)b * O + o) * NPOS + n] = v;
        }
    }
}

// ---------------- per-channel 1/||.|| for q,k ----------------
__global__ void k_sumsq() {
    int id = blockIdx.x;               // [which][b][c]
    int which = id >> 7, b = (id >> 6) & 1, c = id & 63;
    const float* p = g_qkv + ((size_t)b * 192 + which * 64 + c) * NPOS;
    float ss = 0.f;
    for (int i = threadIdx.x; i < NPOS; i += 256) { float v = p[i]; ss += v * v; }
    __shared__ float red[256];
    red[threadIdx.x] = ss; __syncthreads();
    for (int st = 128; st; st >>= 1) {
        if (threadIdx.x < st) red[threadIdx.x] += red[threadIdx.x + st];
        __syncthreads();
    }
    if (threadIdx.x == 0) g_scale[id] = 1.f / fmaxf(sqrtf(red[0]), 1e-12f);
}

// ---------------- gram q.k^T (partial over 256-chunks, atomic) ----------------
__global__ void k_gram() {
    int bh = blockIdx.y; int b = bh >> 2, h = bh & 3;
    int n0 = blockIdx.x * 256;
    __shared__ float qt[16 * 257], kt[16 * 257];
    #pragma unroll
    for (int it = 0; it < 16; it++) {
        qt[it * 257 + threadIdx.x] =
            g_qkv[((size_t)b * 192 + h * 16 + it) * NPOS + n0 + threadIdx.x];
        kt[it * 257 + threadIdx.x] =
            g_qkv[((size_t)b * 192 + 64 + h * 16 + it) * NPOS + n0 + threadIdx.x];
    }
    __syncthreads();
    int i = threadIdx.x >> 4, j = threadIdx.x & 15;
    float acc = 0.f;
    #pragma unroll 8
    for (int nn = 0; nn < 256; nn++) acc += qt[i * 257 + nn] * kt[j * 257 + nn];
    atomicAdd(&g_attn[(bh * 16 + i) * 16 + j], acc);
}

// ---------------- scale + temperature + softmax ----------------
__global__ void k_softmax(const float* __restrict__ temp) {
    int r = threadIdx.x;               // (b,h,i)
    int b = r >> 6, h = (r >> 4) & 3, i = r & 15;
    float sq = g_scale[b * 64 + h * 16 + i];
    float t = temp[h];
    float v[16], m = -1e30f;
    #pragma unroll
    for (int j = 0; j < 16; j++) {
        float sk = g_scale[128 + b * 64 + h * 16 + j];
        v[j] = g_attn[r * 16 + j] * sq * sk * t;
        m = fmaxf(m, v[j]);
    }
    float s = 0.f;
    #pragma unroll
    for (int j = 0; j < 16; j++) { v[j] = expf(v[j] - m); s += v[j]; }
    float inv = 1.f / s;
    #pragma unroll
    for (int j = 0; j < 16; j++) g_attnsm[r * 16 + j] = v[j] * inv;
}

// ---------------- x_ca = attn@v, LN1, -> x5 [B,64,N] ----------------
__global__ void __launch_bounds__(128) k_xca_ln(const float* __restrict__ nw,
                                                const float* __restrict__ nb) {
    int b = blockIdx.y;
    int n = blockIdx.x * 128 + threadIdx.x;
    float acc[64];
    #pragma unroll
    for (int c = 0; c < 64; c++) acc[c] = 0.f;
    #pragma unroll 1
    for (int h = 0; h < 4; h++) {
        const float* vb = g_qkv + ((size_t)b * 192 + 128 + h * 16) * NPOS + n;
        const float* ab = g_attnsm + (b * 4 + h) * 256;
        #pragma unroll 1
        for (int j = 0; j < 16; j++) {
            float vv = vb[(size_t)j * NPOS];
            #pragma unroll
            for (int i = 0; i < 16; i++) acc[h * 16 + i] += ab[i * 16 + j] * vv;
        }
    }
    float mean = 0.f;
    #pragma unroll
    for (int c = 0; c < 64; c++) mean += acc[c];
    mean *= (1.f / 64.f);
    float var = 0.f;
    #pragma unroll
    for (int c = 0; c < 64; c++) { float d = acc[c] - mean; var += d * d; }
    float rs = rsqrtf(var * (1.f / 64.f) + 1e-5f);
    #pragma unroll
    for (int c = 0; c < 64; c++)
        g_x5[((size_t)b * 64 + c) * NPOS + n] = (acc[c] - mean) * rs * nw[c] + nb[c];
}

// ---------------- depthwise 3D conv ----------------
template<int K, int DIL, int PAD>
__global__ void k_dwconv(const float* __restrict__ in, const float* __restrict__ w,
                         const float* __restrict__ bias, float* __restrict__ out) {
    int bc = blockIdx.y;
    int s = blockIdx.x * 256 + threadIdx.x;
    int z = s >> 10, y = (s >> 5) & 31, x = s & 31;
    const float* inp = in + (size_t)bc * NPOS;
    const float* wc = w + (bc & 63) * K * K * K;
    float acc = bias[bc & 63];
    #pragma unroll 1
    for (int kz = 0; kz < K; kz++) {
        int zz = z + kz * DIL - PAD;
        if ((unsigned)zz >= 32u) continue;
        #pragma unroll 1
        for (int ky = 0; ky < K; ky++) {
            int yy = y + ky * DIL - PAD;
            if ((unsigned)yy >= 32u) continue;
            const float* row = inp + zz * 1024 + yy * 32;
            const float* wrow = wc + (kz * K + ky) * K;
            #pragma unroll
            for (int kx = 0; kx < K; kx++) {
                int xx = x + kx * DIL - PAD;
                float v = ((unsigned)xx < 32u) ? row[xx] : 0.f;
                acc += wrow[kx] * v;
            }
        }
    }
    out[(size_t)bc * NPOS + s] = acc;
}

// ---------------- offsets conv: 64 -> 81, 3^3, pad 1 (reads g_b) ----------------
__global__ void __launch_bounds__(128) k_offconv(const float* __restrict__ bias) {
    int b = blockIdx.y;
    int n = blockIdx.x * 128 + threadIdx.x;
    int z = n >> 10, y = (n >> 5) & 31, x = n & 31;
    float acc[84];
    #pragma unroll
    for (int j = 0; j < 84; j++) acc[j] = (j < 81) ? bias[j] : 0.f;
    #pragma unroll 1
    for (int k = 0; k < 27; k++) {
        int zz = z + k / 9 - 1, yy = y + (k / 3) % 3 - 1, xx = x + k % 3 - 1;
        if ((unsigned)zz >= 32u || (unsigned)yy >= 32u || (unsigned)xx >= 32u) continue;
        const float* ib = g_b + (size_t)b * 64 * NPOS + zz * 1024 + yy * 32 + xx;
        const float* wb = g_offT + k * 64 * 84;
        #pragma unroll 1
        for (int c = 0; c < 64; c++) {
            float v = ib[(size_t)c * NPOS];
            const float4* w4 = (const float4*)(wb + c * 84);
            #pragma unroll
            for (int q = 0; q < 21; q++) {
                float4 w = w4[q];
                acc[q*4+0] += w.x * v; acc[q*4+1] += w.y * v;
                acc[q*4+2] += w.z * v; acc[q*4+3] += w.w * v;
            }
        }
    }
    #pragma unroll
    for (int j = 0; j < 81; j++)
        g_off[((size_t)b * 81 + j) * NPOS + n] = acc[j];
}

// ---------------- deformable conv (reads g_b, g_off; writes g_a) ----------------
__global__ void __launch_bounds__(128) k_dcn(const float* __restrict__ bias) {
    int b = blockIdx.y;
    int n = blockIdx.x * 128 + threadIdx.x;
    int z = n >> 10, y = (n >> 5) & 31, x = n & 31;
    float acc[64];
    #pragma unroll
    for (int o = 0; o < 64; o++) acc[o] = bias[o];
    const float* offp = g_off + (size_t)b * 81 * NPOS + n;
    const float* inp = g_b + (size_t)b * 64 * NPOS;
    #pragma unroll 1
    for (int k = 0; k < 27; k++) {
        float pz = (float)(z + k / 9 - 1)     + offp[(size_t)(k * 3 + 0) * NPOS];
        float py = (float)(y + (k / 3) % 3 - 1) + offp[(size_t)(k * 3 + 1) * NPOS];
        float px = (float)(x + k % 3 - 1)     + offp[(size_t)(k * 3 + 2) * NPOS];
        float fz = floorf(pz), fy = floorf(py), fx = floorf(px);
        float wz = pz - fz, wy = py - fy, wx = px - fx;
        int iz = (int)fz, iy = (int)fy, ix = (int)fx;
        float cw[8]; int ci[8];
        #pragma unroll
        for (int m = 0; m < 8; m++) {
            int az = iz + (m >> 2), ay = iy + ((m >> 1) & 1), ax = ix + (m & 1);
            bool ok = ((unsigned)az < 32u) && ((unsigned)ay < 32u) && ((unsigned)ax < 32u);
            float w = ((m >> 2) ? wz : 1.f - wz) * (((m >> 1) & 1) ? wy : 1.f - wy)
                      * ((m & 1) ? wx : 1.f - wx);
            cw[m] = ok ? w : 0.f;
            ci[m] = (min(max(az,0),31) * 32 + min(max(ay,0),31)) * 32 + min(max(ax,0),31);
        }
        const float* wb = g_dwT + k * 64 * 64;
        #pragma unroll 1
        for (int c = 0; c < 64; c++) {
            const float* ic = inp + (size_t)c * NPOS;
            float v = 0.f;
            #pragma unroll
            for (int m = 0; m < 8; m++) v += cw[m] * ic[ci[m]];
            const float4* w4 = (const float4*)(wb + c * 64);
            #pragma unroll
            for (int q = 0; q < 16; q++) {
                float4 w = w4[q];
                acc[q*4+0] += w.x * v; acc[q*4+1] += w.y * v;
                acc[q*4+2] += w.z * v; acc[q*4+3] += w.w * v;
            }
        }
    }
    #pragma unroll
    for (int o = 0; o < 64; o++) g_a[((size_t)b * 64 + o) * NPOS + n] = acc[o];
}

// ---------------- final: permuted gather + LN2 + out matvec (reads g_xt) ----------------
__global__ void __launch_bounds__(128) k_final(const float* __restrict__ w2,
        const float* __restrict__ b2, const float* __restrict__ ob,
        float* __restrict__ out) {
    int bc = blockIdx.y; int b = bc >> 6, c = bc & 63;
    int s = blockIdx.x * 128 + threadIdx.x;
    const float* yp = g_xt + (size_t)bc * NPOS;
    float r[64], mean = 0.f;
    #pragma unroll
    for (int j = 0; j < 64; j++) { r[j] = yp[j * 512 + s]; mean += r[j]; }
    mean *= (1.f / 64.f);
    float var = 0.f;
    #pragma unroll
    for (int j = 0; j < 64; j++) { float d = r[j] - mean; var += d * d; }
    float rs = rsqrtf(var * (1.f / 64.f) + 1e-5f);
    float acc[64];
    #pragma unroll
    for (int o = 0; o < 64; o++) acc[o] = ob[o];
    #pragma unroll 1
    for (int j = 0; j < 64; j++) {
        float v = (r[j] - mean) * rs * w2[j] + b2[j];
        const float4* w4 = (const float4*)(g_oT + j * 64);
        #pragma unroll
        for (int q = 0; q < 16; q++) {
            float4 w = w4[q];
            acc[q*4+0] += w.x * v; acc[q*4+1] += w.y * v;
            acc[q*4+2] += w.z * v; acc[q*4+3] += w.w * v;
        }
    }
    float4* op = (float4*)(out + ((size_t)b * NPOS + c + 64 * s) * 64);
    #pragma unroll
    for (int q = 0; q < 16; q++)
        op[q] = make_float4(acc[q*4], acc[q*4+1], acc[q*4+2], acc[q*4+3]);
}

// ---------------- launch ----------------
extern "C" void kernel_launch(void* const* d_in, const int* in_sizes, int n_in,
                              void* d_out, int out_size) {
    const float* x     = (const float*)d_in[0];
    const float* temp  = (const float*)d_in[1];
    const float* qkv_w = (const float*)d_in[2];
    const float* nw    = (const float*)d_in[3];
    const float* nb    = (const float*)d_in[4];
    const float* p1w   = (const float*)d_in[5];
    const float* p1b   = (const float*)d_in[6];
    const float* c0w   = (const float*)d_in[7];
    const float* c0b   = (const float*)d_in[8];
    const float* cspw  = (const float*)d_in[9];
    const float* cspb  = (const float*)d_in[10];
    const float* offw  = (const float*)d_in[11];
    const float* offb  = (const float*)d_in[12];
    const float* dcnw  = (const float*)d_in[13];
    const float* dcnb  = (const float*)d_in[14];
    const float* c1w   = (const float*)d_in[15];
    const float* c1b   = (const float*)d_in[16];
    const float* p2w   = (const float*)d_in[17];
    const float* p2b   = (const float*)d_in[18];
    const float* n2w   = (const float*)d_in[19];
    const float* n2b   = (const float*)d_in[20];
    const float* ow    = (const float*)d_in[21];
    const float* obias = (const float*)d_in[22];
    float* out = (float*)d_out;

    float *xt, *qkv, *x5, *u, *a, *bb, *qkvT, *p1T, *c1T, *p2T, *oT;
    cudaGetSymbolAddress((void**)&xt,  g_xt);
    cudaGetSymbolAddress((void**)&qkv, g_qkv);
    cudaGetSymbolAddress((void**)&x5,  g_x5);
    cudaGetSymbolAddress((void**)&u,   g_u);
    cudaGetSymbolAddress((void**)&a,   g_a);
    cudaGetSymbolAddress((void**)&bb,  g_b);
    cudaGetSymbolAddress((void**)&qkvT,g_qkvT);
    cudaGetSymbolAddress((void**)&p1T, g_p1T);
    cudaGetSymbolAddress((void**)&c1T, g_c1T);
    cudaGetSymbolAddress((void**)&p2T, g_p2T);
    cudaGetSymbolAddress((void**)&oT,  g_oT);

    // weight prep
    k_trans<<<48, 256>>>(qkv_w, qkvT, 192);
    k_trans<<<16, 256>>>(p1w, p1T, 64);
    k_trans<<<16, 256>>>(c1w, c1T, 64);
    k_trans<<<16, 256>>>(p2w, p2T, 64);
    k_trans<<<16, 256>>>(ow,  oT,  64);
    k_prep_offT<<<(27*64*84 + 255)/256, 256>>>(offw);
    k_prep_dwT<<<(27*64*64 + 255)/256, 256>>>(dcnw);
    k_zero_attn<<<8, 256>>>();

    // channel attention
    k_transpose_x<<<dim3(512, NB), 256>>>(x);
    k_pointwise<192, 0><<<dim3(256, NB), 128>>>(xt, qkvT, nullptr, nullptr, qkv);
    k_sumsq<<<256, 256>>>();
    k_gram<<<dim3(128, NB * 4), 256>>>();
    k_softmax<<<1, 128>>>(temp);
    k_xca_ln<<<dim3(256, NB), 128>>>(nw, nb);

    // LKA branch
    k_pointwise<64, 1><<<dim3(256, NB), 128>>>(x5, p1T, p1b, nullptr, u);
    k_dwconv<5, 1, 2><<<dim3(128, NB * 64), 256>>>(u, c0w, c0b, a);
    k_dwconv<7, 3, 9><<<dim3(128, NB * 64), 256>>>(a, cspw, cspb, bb);
    k_offconv<<<dim3(256, NB), 128>>>(offb);
    k_dcn<<<dim3(256, NB), 128>>>(dcnb);
    k_pointwise<64, 2><<<dim3(256, NB), 128>>>(a, c1T, c1b, u, bb);   // conv1 * u
    k_pointwise<64, 3><<<dim3(256, NB), 128>>>(bb, p2T, p2b, x5, xt); // proj2 + shortcut

    // permute + LN2 + output projection
    k_final<<<dim3(4, NB * 64), 128>>>(n2w, n2b, obias, out);
}

// round 7
// speedup vs baseline: 1.4142x; 1.4142x over previous
#include <cuda_runtime.h>
#include <mma.h>
#include <math.h>

using namespace nvcuda;

#define NPOS 32768
#define NB 2

// ---------------- scratch (device globals) ----------------
__device__ __align__(16) float g_xt [NB*64*NPOS];   // x transposed [B][64][N]; later reused for y2
__device__ __align__(16) float g_qkv[NB*192*NPOS];
__device__ __align__(16) float g_x5 [NB*64*NPOS];   // shortcut
__device__ __align__(16) float g_u  [NB*64*NPOS];
__device__ __align__(16) float g_a  [NB*64*NPOS];
__device__ __align__(16) float g_b  [NB*64*NPOS];
__device__ __align__(16) float g_bcl[NB*64*NPOS];   // channels-last copy of g_b: [B][N][64]
__device__ __align__(16) float g_off[NB*96*NPOS];   // 81 rows used, padded to 96 for wmma stores
__device__ float g_scale[256];
__device__ float g_attn[NB*4*16*16];
__device__ float g_attnsm[NB*4*16*16];
__device__ __align__(16) float g_qkvT[64*192];
__device__ __align__(16) float g_p1T[64*64];
__device__ __align__(16) float g_c1T[64*64];
__device__ __align__(16) float g_p2T[64*64];
__device__ __align__(16) float g_oT [64*64];
__device__ __align__(16) float g_offW[27*96*64];    // [tap][o(96, zero-padded>=81)][c]
__device__ __align__(16) float g_dcnW[27*64*64];    // [tap][o][c]
__device__ float g_c1bf[64];                        // conv1 bias with dcn bias folded in

// ---------------- prep ----------------
__global__ void k_trans(const float* __restrict__ w, float* __restrict__ wT, int O) {
    int i = blockIdx.x * 256 + threadIdx.x;
    if (i < O * 64) { int o = i / 64, c = i % 64; wT[c * O + o] = w[i]; }
}
__global__ void k_prep_offW(const float* __restrict__ w) {
    int i = blockIdx.x * 256 + threadIdx.x;
    if (i < 27 * 96 * 64) {
        int c = i & 63, o = (i >> 6) % 96, k = i / (96 * 64);
        g_offW[i] = (o < 81) ? w[(o * 64 + c) * 27 + k] : 0.f;
    }
}
__global__ void k_prep_dcnW(const float* __restrict__ w) {
    int i = blockIdx.x * 256 + threadIdx.x;
    if (i < 27 * 64 * 64) {
        int c = i & 63, o = (i >> 6) & 63, k = i >> 12;
        g_dcnW[i] = w[(o * 64 + c) * 27 + k];
    }
}
__global__ void k_fold_c1b(const float* __restrict__ c1w, const float* __restrict__ c1b,
                           const float* __restrict__ dcnb) {
    int o = threadIdx.x;
    float s = c1b[o];
    for (int c = 0; c < 64; c++) s += c1w[o * 64 + c] * dcnb[c];
    g_c1bf[o] = s;
}
__global__ void k_zero_attn() {
    int i = blockIdx.x * 256 + threadIdx.x;
    if (i < NB * 4 * 16 * 16) g_attn[i] = 0.f;
}

// ---------------- transpose x [B,N,64] -> [B,64,N] ----------------
__global__ void k_transpose_x(const float* __restrict__ x) {
    __shared__ float tile[64][65];
    int b = blockIdx.y; int n0 = blockIdx.x * 64;
    #pragma unroll
    for (int it = 0; it < 16; it++) {
        int idx = it * 256 + threadIdx.x;
        int r = idx >> 6, c = idx & 63;
        tile[c][r] = x[((size_t)b * NPOS + n0 + r) * 64 + c];
    }
    __syncthreads();
    #pragma unroll
    for (int it = 0; it < 16; it++) {
        int idx = it * 256 + threadIdx.x;
        int c = idx >> 6, r = idx & 63;
        g_xt[((size_t)b * 64 + c) * NPOS + n0 + r] = tile[c][r];
    }
}

// ---------------- transpose [B,64,N] -> channels-last [B,N,64] ----------------
__global__ void k_to_cl(const float* __restrict__ in, float* __restrict__ out) {
    __shared__ float tile[64][65];
    int b = blockIdx.y; int n0 = blockIdx.x * 64;
    #pragma unroll
    for (int it = 0; it < 16; it++) {
        int idx = it * 256 + threadIdx.x;
        int c = idx >> 6, r = idx & 63;                 // coalesced read along n
        tile[r][c] = in[((size_t)b * 64 + c) * NPOS + n0 + r];
    }
    __syncthreads();
    #pragma unroll
    for (int it = 0; it < 16; it++) {
        int idx = it * 256 + threadIdx.x;
        int r = idx >> 6, c = idx & 63;                 // coalesced write along c
        out[((size_t)b * NPOS + n0 + r) * 64 + c] = tile[r][c];
    }
}

// ---------------- 1x1 channel conv: in [B,64,N] -> out [B,O,N] ----------------
// EPI: 0 none, 1 gelu, 2 multiply by extra, 3 add extra
template<int O, int EPI>
__global__ void __launch_bounds__(128) k_pointwise(
        const float* __restrict__ in, const float* __restrict__ wT,
        const float* __restrict__ bias, const float* __restrict__ extra,
        float* __restrict__ out) {
    int b = blockIdx.y;
    int n = blockIdx.x * 128 + threadIdx.x;
    const float* inb = in + (size_t)b * 64 * NPOS + n;
    float xv[64];
    #pragma unroll
    for (int c = 0; c < 64; c++) xv[c] = inb[(size_t)c * NPOS];
    #pragma unroll 1
    for (int oc = 0; oc < O / 16; oc++) {
        float acc[16];
        #pragma unroll
        for (int j = 0; j < 16; j++) acc[j] = bias ? bias[oc * 16 + j] : 0.f;
        #pragma unroll
        for (int c = 0; c < 64; c++) {
            float xc = xv[c];
            const float4* w4 = (const float4*)(wT + c * O + oc * 16);
            #pragma unroll
            for (int q = 0; q < 4; q++) {
                float4 w = w4[q];
                acc[q*4+0] += w.x * xc; acc[q*4+1] += w.y * xc;
                acc[q*4+2] += w.z * xc; acc[q*4+3] += w.w * xc;
            }
        }
        #pragma unroll
        for (int j = 0; j < 16; j++) {
            float v = acc[j];
            int o = oc * 16 + j;
            if (EPI == 1) v = 0.5f * v * (1.f + erff(v * 0.70710678118654752f));
            else if (EPI == 2) v *= extra[((size_t)b * 64 + o) * NPOS + n];
            else if (EPI == 3) v += extra[((size_t)b * 64 + o) * NPOS + n];
            out[((size_t)b * O + o) * NPOS + n] = v;
        }
    }
}

// ---------------- per-channel 1/||.|| for q,k ----------------
__global__ void k_sumsq() {
    int id = blockIdx.x;               // [which][b][c]
    int which = id >> 7, b = (id >> 6) & 1, c = id & 63;
    const float* p = g_qkv + ((size_t)b * 192 + which * 64 + c) * NPOS;
    float ss = 0.f;
    for (int i = threadIdx.x; i < NPOS; i += 256) { float v = p[i]; ss += v * v; }
    __shared__ float red[256];
    red[threadIdx.x] = ss; __syncthreads();
    for (int st = 128; st; st >>= 1) {
        if (threadIdx.x < st) red[threadIdx.x] += red[threadIdx.x + st];
        __syncthreads();
    }
    if (threadIdx.x == 0) g_scale[id] = 1.f / fmaxf(sqrtf(red[0]), 1e-12f);
}

// ---------------- gram q.k^T (partial over 256-chunks, atomic) ----------------
__global__ void k_gram() {
    int bh = blockIdx.y; int b = bh >> 2, h = bh & 3;
    int n0 = blockIdx.x * 256;
    __shared__ float qt[16 * 257], kt[16 * 257];
    #pragma unroll
    for (int it = 0; it < 16; it++) {
        qt[it * 257 + threadIdx.x] =
            g_qkv[((size_t)b * 192 + h * 16 + it) * NPOS + n0 + threadIdx.x];
        kt[it * 257 + threadIdx.x] =
            g_qkv[((size_t)b * 192 + 64 + h * 16 + it) * NPOS + n0 + threadIdx.x];
    }
    __syncthreads();
    int i = threadIdx.x >> 4, j = threadIdx.x & 15;
    float acc = 0.f;
    #pragma unroll 8
    for (int nn = 0; nn < 256; nn++) acc += qt[i * 257 + nn] * kt[j * 257 + nn];
    atomicAdd(&g_attn[(bh * 16 + i) * 16 + j], acc);
}

// ---------------- scale + temperature + softmax ----------------
__global__ void k_softmax(const float* __restrict__ temp) {
    int r = threadIdx.x;               // (b,h,i)
    int b = r >> 6, h = (r >> 4) & 3, i = r & 15;
    float sq = g_scale[b * 64 + h * 16 + i];
    float t = temp[h];
    float v[16], m = -1e30f;
    #pragma unroll
    for (int j = 0; j < 16; j++) {
        float sk = g_scale[128 + b * 64 + h * 16 + j];
        v[j] = g_attn[r * 16 + j] * sq * sk * t;
        m = fmaxf(m, v[j]);
    }
    float s = 0.f;
    #pragma unroll
    for (int j = 0; j < 16; j++) { v[j] = expf(v[j] - m); s += v[j]; }
    float inv = 1.f / s;
    #pragma unroll
    for (int j = 0; j < 16; j++) g_attnsm[r * 16 + j] = v[j] * inv;
}

// ---------------- x_ca = attn@v, LN1, -> x5 [B,64,N] ----------------
__global__ void __launch_bounds__(128) k_xca_ln(const float* __restrict__ nw,
                                                const float* __restrict__ nb) {
    int b = blockIdx.y;
    int n = blockIdx.x * 128 + threadIdx.x;
    float acc[64];
    #pragma unroll
    for (int c = 0; c < 64; c++) acc[c] = 0.f;
    #pragma unroll 1
    for (int h = 0; h < 4; h++) {
        const float* vb = g_qkv + ((size_t)b * 192 + 128 + h * 16) * NPOS + n;
        const float* ab = g_attnsm + (b * 4 + h) * 256;
        #pragma unroll 1
        for (int j = 0; j < 16; j++) {
            float vv = vb[(size_t)j * NPOS];
            #pragma unroll
            for (int i = 0; i < 16; i++) acc[h * 16 + i] += ab[i * 16 + j] * vv;
        }
    }
    float mean = 0.f;
    #pragma unroll
    for (int c = 0; c < 64; c++) mean += acc[c];
    mean *= (1.f / 64.f);
    float var = 0.f;
    #pragma unroll
    for (int c = 0; c < 64; c++) { float d = acc[c] - mean; var += d * d; }
    float rs = rsqrtf(var * (1.f / 64.f) + 1e-5f);
    #pragma unroll
    for (int c = 0; c < 64; c++)
        g_x5[((size_t)b * 64 + c) * NPOS + n] = (acc[c] - mean) * rs * nw[c] + nb[c];
}

// ---------------- depthwise 3D conv ----------------
template<int K, int DIL, int PAD>
__global__ void k_dwconv(const float* __restrict__ in, const float* __restrict__ w,
                         const float* __restrict__ bias, float* __restrict__ out) {
    int bc = blockIdx.y;
    int s = blockIdx.x * 256 + threadIdx.x;
    int z = s >> 10, y = (s >> 5) & 31, x = s & 31;
    const float* inp = in + (size_t)bc * NPOS;
    const float* wc = w + (bc & 63) * K * K * K;
    float acc = bias[bc & 63];
    #pragma unroll 1
    for (int kz = 0; kz < K; kz++) {
        int zz = z + kz * DIL - PAD;
        if ((unsigned)zz >= 32u) continue;
        #pragma unroll 1
        for (int ky = 0; ky < K; ky++) {
            int yy = y + ky * DIL - PAD;
            if ((unsigned)yy >= 32u) continue;
            const float* row = inp + zz * 1024 + yy * 32;
            const float* wrow = wc + (kz * K + ky) * K;
            #pragma unroll
            for (int kx = 0; kx < K; kx++) {
                int xx = x + kx * DIL - PAD;
                float v = ((unsigned)xx < 32u) ? row[xx] : 0.f;
                acc += wrow[kx] * v;
            }
        }
    }
    out[(size_t)bc * NPOS + s] = acc;
}

// ================= wmma tf32 helpers =================
#define SLD 68   // smem row pitch (floats) for S[128][SLD]

__device__ __forceinline__ void cvt_tf32_a(
        wmma::fragment<wmma::matrix_a,16,16,8,wmma::precision::tf32,wmma::row_major>& f) {
    #pragma unroll
    for (int i = 0; i < f.num_elements; i++) f.x[i] = wmma::__float_to_tf32(f.x[i]);
}
__device__ __forceinline__ void cvt_tf32_b(
        wmma::fragment<wmma::matrix_b,16,16,8,wmma::precision::tf32,wmma::col_major>& f) {
    #pragma unroll
    for (int i = 0; i < f.num_elements; i++) f.x[i] = wmma::__float_to_tf32(f.x[i]);
}

// ---------------- offsets conv via wmma: 64 -> 81(96), 3^3, pad 1 ----------------
// reads g_bcl [B][N][64]; writes g_off [B][96][N]
__global__ void __launch_bounds__(256) k_offconv_mma() {
    __shared__ float S[128][SLD];   // S[p][c] : pos-major (wmma matrix_b col_major)
    int b = blockIdx.y;
    int n0 = blockIdx.x * 128;
    int z = n0 >> 10, y0 = (n0 >> 5) & 31;
    int t = threadIdx.x, warp = t >> 5;
    int wm = warp >> 2, wn = warp & 3;   // wm: 48-row strip, wn: 32-col strip

    wmma::fragment<wmma::accumulator,16,16,8,float> acc[3][2];
    #pragma unroll
    for (int mi = 0; mi < 3; mi++)
        #pragma unroll
        for (int ni = 0; ni < 2; ni++) wmma::fill_fragment(acc[mi][ni], 0.f);

    const float4* in4 = (const float4*)g_bcl;

    for (int k = 0; k < 27; k++) {
        int dz = k / 9 - 1, dy = (k / 3) % 3 - 1, dx = k % 3 - 1;
        // fill S: 128 pos x 16 float4-channel-groups
        #pragma unroll
        for (int it = 0; it < 8; it++) {
            int idx = it * 256 + t;
            int p = idx >> 4, c4 = idx & 15;
            int zz = z + dz, yy = y0 + (p >> 5) + dy, xx = (p & 31) + dx;
            float4 v = make_float4(0.f, 0.f, 0.f, 0.f);
            if ((unsigned)zz < 32u && (unsigned)yy < 32u && (unsigned)xx < 32u)
                v = in4[((size_t)b * NPOS + zz * 1024 + yy * 32 + xx) * 16 + c4];
            *(float4*)&S[p][c4 * 4] = v;
        }
        __syncthreads();
        const float* wk = g_dcnW; // placeholder to keep compiler honest (unused)
        (void)wk;
        #pragma unroll 1
        for (int ks = 0; ks < 8; ks++) {
            wmma::fragment<wmma::matrix_a,16,16,8,wmma::precision::tf32,wmma::row_major> af[3];
            wmma::fragment<wmma::matrix_b,16,16,8,wmma::precision::tf32,wmma::col_major> bf[2];
            #pragma unroll
            for (int mi = 0; mi < 3; mi++) {
                wmma::load_matrix_sync(af[mi],
                    g_offW + ((size_t)k * 96 + wm * 48 + mi * 16) * 64 + ks * 8, 64);
                cvt_tf32_a(af[mi]);
            }
            #pragma unroll
            for (int ni = 0; ni < 2; ni++) {
                wmma::load_matrix_sync(bf[ni], &S[wn * 32 + ni * 16][ks * 8], SLD);
                cvt_tf32_b(bf[ni]);
            }
            #pragma unroll
            for (int mi = 0; mi < 3; mi++)
                #pragma unroll
                for (int ni = 0; ni < 2; ni++)
                    wmma::mma_sync(acc[mi][ni], af[mi], bf[ni], acc[mi][ni]);
        }
        __syncthreads();
    }
    #pragma unroll
    for (int mi = 0; mi < 3; mi++)
        #pragma unroll
        for (int ni = 0; ni < 2; ni++) {
            int row = wm * 48 + mi * 16;
            int col = n0 + wn * 32 + ni * 16;
            wmma::store_matrix_sync(g_off + ((size_t)b * 96 + row) * NPOS + col,
                                    acc[mi][ni], NPOS, wmma::mem_row_major);
        }
}

// ---------------- deformable conv via wmma ----------------
// reads g_bcl [B][N][64], g_off [B][96][N]; writes g_a [B][64][N]
__global__ void __launch_bounds__(256) k_dcn_mma(const float* __restrict__ offb) {
    __shared__ float S[128][SLD];
    int b = blockIdx.y;
    int n0 = blockIdx.x * 128;
    int t = threadIdx.x, warp = t >> 5;
    int wm = warp >> 2, wn = warp & 3;   // wm: 32-row strip, wn: 32-col strip
    int p = t & 127, half = t >> 7;      // 2 threads per position for the gather
    int n = n0 + p;
    int z = n >> 10, y = (n >> 5) & 31, x = n & 31;

    wmma::fragment<wmma::accumulator,16,16,8,float> acc[2][2];
    #pragma unroll
    for (int mi = 0; mi < 2; mi++)
        #pragma unroll
        for (int ni = 0; ni < 2; ni++) wmma::fill_fragment(acc[mi][ni], 0.f);

    const float4* in4 = (const float4*)g_bcl + (size_t)b * NPOS * 16;
    const float* offp = g_off + (size_t)b * 96 * NPOS + n;

    for (int k = 0; k < 27; k++) {
        // trilinear corner weights/indices for this position
        float pz = (float)(z + k / 9 - 1)       + offp[(size_t)(k * 3 + 0) * NPOS] + offb[k * 3 + 0];
        float py = (float)(y + (k / 3) % 3 - 1) + offp[(size_t)(k * 3 + 1) * NPOS] + offb[k * 3 + 1];
        float px = (float)(x + k % 3 - 1)       + offp[(size_t)(k * 3 + 2) * NPOS] + offb[k * 3 + 2];
        float fz = floorf(pz), fy = floorf(py), fx = floorf(px);
        float wz = pz - fz, wy = py - fy, wx = px - fx;
        int iz = (int)fz, iy = (int)fy, ix = (int)fx;
        float cw[8]; int ci[8];
        #pragma unroll
        for (int m = 0; m < 8; m++) {
            int az = iz + (m >> 2), ay = iy + ((m >> 1) & 1), ax = ix + (m & 1);
            bool ok = ((unsigned)az < 32u) && ((unsigned)ay < 32u) && ((unsigned)ax < 32u);
            float w = ((m >> 2) ? wz : 1.f - wz) * (((m >> 1) & 1) ? wy : 1.f - wy)
                      * ((m & 1) ? wx : 1.f - wx);
            cw[m] = ok ? w : 0.f;
            ci[m] = (min(max(az,0),31) * 32 + min(max(ay,0),31)) * 32 + min(max(ax,0),31);
        }
        // gather 8 float4 channel-groups (this thread's half of 16)
        #pragma unroll
        for (int q = 0; q < 8; q++) {
            int c4 = half * 8 + q;
            float4 s = make_float4(0.f, 0.f, 0.f, 0.f);
            #pragma unroll
            for (int m = 0; m < 8; m++) {
                float4 v = in4[(size_t)ci[m] * 16 + c4];
                s.x += cw[m] * v.x; s.y += cw[m] * v.y;
                s.z += cw[m] * v.z; s.w += cw[m] * v.w;
            }
            *(float4*)&S[p][c4 * 4] = s;
        }
        __syncthreads();
        #pragma unroll 1
        for (int ks = 0; ks < 8; ks++) {
            wmma::fragment<wmma::matrix_a,16,16,8,wmma::precision::tf32,wmma::row_major> af[2];
            wmma::fragment<wmma::matrix_b,16,16,8,wmma::precision::tf32,wmma::col_major> bf[2];
            #pragma unroll
            for (int mi = 0; mi < 2; mi++) {
                wmma::load_matrix_sync(af[mi],
                    g_dcnW + ((size_t)k * 64 + wm * 32 + mi * 16) * 64 + ks * 8, 64);
                cvt_tf32_a(af[mi]);
            }
            #pragma unroll
            for (int ni = 0; ni < 2; ni++) {
                wmma::load_matrix_sync(bf[ni], &S[wn * 32 + ni * 16][ks * 8], SLD);
                cvt_tf32_b(bf[ni]);
            }
            #pragma unroll
            for (int mi = 0; mi < 2; mi++)
                #pragma unroll
                for (int ni = 0; ni < 2; ni++)
                    wmma::mma_sync(acc[mi][ni], af[mi], bf[ni], acc[mi][ni]);
        }
        __syncthreads();
    }
    #pragma unroll
    for (int mi = 0; mi < 2; mi++)
        #pragma unroll
        for (int ni = 0; ni < 2; ni++) {
            int row = wm * 32 + mi * 16;
            int col = n0 + wn * 32 + ni * 16;
            wmma::store_matrix_sync(g_a + ((size_t)b * 64 + row) * NPOS + col,
                                    acc[mi][ni], NPOS, wmma::mem_row_major);
        }
}

// ---------------- final: permuted gather + LN2 + out matvec (reads g_xt) ----------------
__global__ void __launch_bounds__(128) k_final(const float* __restrict__ w2,
        const float* __restrict__ b2, const float* __restrict__ ob,
        float* __restrict__ out) {
    int bc = blockIdx.y; int b = bc >> 6, c = bc & 63;
    int s = blockIdx.x * 128 + threadIdx.x;
    const float* yp = g_xt + (size_t)bc * NPOS;
    float r[64], mean = 0.f;
    #pragma unroll
    for (int j = 0; j < 64; j++) { r[j] = yp[j * 512 + s]; mean += r[j]; }
    mean *= (1.f / 64.f);
    float var = 0.f;
    #pragma unroll
    for (int j = 0; j < 64; j++) { float d = r[j] - mean; var += d * d; }
    float rs = rsqrtf(var * (1.f / 64.f) + 1e-5f);
    float acc[64];
    #pragma unroll
    for (int o = 0; o < 64; o++) acc[o] = ob[o];
    #pragma unroll 1
    for (int j = 0; j < 64; j++) {
        float v = (r[j] - mean) * rs * w2[j] + b2[j];
        const float4* w4 = (const float4*)(g_oT + j * 64);
        #pragma unroll
        for (int q = 0; q < 16; q++) {
            float4 w = w4[q];
            acc[q*4+0] += w.x * v; acc[q*4+1] += w.y * v;
            acc[q*4+2] += w.z * v; acc[q*4+3] += w.w * v;
        }
    }
    float4* op = (float4*)(out + ((size_t)b * NPOS + c + 64 * s) * 64);
    #pragma unroll
    for (int q = 0; q < 16; q++)
        op[q] = make_float4(acc[q*4], acc[q*4+1], acc[q*4+2], acc[q*4+3]);
}

// ---------------- launch ----------------
extern "C" void kernel_launch(void* const* d_in, const int* in_sizes, int n_in,
                              void* d_out, int out_size) {
    const float* x     = (const float*)d_in[0];
    const float* temp  = (const float*)d_in[1];
    const float* qkv_w = (const float*)d_in[2];
    const float* nw    = (const float*)d_in[3];
    const float* nb    = (const float*)d_in[4];
    const float* p1w   = (const float*)d_in[5];
    const float* p1b   = (const float*)d_in[6];
    const float* c0w   = (const float*)d_in[7];
    const float* c0b   = (const float*)d_in[8];
    const float* cspw  = (const float*)d_in[9];
    const float* cspb  = (const float*)d_in[10];
    const float* offw  = (const float*)d_in[11];
    const float* offb  = (const float*)d_in[12];
    const float* dcnw  = (const float*)d_in[13];
    const float* dcnb  = (const float*)d_in[14];
    const float* c1w   = (const float*)d_in[15];
    const float* c1b   = (const float*)d_in[16];
    const float* p2w   = (const float*)d_in[17];
    const float* p2b   = (const float*)d_in[18];
    const float* n2w   = (const float*)d_in[19];
    const float* n2b   = (const float*)d_in[20];
    const float* ow    = (const float*)d_in[21];
    const float* obias = (const float*)d_in[22];
    float* out = (float*)d_out;

    float *xt, *qkv, *x5, *u, *a, *bb, *bcl, *qkvT, *p1T, *c1T, *p2T, *oT, *c1bf;
    cudaGetSymbolAddress((void**)&xt,  g_xt);
    cudaGetSymbolAddress((void**)&qkv, g_qkv);
    cudaGetSymbolAddress((void**)&x5,  g_x5);
    cudaGetSymbolAddress((void**)&u,   g_u);
    cudaGetSymbolAddress((void**)&a,   g_a);
    cudaGetSymbolAddress((void**)&bb,  g_b);
    cudaGetSymbolAddress((void**)&bcl, g_bcl);
    cudaGetSymbolAddress((void**)&qkvT,g_qkvT);
    cudaGetSymbolAddress((void**)&p1T, g_p1T);
    cudaGetSymbolAddress((void**)&c1T, g_c1T);
    cudaGetSymbolAddress((void**)&p2T, g_p2T);
    cudaGetSymbolAddress((void**)&oT,  g_oT);
    cudaGetSymbolAddress((void**)&c1bf,g_c1bf);

    // weight prep
    k_trans<<<48, 256>>>(qkv_w, qkvT, 192);
    k_trans<<<16, 256>>>(p1w, p1T, 64);
    k_trans<<<16, 256>>>(c1w, c1T, 64);
    k_trans<<<16, 256>>>(p2w, p2T, 64);
    k_trans<<<16, 256>>>(ow,  oT,  64);
    k_prep_offW<<<(27*96*64 + 255)/256, 256>>>(offw);
    k_prep_dcnW<<<(27*64*64 + 255)/256, 256>>>(dcnw);
    k_fold_c1b<<<1, 64>>>(c1w, c1b, dcnb);
    k_zero_attn<<<8, 256>>>();

    // channel attention
    k_transpose_x<<<dim3(512, NB), 256>>>(x);
    k_pointwise<192, 0><<<dim3(256, NB), 128>>>(xt, qkvT, nullptr, nullptr, qkv);
    k_sumsq<<<256, 256>>>();
    k_gram<<<dim3(128, NB * 4), 256>>>();
    k_softmax<<<1, 128>>>(temp);
    k_xca_ln<<<dim3(256, NB), 128>>>(nw, nb);

    // LKA branch
    k_pointwise<64, 1><<<dim3(256, NB), 128>>>(x5, p1T, p1b, nullptr, u);
    k_dwconv<5, 1, 2><<<dim3(128, NB * 64), 256>>>(u, c0w, c0b, a);
    k_dwconv<7, 3, 9><<<dim3(128, NB * 64), 256>>>(a, cspw, cspb, bb);
    k_to_cl<<<dim3(512, NB), 256>>>(bb, bcl);
    k_offconv_mma<<<dim3(256, NB), 256>>>();
    k_dcn_mma<<<dim3(256, NB), 256>>>(offb);
    k_pointwise<64, 2><<<dim3(256, NB), 128>>>(a, c1T, c1bf, u, bb);   // conv1 * u (dcn bias folded)
    k_pointwise<64, 3><<<dim3(256, NB), 128>>>(bb, p2T, p2b, x5, xt);  // proj2 + shortcut

    // permute + LN2 + output projection
    k_final<<<dim3(4, NB * 64), 128>>>(n2w, n2b, obias, out);
}

// round 8
// speedup vs baseline: 1.6840x; 1.1908x over previous
#include <cuda_runtime.h>
#include <mma.h>
#include <math.h>

using namespace nvcuda;

#define NPOS 32768
#define NB 2

// ---------------- scratch (device globals) ----------------
__device__ __align__(16) float g_xt [NB*64*NPOS];   // x transposed; later y2
__device__ __align__(16) float g_qkv[NB*192*NPOS];
__device__ __align__(16) float g_x5 [NB*64*NPOS];   // shortcut
__device__ __align__(16) float g_u  [NB*64*NPOS];
__device__ __align__(16) float g_a  [NB*64*NPOS];
__device__ __align__(16) float g_b  [NB*64*NPOS];
__device__ __align__(16) float g_bcl[NB*64*NPOS];   // channels-last of g_b
__device__ __align__(16) float g_off[NB*96*NPOS];
__device__ float g_scale[256];                      // RAW sum-of-squares (q:0-127, k:128-255)
__device__ float g_attn[NB*4*16*16];                // RAW gram
__device__ __align__(16) float g_qkvT[64*192];
__device__ __align__(16) float g_p1T[64*64];
__device__ __align__(16) float g_c1T[64*64];
__device__ __align__(16) float g_p2T[64*64];
__device__ __align__(16) float g_oT [64*64];
__device__ __align__(16) float g_offW[27*96*64];
__device__ __align__(16) float g_dcnW[27*64*64];
__device__ float g_c1bf[64];

// ---------------- one mega prep kernel ----------------
__global__ void k_prep(const float* __restrict__ qkvw, const float* __restrict__ p1w,
                       const float* __restrict__ c1w, const float* __restrict__ p2w,
                       const float* __restrict__ ow,  const float* __restrict__ offw,
                       const float* __restrict__ dcnw, const float* __restrict__ c1b,
                       const float* __restrict__ dcnb) {
    int i = blockIdx.x * 256 + threadIdx.x;
    if (i < 165888) {                      // offW [27][96][64]
        int c = i & 63, o = (i >> 6) % 96, k = i / (96 * 64);
        g_offW[i] = (o < 81) ? offw[(o * 64 + c) * 27 + k] : 0.f;
        return;
    }
    int j = i - 165888;
    if (j < 110592) {                      // dcnW [27][64][64]
        int c = j & 63, o = (j >> 6) & 63, k = j >> 12;
        g_dcnW[j] = dcnw[(o * 64 + c) * 27 + k];
        return;
    }
    j -= 110592;
    if (j < 12288) { int c = j / 192, o = j % 192; g_qkvT[j] = qkvw[o * 64 + c]; return; }
    j -= 12288;
    if (j < 4096) { int c = j >> 6, o = j & 63; g_p1T[j] = p1w[o * 64 + c]; return; }
    j -= 4096;
    if (j < 4096) { int c = j >> 6, o = j & 63; g_c1T[j] = c1w[o * 64 + c]; return; }
    j -= 4096;
    if (j < 4096) { int c = j >> 6, o = j & 63; g_p2T[j] = p2w[o * 64 + c]; return; }
    j -= 4096;
    if (j < 4096) { int c = j >> 6, o = j & 63; g_oT[j] = ow[o * 64 + c]; return; }
    j -= 4096;
    if (j < 64) {
        float s = c1b[j];
        for (int c = 0; c < 64; c++) s += c1w[j * 64 + c] * dcnb[c];
        g_c1bf[j] = s;
    }
}

// ---------------- transpose x [B,N,64] -> [B,64,N] (+ zero attn/scale) ----------------
__global__ void k_transpose_x(const float* __restrict__ x) {
    if (blockIdx.x == 0 && blockIdx.y == 0) {
        for (int i = threadIdx.x; i < 2048 + 256; i += 256) {
            if (i < 2048) g_attn[i] = 0.f; else g_scale[i - 2048] = 0.f;
        }
    }
    __shared__ float tile[64][65];
    int b = blockIdx.y; int n0 = blockIdx.x * 64;
    #pragma unroll
    for (int it = 0; it < 16; it++) {
        int idx = it * 256 + threadIdx.x;
        int r = idx >> 6, c = idx & 63;
        tile[c][r] = x[((size_t)b * NPOS + n0 + r) * 64 + c];
    }
    __syncthreads();
    #pragma unroll
    for (int it = 0; it < 16; it++) {
        int idx = it * 256 + threadIdx.x;
        int c = idx >> 6, r = idx & 63;
        g_xt[((size_t)b * 64 + c) * NPOS + n0 + r] = tile[c][r];
    }
}

// ---------------- transpose [B,64,N] -> channels-last [B,N,64] ----------------
__global__ void k_to_cl(const float* __restrict__ in, float* __restrict__ out) {
    __shared__ float tile[64][65];
    int b = blockIdx.y; int n0 = blockIdx.x * 64;
    #pragma unroll
    for (int it = 0; it < 16; it++) {
        int idx = it * 256 + threadIdx.x;
        int c = idx >> 6, r = idx & 63;
        tile[r][c] = in[((size_t)b * 64 + c) * NPOS + n0 + r];
    }
    __syncthreads();
    #pragma unroll
    for (int it = 0; it < 16; it++) {
        int idx = it * 256 + threadIdx.x;
        int r = idx >> 6, c = idx & 63;
        out[((size_t)b * NPOS + n0 + r) * 64 + c] = tile[r][c];
    }
}

// ---------------- qkv pointwise: [B,64,N] -> [B,192,N] ----------------
__global__ void __launch_bounds__(128) k_qkv(const float* __restrict__ in,
                                             float* __restrict__ out) {
    int b = blockIdx.y;
    int n = blockIdx.x * 128 + threadIdx.x;
    const float* inb = in + (size_t)b * 64 * NPOS + n;
    float xv[64];
    #pragma unroll
    for (int c = 0; c < 64; c++) xv[c] = inb[(size_t)c * NPOS];
    #pragma unroll 1
    for (int oc = 0; oc < 12; oc++) {
        float acc[16];
        #pragma unroll
        for (int j = 0; j < 16; j++) acc[j] = 0.f;
        #pragma unroll
        for (int c = 0; c < 64; c++) {
            float xc = xv[c];
            const float4* w4 = (const float4*)(g_qkvT + c * 192 + oc * 16);
            #pragma unroll
            for (int q = 0; q < 4; q++) {
                float4 w = w4[q];
                acc[q*4+0] += w.x * xc; acc[q*4+1] += w.y * xc;
                acc[q*4+2] += w.z * xc; acc[q*4+3] += w.w * xc;
            }
        }
        #pragma unroll
        for (int j = 0; j < 16; j++)
            out[((size_t)b * 192 + oc * 16 + j) * NPOS + n] = acc[j];
    }
}

// ---------------- gram q.k^T + raw sumsq (atomics) ----------------
__global__ void k_gram() {
    int bh = blockIdx.y; int b = bh >> 2, h = bh & 3;
    int n0 = blockIdx.x * 256;
    __shared__ float qt[16 * 257], kt[16 * 257];
    #pragma unroll
    for (int it = 0; it < 16; it++) {
        qt[it * 257 + threadIdx.x] =
            g_qkv[((size_t)b * 192 + h * 16 + it) * NPOS + n0 + threadIdx.x];
        kt[it * 257 + threadIdx.x] =
            g_qkv[((size_t)b * 192 + 64 + h * 16 + it) * NPOS + n0 + threadIdx.x];
    }
    __syncthreads();
    int i = threadIdx.x >> 4, j = threadIdx.x & 15;
    float acc = 0.f;
    #pragma unroll 8
    for (int nn = 0; nn < 256; nn++) acc += qt[i * 257 + nn] * kt[j * 257 + nn];
    atomicAdd(&g_attn[(bh * 16 + i) * 16 + j], acc);
    // sum-of-squares partials: thread (cc=i-range) handles channel j, segment i
    float sq = 0.f, sk = 0.f;
    #pragma unroll
    for (int m = 0; m < 16; m++) {
        float a = qt[j * 257 + i * 16 + m]; sq += a * a;
        float bb2 = kt[j * 257 + i * 16 + m]; sk += bb2 * bb2;
    }
    atomicAdd(&g_scale[b * 64 + h * 16 + j], sq);
    atomicAdd(&g_scale[128 + b * 64 + h * 16 + j], sk);
}

// ---------------- softmax(inline) + attn@v + LN1 -> x5, then u=gelu(p1@x5) ----------------
__global__ void __launch_bounds__(128) k_xca_ln_p1(const float* __restrict__ temp,
        const float* __restrict__ nw, const float* __restrict__ nb,
        const float* __restrict__ p1b) {
    int b = blockIdx.y;
    __shared__ float asm_s[4 * 256];
    if (threadIdx.x < 64) {
        int h = threadIdx.x >> 4, i = threadIdx.x & 15;
        float sq = 1.f / fmaxf(sqrtf(g_scale[b * 64 + h * 16 + i]), 1e-12f);
        float t = temp[h];
        float v[16], m = -1e30f;
        #pragma unroll
        for (int j = 0; j < 16; j++) {
            float sk = 1.f / fmaxf(sqrtf(g_scale[128 + b * 64 + h * 16 + j]), 1e-12f);
            v[j] = g_attn[(b * 4 + h) * 256 + i * 16 + j] * sq * sk * t;
            m = fmaxf(m, v[j]);
        }
        float s = 0.f;
        #pragma unroll
        for (int j = 0; j < 16; j++) { v[j] = expf(v[j] - m); s += v[j]; }
        float inv = 1.f / s;
        #pragma unroll
        for (int j = 0; j < 16; j++) asm_s[h * 256 + i * 16 + j] = v[j] * inv;
    }
    __syncthreads();

    int n = blockIdx.x * 128 + threadIdx.x;
    float acc[64];
    #pragma unroll
    for (int c = 0; c < 64; c++) acc[c] = 0.f;
    #pragma unroll 1
    for (int h = 0; h < 4; h++) {
        const float* vb = g_qkv + ((size_t)b * 192 + 128 + h * 16) * NPOS + n;
        const float* ab = asm_s + h * 256;
        #pragma unroll 1
        for (int j = 0; j < 16; j++) {
            float vv = vb[(size_t)j * NPOS];
            #pragma unroll
            for (int i = 0; i < 16; i++) acc[h * 16 + i] += ab[i * 16 + j] * vv;
        }
    }
    float mean = 0.f;
    #pragma unroll
    for (int c = 0; c < 64; c++) mean += acc[c];
    mean *= (1.f / 64.f);
    float var = 0.f;
    #pragma unroll
    for (int c = 0; c < 64; c++) { float d = acc[c] - mean; var += d * d; }
    float rs = rsqrtf(var * (1.f / 64.f) + 1e-5f);
    #pragma unroll
    for (int c = 0; c < 64; c++) {
        acc[c] = (acc[c] - mean) * rs * nw[c] + nb[c];
        g_x5[((size_t)b * 64 + c) * NPOS + n] = acc[c];
    }
    // u = gelu(p1 @ x5)
    #pragma unroll 1
    for (int oc = 0; oc < 4; oc++) {
        float a2[16];
        #pragma unroll
        for (int j = 0; j < 16; j++) a2[j] = p1b[oc * 16 + j];
        #pragma unroll
        for (int c = 0; c < 64; c++) {
            float xc = acc[c];
            const float4* w4 = (const float4*)(g_p1T + c * 64 + oc * 16);
            #pragma unroll
            for (int q = 0; q < 4; q++) {
                float4 w = w4[q];
                a2[q*4+0] += w.x * xc; a2[q*4+1] += w.y * xc;
                a2[q*4+2] += w.z * xc; a2[q*4+3] += w.w * xc;
            }
        }
        #pragma unroll
        for (int j = 0; j < 16; j++) {
            float v = a2[j];
            v = 0.5f * v * (1.f + erff(v * 0.70710678118654752f));
            g_u[((size_t)b * 64 + oc * 16 + j) * NPOS + n] = v;
        }
    }
}

// ---------------- dw5: k=5, dil=1, pad=2; 8 z-outputs per thread ----------------
__global__ void __launch_bounds__(256) k_dw5(const float* __restrict__ in,
        const float* __restrict__ w, const float* __restrict__ bias,
        float* __restrict__ out) {
    __shared__ float ws[125];
    int bc = blockIdx.y, c = bc & 63;
    for (int i = threadIdx.x; i < 125; i += 256) ws[i] = w[c * 125 + i];
    __syncthreads();
    int task = blockIdx.x * 256 + threadIdx.x;          // 4096 tasks
    int g = task >> 10, yx = task & 1023;
    int y = yx >> 5, x = yx & 31;
    int z0 = g * 8;
    const float* inp = in + (size_t)bc * NPOS;
    float bv = bias[c];
    float acc[8];
    #pragma unroll
    for (int j = 0; j < 8; j++) acc[j] = bv;
    #pragma unroll 1
    for (int ky = 0; ky < 5; ky++) {
        int yy = y + ky - 2; if ((unsigned)yy >= 32u) continue;
        #pragma unroll 1
        for (int kx = 0; kx < 5; kx++) {
            int xx = x + kx - 2; if ((unsigned)xx >= 32u) continue;
            const float* col = inp + yy * 32 + xx;
            float vals[12];
            #pragma unroll
            for (int t = 0; t < 12; t++) {
                int zz = z0 + t - 2;
                vals[t] = ((unsigned)zz < 32u) ? col[zz * 1024] : 0.f;
            }
            float wc[5];
            #pragma unroll
            for (int kz = 0; kz < 5; kz++) wc[kz] = ws[(kz * 5 + ky) * 5 + kx];
            #pragma unroll
            for (int j = 0; j < 8; j++)
                #pragma unroll
                for (int kz = 0; kz < 5; kz++)
                    acc[j] += wc[kz] * vals[j + kz];
        }
    }
    #pragma unroll
    for (int j = 0; j < 8; j++)
        out[(size_t)bc * NPOS + (z0 + j) * 1024 + y * 32 + x] = acc[j];
}

// ---------------- dw7: k=7, dil=3, pad=9; mod-3 z-lattice column per thread ----------------
__global__ void __launch_bounds__(256) k_dw7(const float* __restrict__ in,
        const float* __restrict__ w, const float* __restrict__ bias,
        float* __restrict__ out) {
    __shared__ float ws[343];
    int bc = blockIdx.y, c = bc & 63;
    for (int i = threadIdx.x; i < 343; i += 256) ws[i] = w[c * 343 + i];
    __syncthreads();
    int task = blockIdx.x * 256 + threadIdx.x;          // 3072 tasks
    int r = task >> 10, yx = task & 1023;
    int y = yx >> 5, x = yx & 31;
    int nz = (r == 2) ? 10 : 11;                        // z = r + 3j
    const float* inp = in + (size_t)bc * NPOS;
    float bv = bias[c];
    float acc[11];
    #pragma unroll
    for (int j = 0; j < 11; j++) acc[j] = bv;
    #pragma unroll 1
    for (int ky = 0; ky < 7; ky++) {
        int yy = y + ky * 3 - 9; if ((unsigned)yy >= 32u) continue;
        #pragma unroll 1
        for (int kx = 0; kx < 7; kx++) {
            int xx = x + kx * 3 - 9; if ((unsigned)xx >= 32u) continue;
            const float* col = inp + yy * 32 + xx;
            float vals[17];                              // m = t-3, z' = r+3m
            #pragma unroll
            for (int t = 0; t < 17; t++) {
                int m = t - 3;
                vals[t] = (m >= 0 && m < nz) ? col[(r + 3 * m) * 1024] : 0.f;
            }
            float wc[7];
            #pragma unroll
            for (int kz = 0; kz < 7; kz++) wc[kz] = ws[(kz * 7 + ky) * 7 + kx];
            #pragma unroll
            for (int j = 0; j < 11; j++)
                #pragma unroll
                for (int kz = 0; kz < 7; kz++)
                    acc[j] += wc[kz] * vals[j + kz];     // z' = r+3(j+kz-3)
        }
    }
    #pragma unroll
    for (int j = 0; j < 11; j++)
        if (j < nz) out[(size_t)bc * NPOS + (r + 3 * j) * 1024 + y * 32 + x] = acc[j];
}

// ================= wmma tf32 =================
#define SLD 68

__device__ __forceinline__ void cvt_tf32_a(
        wmma::fragment<wmma::matrix_a,16,16,8,wmma::precision::tf32,wmma::row_major>& f) {
    #pragma unroll
    for (int i = 0; i < f.num_elements; i++) f.x[i] = wmma::__float_to_tf32(f.x[i]);
}
__device__ __forceinline__ void cvt_tf32_b(
        wmma::fragment<wmma::matrix_b,16,16,8,wmma::precision::tf32,wmma::col_major>& f) {
    #pragma unroll
    for (int i = 0; i < f.num_elements; i++) f.x[i] = wmma::__float_to_tf32(f.x[i]);
}

// ---------------- offsets conv via wmma ----------------
__global__ void __launch_bounds__(256) k_offconv_mma() {
    __shared__ float S[128][SLD];
    int b = blockIdx.y;
    int n0 = blockIdx.x * 128;
    int z = n0 >> 10, y0 = (n0 >> 5) & 31;
    int t = threadIdx.x, warp = t >> 5;
    int wm = warp >> 2, wn = warp & 3;

    wmma::fragment<wmma::accumulator,16,16,8,float> acc[3][2];
    #pragma unroll
    for (int mi = 0; mi < 3; mi++)
        #pragma unroll
        for (int ni = 0; ni < 2; ni++) wmma::fill_fragment(acc[mi][ni], 0.f);

    const float4* in4 = (const float4*)g_bcl;

    for (int k = 0; k < 27; k++) {
        int dz = k / 9 - 1, dy = (k / 3) % 3 - 1, dx = k % 3 - 1;
        #pragma unroll
        for (int it = 0; it < 8; it++) {
            int idx = it * 256 + t;
            int p = idx >> 4, c4 = idx & 15;
            int zz = z + dz, yy = y0 + (p >> 5) + dy, xx = (p & 31) + dx;
            float4 v = make_float4(0.f, 0.f, 0.f, 0.f);
            if ((unsigned)zz < 32u && (unsigned)yy < 32u && (unsigned)xx < 32u)
                v = in4[((size_t)b * NPOS + zz * 1024 + yy * 32 + xx) * 16 + c4];
            *(float4*)&S[p][c4 * 4] = v;
        }
        __syncthreads();
        #pragma unroll 1
        for (int ks = 0; ks < 8; ks++) {
            wmma::fragment<wmma::matrix_a,16,16,8,wmma::precision::tf32,wmma::row_major> af[3];
            wmma::fragment<wmma::matrix_b,16,16,8,wmma::precision::tf32,wmma::col_major> bf[2];
            #pragma unroll
            for (int mi = 0; mi < 3; mi++) {
                wmma::load_matrix_sync(af[mi],
                    g_offW + ((size_t)k * 96 + wm * 48 + mi * 16) * 64 + ks * 8, 64);
                cvt_tf32_a(af[mi]);
            }
            #pragma unroll
            for (int ni = 0; ni < 2; ni++) {
                wmma::load_matrix_sync(bf[ni], &S[wn * 32 + ni * 16][ks * 8], SLD);
                cvt_tf32_b(bf[ni]);
            }
            #pragma unroll
            for (int mi = 0; mi < 3; mi++)
                #pragma unroll
                for (int ni = 0; ni < 2; ni++)
                    wmma::mma_sync(acc[mi][ni], af[mi], bf[ni], acc[mi][ni]);
        }
        __syncthreads();
    }
    #pragma unroll
    for (int mi = 0; mi < 3; mi++)
        #pragma unroll
        for (int ni = 0; ni < 2; ni++)
            wmma::store_matrix_sync(g_off + ((size_t)b * 96 + wm * 48 + mi * 16) * NPOS
                                    + n0 + wn * 32 + ni * 16,
                                    acc[mi][ni], NPOS, wmma::mem_row_major);
}

// ---------------- deformable conv via wmma ----------------
__global__ void __launch_bounds__(256) k_dcn_mma(const float* __restrict__ offb) {
    __shared__ float S[128][SLD];
    int b = blockIdx.y;
    int n0 = blockIdx.x * 128;
    int t = threadIdx.x, warp = t >> 5;
    int wm = warp >> 2, wn = warp & 3;
    int p = t & 127, half = t >> 7;
    int n = n0 + p;
    int z = n >> 10, y = (n >> 5) & 31, x = n & 31;

    wmma::fragment<wmma::accumulator,16,16,8,float> acc[2][2];
    #pragma unroll
    for (int mi = 0; mi < 2; mi++)
        #pragma unroll
        for (int ni = 0; ni < 2; ni++) wmma::fill_fragment(acc[mi][ni], 0.f);

    const float4* in4 = (const float4*)g_bcl + (size_t)b * NPOS * 16;
    const float* offp = g_off + (size_t)b * 96 * NPOS + n;

    for (int k = 0; k < 27; k++) {
        float pz = (float)(z + k / 9 - 1)       + offp[(size_t)(k * 3 + 0) * NPOS] + offb[k * 3 + 0];
        float py = (float)(y + (k / 3) % 3 - 1) + offp[(size_t)(k * 3 + 1) * NPOS] + offb[k * 3 + 1];
        float px = (float)(x + k % 3 - 1)       + offp[(size_t)(k * 3 + 2) * NPOS] + offb[k * 3 + 2];
        float fz = floorf(pz), fy = floorf(py), fx = floorf(px);
        float wz = pz - fz, wy = py - fy, wx = px - fx;
        int iz = (int)fz, iy = (int)fy, ix = (int)fx;
        float cw[8]; int ci[8];
        #pragma unroll
        for (int m = 0; m < 8; m++) {
            int az = iz + (m >> 2), ay = iy + ((m >> 1) & 1), ax = ix + (m & 1);
            bool ok = ((unsigned)az < 32u) && ((unsigned)ay < 32u) && ((unsigned)ax < 32u);
            float w = ((m >> 2) ? wz : 1.f - wz) * (((m >> 1) & 1) ? wy : 1.f - wy)
                      * ((m & 1) ? wx : 1.f - wx);
            cw[m] = ok ? w : 0.f;
            ci[m] = (min(max(az,0),31) * 32 + min(max(ay,0),31)) * 32 + min(max(ax,0),31);
        }
        #pragma unroll
        for (int q = 0; q < 8; q++) {
            int c4 = half * 8 + q;
            float4 s = make_float4(0.f, 0.f, 0.f, 0.f);
            #pragma unroll
            for (int m = 0; m < 8; m++) {
                float4 v = in4[(size_t)ci[m] * 16 + c4];
                s.x += cw[m] * v.x; s.y += cw[m] * v.y;
                s.z += cw[m] * v.z; s.w += cw[m] * v.w;
            }
            *(float4*)&S[p][c4 * 4] = s;
        }
        __syncthreads();
        #pragma unroll 1
        for (int ks = 0; ks < 8; ks++) {
            wmma::fragment<wmma::matrix_a,16,16,8,wmma::precision::tf32,wmma::row_major> af[2];
            wmma::fragment<wmma::matrix_b,16,16,8,wmma::precision::tf32,wmma::col_major> bf[2];
            #pragma unroll
            for (int mi = 0; mi < 2; mi++) {
                wmma::load_matrix_sync(af[mi],
                    g_dcnW + ((size_t)k * 64 + wm * 32 + mi * 16) * 64 + ks * 8, 64);
                cvt_tf32_a(af[mi]);
            }
            #pragma unroll
            for (int ni = 0; ni < 2; ni++) {
                wmma::load_matrix_sync(bf[ni], &S[wn * 32 + ni * 16][ks * 8], SLD);
                cvt_tf32_b(bf[ni]);
            }
            #pragma unroll
            for (int mi = 0; mi < 2; mi++)
                #pragma unroll
                for (int ni = 0; ni < 2; ni++)
                    wmma::mma_sync(acc[mi][ni], af[mi], bf[ni], acc[mi][ni]);
        }
        __syncthreads();
    }
    #pragma unroll
    for (int mi = 0; mi < 2; mi++)
        #pragma unroll
        for (int ni = 0; ni < 2; ni++)
            wmma::store_matrix_sync(g_a + ((size_t)b * 64 + wm * 32 + mi * 16) * NPOS
                                    + n0 + wn * 32 + ni * 16,
                                    acc[mi][ni], NPOS, wmma::mem_row_major);
}

// ---------------- fused: y2 = p2 @ ((c1 @ a) * u) + x5  -> g_xt ----------------
__global__ void __launch_bounds__(128) k_c1p2(const float* __restrict__ p2b) {
    int b = blockIdx.y;
    int n = blockIdx.x * 128 + threadIdx.x;
    const float* ap = g_a + (size_t)b * 64 * NPOS + n;
    float av[64];
    #pragma unroll
    for (int c = 0; c < 64; c++) av[c] = ap[(size_t)c * NPOS];
    float tv[64];
    #pragma unroll
    for (int o = 0; o < 64; o++) tv[o] = g_c1bf[o];
    #pragma unroll
    for (int c = 0; c < 64; c++) {
        float xc = av[c];
        const float4* w4 = (const float4*)(g_c1T + c * 64);
        #pragma unroll
        for (int q = 0; q < 16; q++) {
            float4 w = w4[q];
            tv[q*4+0] += w.x * xc; tv[q*4+1] += w.y * xc;
            tv[q*4+2] += w.z * xc; tv[q*4+3] += w.w * xc;
        }
    }
    const float* up = g_u + (size_t)b * 64 * NPOS + n;
    #pragma unroll
    for (int o = 0; o < 64; o++) tv[o] *= up[(size_t)o * NPOS];
    float acc[64];
    #pragma unroll
    for (int o = 0; o < 64; o++) acc[o] = p2b[o];
    #pragma unroll
    for (int c = 0; c < 64; c++) {
        float xc = tv[c];
        const float4* w4 = (const float4*)(g_p2T + c * 64);
        #pragma unroll
        for (int q = 0; q < 16; q++) {
            float4 w = w4[q];
            acc[q*4+0] += w.x * xc; acc[q*4+1] += w.y * xc;
            acc[q*4+2] += w.z * xc; acc[q*4+3] += w.w * xc;
        }
    }
    const float* sp = g_x5 + (size_t)b * 64 * NPOS + n;
    #pragma unroll
    for (int o = 0; o < 64; o++)
        g_xt[((size_t)b * 64 + o) * NPOS + n] = acc[o] + sp[(size_t)o * NPOS];
}

// ---------------- final: permuted gather + LN2 + out matvec ----------------
__global__ void __launch_bounds__(128) k_final(const float* __restrict__ w2,
        const float* __restrict__ b2, const float* __restrict__ ob,
        float* __restrict__ out) {
    int bc = blockIdx.y; int b = bc >> 6, c = bc & 63;
    int s = blockIdx.x * 128 + threadIdx.x;
    const float* yp = g_xt + (size_t)bc * NPOS;
    float r[64], mean = 0.f;
    #pragma unroll
    for (int j = 0; j < 64; j++) { r[j] = yp[j * 512 + s]; mean += r[j]; }
    mean *= (1.f / 64.f);
    float var = 0.f;
    #pragma unroll
    for (int j = 0; j < 64; j++) { float d = r[j] - mean; var += d * d; }
    float rs = rsqrtf(var * (1.f / 64.f) + 1e-5f);
    float acc[64];
    #pragma unroll
    for (int o = 0; o < 64; o++) acc[o] = ob[o];
    #pragma unroll 1
    for (int j = 0; j < 64; j++) {
        float v = (r[j] - mean) * rs * w2[j] + b2[j];
        const float4* w4 = (const float4*)(g_oT + j * 64);
        #pragma unroll
        for (int q = 0; q < 16; q++) {
            float4 w = w4[q];
            acc[q*4+0] += w.x * v; acc[q*4+1] += w.y * v;
            acc[q*4+2] += w.z * v; acc[q*4+3] += w.w * v;
        }
    }
    float4* op = (float4*)(out + ((size_t)b * NPOS + c + 64 * s) * 64);
    #pragma unroll
    for (int q = 0; q < 16; q++)
        op[q] = make_float4(acc[q*4], acc[q*4+1], acc[q*4+2], acc[q*4+3]);
}

// ---------------- launch ----------------
extern "C" void kernel_launch(void* const* d_in, const int* in_sizes, int n_in,
                              void* d_out, int out_size) {
    const float* x     = (const float*)d_in[0];
    const float* temp  = (const float*)d_in[1];
    const float* qkv_w = (const float*)d_in[2];
    const float* nw    = (const float*)d_in[3];
    const float* nb    = (const float*)d_in[4];
    const float* p1w   = (const float*)d_in[5];
    const float* p1b   = (const float*)d_in[6];
    const float* c0w   = (const float*)d_in[7];
    const float* c0b   = (const float*)d_in[8];
    const float* cspw  = (const float*)d_in[9];
    const float* cspb  = (const float*)d_in[10];
    const float* offw  = (const float*)d_in[11];
    const float* offb  = (const float*)d_in[12];
    const float* dcnw  = (const float*)d_in[13];
    const float* dcnb  = (const float*)d_in[14];
    const float* c1w   = (const float*)d_in[15];
    const float* c1b   = (const float*)d_in[16];
    const float* p2w   = (const float*)d_in[17];
    const float* p2b   = (const float*)d_in[18];
    const float* n2w   = (const float*)d_in[19];
    const float* n2b   = (const float*)d_in[20];
    const float* ow    = (const float*)d_in[21];
    const float* obias = (const float*)d_in[22];
    float* out = (float*)d_out;

    float *xt, *qkv, *u, *a, *bb, *bcl;
    cudaGetSymbolAddress((void**)&xt,  g_xt);
    cudaGetSymbolAddress((void**)&qkv, g_qkv);
    cudaGetSymbolAddress((void**)&u,   g_u);
    cudaGetSymbolAddress((void**)&a,   g_a);
    cudaGetSymbolAddress((void**)&bb,  g_b);
    cudaGetSymbolAddress((void**)&bcl, g_bcl);

    // 1: all weight prep in one kernel (305216 elements)
    k_prep<<<1193, 256>>>(qkv_w, p1w, c1w, p2w, ow, offw, dcnw, c1b, dcnb);
    // 2: transpose x (+ zero attn/scale)
    k_transpose_x<<<dim3(512, NB), 256>>>(x);
    // 3: qkv projection
    k_qkv<<<dim3(256, NB), 128>>>(xt, qkv);
    // 4: gram + sumsq
    k_gram<<<dim3(128, NB * 4), 256>>>();
    // 5: softmax + attn@v + LN1 + proj1/gelu
    k_xca_ln_p1<<<dim3(256, NB), 128>>>(temp, nw, nb, p1b);
    // 6: depthwise 5^3  (ncu -s 5 captures this one)
    k_dw5<<<dim3(16, NB * 64), 256>>>(u, c0w, c0b, a);
    // 7: depthwise 7^3 dil 3
    k_dw7<<<dim3(12, NB * 64), 256>>>(a, cspw, cspb, bb);
    // 8: channels-last copy
    k_to_cl<<<dim3(512, NB), 256>>>(bb, bcl);
    // 9-10: offsets conv + deformable conv (tensor cores)
    k_offconv_mma<<<dim3(256, NB), 256>>>();
    k_dcn_mma<<<dim3(256, NB), 256>>>(offb);
    // 11: conv1*u then proj2+shortcut fused
    k_c1p2<<<dim3(256, NB), 128>>>(p2b);
    // 12: permute + LN2 + output projection
    k_final<<<dim3(4, NB * 64), 128>>>(n2w, n2b, obias, out);
}

// round 9
// speedup vs baseline: 2.5122x; 1.4918x over previous
#include <cuda_runtime.h>
#include <cuda_bf16.h>
#include <mma.h>
#include <math.h>

using namespace nvcuda;

#define NPOS 32768
#define NB 2

// ---------------- scratch (device globals) ----------------
__device__ __align__(16) float g_xt [NB*64*NPOS];   // x transposed; later y2
__device__ __align__(16) float g_qkv[NB*192*NPOS];
__device__ __align__(16) float g_x5 [NB*64*NPOS];   // shortcut
__device__ __align__(16) float g_u  [NB*64*NPOS];
__device__ __align__(16) float g_a  [NB*64*NPOS];
__device__ __align__(16) float g_b  [NB*64*NPOS];
__device__ __align__(16) __nv_bfloat16 g_bclh[NB*64*NPOS];  // channels-last bf16 of g_b
__device__ __align__(16) float g_off[NB*96*NPOS];
__device__ float g_scale[256];                      // RAW sum-of-squares
__device__ float g_attn[NB*4*16*16];                // RAW gram
__device__ __align__(16) float g_qkvT[64*192];
__device__ __align__(16) float g_p1T[64*64];
__device__ __align__(16) float g_c1T[64*64];
__device__ __align__(16) float g_p2T[64*64];
__device__ __align__(16) float g_oT [64*64];
__device__ __align__(16) __nv_bfloat16 g_offWh[27*96*64];   // bf16 [tap][o][c]
__device__ __align__(16) __nv_bfloat16 g_dcnWh[27*64*64];   // bf16 [tap][o][c]
__device__ float g_c1bf[64];

// ---------------- one mega prep kernel ----------------
__global__ void k_prep(const float* __restrict__ qkvw, const float* __restrict__ p1w,
                       const float* __restrict__ c1w, const float* __restrict__ p2w,
                       const float* __restrict__ ow,  const float* __restrict__ offw,
                       const float* __restrict__ dcnw, const float* __restrict__ c1b,
                       const float* __restrict__ dcnb) {
    int i = blockIdx.x * 256 + threadIdx.x;
    if (i < 165888) {                      // offWh [27][96][64]
        int c = i & 63, o = (i >> 6) % 96, k = i / (96 * 64);
        g_offWh[i] = __float2bfloat16((o < 81) ? offw[(o * 64 + c) * 27 + k] : 0.f);
        return;
    }
    int j = i - 165888;
    if (j < 110592) {                      // dcnWh [27][64][64]
        int c = j & 63, o = (j >> 6) & 63, k = j >> 12;
        g_dcnWh[j] = __float2bfloat16(dcnw[(o * 64 + c) * 27 + k]);
        return;
    }
    j -= 110592;
    if (j < 12288) { int c = j / 192, o = j % 192; g_qkvT[j] = qkvw[o * 64 + c]; return; }
    j -= 12288;
    if (j < 4096) { int c = j >> 6, o = j & 63; g_p1T[j] = p1w[o * 64 + c]; return; }
    j -= 4096;
    if (j < 4096) { int c = j >> 6, o = j & 63; g_c1T[j] = c1w[o * 64 + c]; return; }
    j -= 4096;
    if (j < 4096) { int c = j >> 6, o = j & 63; g_p2T[j] = p2w[o * 64 + c]; return; }
    j -= 4096;
    if (j < 4096) { int c = j >> 6, o = j & 63; g_oT[j] = ow[o * 64 + c]; return; }
    j -= 4096;
    if (j < 64) {
        float s = c1b[j];
        for (int c = 0; c < 64; c++) s += c1w[j * 64 + c] * dcnb[c];
        g_c1bf[j] = s;
    }
}

// ---------------- transpose x [B,N,64] -> [B,64,N] (+ zero attn/scale) ----------------
__global__ void k_transpose_x(const float* __restrict__ x) {
    if (blockIdx.x == 0 && blockIdx.y == 0) {
        for (int i = threadIdx.x; i < 2048 + 256; i += 256) {
            if (i < 2048) g_attn[i] = 0.f; else g_scale[i - 2048] = 0.f;
        }
    }
    __shared__ float tile[64][65];
    int b = blockIdx.y; int n0 = blockIdx.x * 64;
    #pragma unroll
    for (int it = 0; it < 16; it++) {
        int idx = it * 256 + threadIdx.x;
        int r = idx >> 6, c = idx & 63;
        tile[c][r] = x[((size_t)b * NPOS + n0 + r) * 64 + c];
    }
    __syncthreads();
    #pragma unroll
    for (int it = 0; it < 16; it++) {
        int idx = it * 256 + threadIdx.x;
        int c = idx >> 6, r = idx & 63;
        g_xt[((size_t)b * 64 + c) * NPOS + n0 + r] = tile[c][r];
    }
}

// ---------------- transpose [B,64,N] -> channels-last bf16 [B,N,64] ----------------
__global__ void k_to_cl(const float* __restrict__ in) {
    __shared__ float tile[64][65];
    int b = blockIdx.y; int n0 = blockIdx.x * 64;
    #pragma unroll
    for (int it = 0; it < 16; it++) {
        int idx = it * 256 + threadIdx.x;
        int c = idx >> 6, r = idx & 63;
        tile[r][c] = in[((size_t)b * 64 + c) * NPOS + n0 + r];
    }
    __syncthreads();
    #pragma unroll
    for (int it = 0; it < 8; it++) {                 // bf16x2 writes
        int idx = it * 256 + threadIdx.x;
        int r = idx >> 5, c2 = idx & 31;
        __nv_bfloat162 v = __floats2bfloat162_rn(tile[r][c2 * 2], tile[r][c2 * 2 + 1]);
        *(__nv_bfloat162*)&g_bclh[((size_t)b * NPOS + n0 + r) * 64 + c2 * 2] = v;
    }
}

// ---------------- qkv pointwise: [B,64,N] -> [B,192,N] ----------------
__global__ void __launch_bounds__(128) k_qkv(const float* __restrict__ in,
                                             float* __restrict__ out) {
    int b = blockIdx.y;
    int n = blockIdx.x * 128 + threadIdx.x;
    const float* inb = in + (size_t)b * 64 * NPOS + n;
    float xv[64];
    #pragma unroll
    for (int c = 0; c < 64; c++) xv[c] = inb[(size_t)c * NPOS];
    #pragma unroll 1
    for (int oc = 0; oc < 12; oc++) {
        float acc[16];
        #pragma unroll
        for (int j = 0; j < 16; j++) acc[j] = 0.f;
        #pragma unroll
        for (int c = 0; c < 64; c++) {
            float xc = xv[c];
            const float4* w4 = (const float4*)(g_qkvT + c * 192 + oc * 16);
            #pragma unroll
            for (int q = 0; q < 4; q++) {
                float4 w = w4[q];
                acc[q*4+0] += w.x * xc; acc[q*4+1] += w.y * xc;
                acc[q*4+2] += w.z * xc; acc[q*4+3] += w.w * xc;
            }
        }
        #pragma unroll
        for (int j = 0; j < 16; j++)
            out[((size_t)b * 192 + oc * 16 + j) * NPOS + n] = acc[j];
    }
}

// ---------------- gram q.k^T + raw sumsq (atomics) ----------------
__global__ void k_gram() {
    int bh = blockIdx.y; int b = bh >> 2, h = bh & 3;
    int n0 = blockIdx.x * 256;
    __shared__ float qt[16 * 257], kt[16 * 257];
    #pragma unroll
    for (int it = 0; it < 16; it++) {
        qt[it * 257 + threadIdx.x] =
            g_qkv[((size_t)b * 192 + h * 16 + it) * NPOS + n0 + threadIdx.x];
        kt[it * 257 + threadIdx.x] =
            g_qkv[((size_t)b * 192 + 64 + h * 16 + it) * NPOS + n0 + threadIdx.x];
    }
    __syncthreads();
    int i = threadIdx.x >> 4, j = threadIdx.x & 15;
    float acc = 0.f;
    #pragma unroll 8
    for (int nn = 0; nn < 256; nn++) acc += qt[i * 257 + nn] * kt[j * 257 + nn];
    atomicAdd(&g_attn[(bh * 16 + i) * 16 + j], acc);
    float sq = 0.f, sk = 0.f;
    #pragma unroll
    for (int m = 0; m < 16; m++) {
        float a = qt[j * 257 + i * 16 + m]; sq += a * a;
        float bb2 = kt[j * 257 + i * 16 + m]; sk += bb2 * bb2;
    }
    atomicAdd(&g_scale[b * 64 + h * 16 + j], sq);
    atomicAdd(&g_scale[128 + b * 64 + h * 16 + j], sk);
}

// ---------------- softmax(inline) + attn@v + LN1 -> x5, then u=gelu(p1@x5) ----------------
__global__ void __launch_bounds__(128) k_xca_ln_p1(const float* __restrict__ temp,
        const float* __restrict__ nw, const float* __restrict__ nb,
        const float* __restrict__ p1b) {
    int b = blockIdx.y;
    __shared__ float asm_s[4 * 256];
    if (threadIdx.x < 64) {
        int h = threadIdx.x >> 4, i = threadIdx.x & 15;
        float sq = 1.f / fmaxf(sqrtf(g_scale[b * 64 + h * 16 + i]), 1e-12f);
        float t = temp[h];
        float v[16], m = -1e30f;
        #pragma unroll
        for (int j = 0; j < 16; j++) {
            float sk = 1.f / fmaxf(sqrtf(g_scale[128 + b * 64 + h * 16 + j]), 1e-12f);
            v[j] = g_attn[(b * 4 + h) * 256 + i * 16 + j] * sq * sk * t;
            m = fmaxf(m, v[j]);
        }
        float s = 0.f;
        #pragma unroll
        for (int j = 0; j < 16; j++) { v[j] = expf(v[j] - m); s += v[j]; }
        float inv = 1.f / s;
        #pragma unroll
        for (int j = 0; j < 16; j++) asm_s[h * 256 + i * 16 + j] = v[j] * inv;
    }
    __syncthreads();

    int n = blockIdx.x * 128 + threadIdx.x;
    float acc[64];
    #pragma unroll
    for (int c = 0; c < 64; c++) acc[c] = 0.f;
    #pragma unroll 1
    for (int h = 0; h < 4; h++) {
        const float* vb = g_qkv + ((size_t)b * 192 + 128 + h * 16) * NPOS + n;
        const float* ab = asm_s + h * 256;
        #pragma unroll 1
        for (int j = 0; j < 16; j++) {
            float vv = vb[(size_t)j * NPOS];
            #pragma unroll
            for (int i = 0; i < 16; i++) acc[h * 16 + i] += ab[i * 16 + j] * vv;
        }
    }
    float mean = 0.f;
    #pragma unroll
    for (int c = 0; c < 64; c++) mean += acc[c];
    mean *= (1.f / 64.f);
    float var = 0.f;
    #pragma unroll
    for (int c = 0; c < 64; c++) { float d = acc[c] - mean; var += d * d; }
    float rs = rsqrtf(var * (1.f / 64.f) + 1e-5f);
    #pragma unroll
    for (int c = 0; c < 64; c++) {
        acc[c] = (acc[c] - mean) * rs * nw[c] + nb[c];
        g_x5[((size_t)b * 64 + c) * NPOS + n] = acc[c];
    }
    #pragma unroll 1
    for (int oc = 0; oc < 4; oc++) {
        float a2[16];
        #pragma unroll
        for (int j = 0; j < 16; j++) a2[j] = p1b[oc * 16 + j];
        #pragma unroll
        for (int c = 0; c < 64; c++) {
            float xc = acc[c];
            const float4* w4 = (const float4*)(g_p1T + c * 64 + oc * 16);
            #pragma unroll
            for (int q = 0; q < 4; q++) {
                float4 w = w4[q];
                a2[q*4+0] += w.x * xc; a2[q*4+1] += w.y * xc;
                a2[q*4+2] += w.z * xc; a2[q*4+3] += w.w * xc;
            }
        }
        #pragma unroll
        for (int j = 0; j < 16; j++) {
            float v = a2[j];
            v = 0.5f * v * (1.f + erff(v * 0.70710678118654752f));
            g_u[((size_t)b * 64 + oc * 16 + j) * NPOS + n] = v;
        }
    }
}

// ---------------- dw5: k=5, dil=1, pad=2; 8 z-outputs per thread ----------------
__global__ void __launch_bounds__(256) k_dw5(const float* __restrict__ in,
        const float* __restrict__ w, const float* __restrict__ bias,
        float* __restrict__ out) {
    __shared__ float ws[125];
    int bc = blockIdx.y, c = bc & 63;
    for (int i = threadIdx.x; i < 125; i += 256) ws[i] = w[c * 125 + i];
    __syncthreads();
    int task = blockIdx.x * 256 + threadIdx.x;
    int g = task >> 10, yx = task & 1023;
    int y = yx >> 5, x = yx & 31;
    int z0 = g * 8;
    const float* inp = in + (size_t)bc * NPOS;
    float bv = bias[c];
    float acc[8];
    #pragma unroll
    for (int j = 0; j < 8; j++) acc[j] = bv;
    #pragma unroll 1
    for (int ky = 0; ky < 5; ky++) {
        int yy = y + ky - 2; if ((unsigned)yy >= 32u) continue;
        #pragma unroll 1
        for (int kx = 0; kx < 5; kx++) {
            int xx = x + kx - 2; if ((unsigned)xx >= 32u) continue;
            const float* col = inp + yy * 32 + xx;
            float vals[12];
            #pragma unroll
            for (int t = 0; t < 12; t++) {
                int zz = z0 + t - 2;
                vals[t] = ((unsigned)zz < 32u) ? col[zz * 1024] : 0.f;
            }
            float wc[5];
            #pragma unroll
            for (int kz = 0; kz < 5; kz++) wc[kz] = ws[(kz * 5 + ky) * 5 + kx];
            #pragma unroll
            for (int j = 0; j < 8; j++)
                #pragma unroll
                for (int kz = 0; kz < 5; kz++)
                    acc[j] += wc[kz] * vals[j + kz];
        }
    }
    #pragma unroll
    for (int j = 0; j < 8; j++)
        out[(size_t)bc * NPOS + (z0 + j) * 1024 + y * 32 + x] = acc[j];
}

// ---------------- dw7: k=7, dil=3, pad=9; mod-3 z-lattice column per thread ----------------
__global__ void __launch_bounds__(256) k_dw7(const float* __restrict__ in,
        const float* __restrict__ w, const float* __restrict__ bias,
        float* __restrict__ out) {
    __shared__ float ws[343];
    int bc = blockIdx.y, c = bc & 63;
    for (int i = threadIdx.x; i < 343; i += 256) ws[i] = w[c * 343 + i];
    __syncthreads();
    int task = blockIdx.x * 256 + threadIdx.x;
    int r = task >> 10, yx = task & 1023;
    int y = yx >> 5, x = yx & 31;
    int nz = (r == 2) ? 10 : 11;
    const float* inp = in + (size_t)bc * NPOS;
    float bv = bias[c];
    float acc[11];
    #pragma unroll
    for (int j = 0; j < 11; j++) acc[j] = bv;
    #pragma unroll 1
    for (int ky = 0; ky < 7; ky++) {
        int yy = y + ky * 3 - 9; if ((unsigned)yy >= 32u) continue;
        #pragma unroll 1
        for (int kx = 0; kx < 7; kx++) {
            int xx = x + kx * 3 - 9; if ((unsigned)xx >= 32u) continue;
            const float* col = inp + yy * 32 + xx;
            float vals[17];
            #pragma unroll
            for (int t = 0; t < 17; t++) {
                int m = t - 3;
                vals[t] = (m >= 0 && m < nz) ? col[(r + 3 * m) * 1024] : 0.f;
            }
            float wc[7];
            #pragma unroll
            for (int kz = 0; kz < 7; kz++) wc[kz] = ws[(kz * 7 + ky) * 7 + kx];
            #pragma unroll
            for (int j = 0; j < 11; j++)
                #pragma unroll
                for (int kz = 0; kz < 7; kz++)
                    acc[j] += wc[kz] * vals[j + kz];
        }
    }
    #pragma unroll
    for (int j = 0; j < 11; j++)
        if (j < nz) out[(size_t)bc * NPOS + (r + 3 * j) * 1024 + y * 32 + x] = acc[j];
}

// ================= wmma bf16 (m16n16k16, fp32 accumulate) =================
#define SLDB 72   // bf16 elements per S row (64 + pad), 144B pitch (16B-multiple)

// ---------------- offsets conv via bf16 wmma: 64 -> 81(96), 3^3, pad 1 ----------------
__global__ void __launch_bounds__(256) k_offconv_mma() {
    __shared__ __nv_bfloat16 S[128 * SLDB];
    int b = blockIdx.y;
    int n0 = blockIdx.x * 128;
    int z = n0 >> 10, y0 = (n0 >> 5) & 31;
    int t = threadIdx.x, warp = t >> 5;
    int wm = warp >> 2, wn = warp & 3;

    wmma::fragment<wmma::accumulator,16,16,16,float> acc[3][2];
    #pragma unroll
    for (int mi = 0; mi < 3; mi++)
        #pragma unroll
        for (int ni = 0; ni < 2; ni++) wmma::fill_fragment(acc[mi][ni], 0.f);

    const uint4* in4 = (const uint4*)g_bclh;   // 8 bf16 per uint4; 8 uint4 per position

    for (int k = 0; k < 27; k++) {
        int dz = k / 9 - 1, dy = (k / 3) % 3 - 1, dx = k % 3 - 1;
        #pragma unroll
        for (int it = 0; it < 4; it++) {
            int idx = it * 256 + t;                 // 1024 uint4
            int p = idx >> 3, g = idx & 7;
            int zz = z + dz, yy = y0 + (p >> 5) + dy, xx = (p & 31) + dx;
            uint4 v = make_uint4(0u, 0u, 0u, 0u);
            if ((unsigned)zz < 32u && (unsigned)yy < 32u && (unsigned)xx < 32u)
                v = in4[((size_t)b * NPOS + zz * 1024 + yy * 32 + xx) * 8 + g];
            *(uint4*)&S[p * SLDB + g * 8] = v;
        }
        __syncthreads();
        #pragma unroll
        for (int ks = 0; ks < 4; ks++) {
            wmma::fragment<wmma::matrix_a,16,16,16,__nv_bfloat16,wmma::row_major> af[3];
            wmma::fragment<wmma::matrix_b,16,16,16,__nv_bfloat16,wmma::col_major> bf[2];
            #pragma unroll
            for (int mi = 0; mi < 3; mi++)
                wmma::load_matrix_sync(af[mi],
                    g_offWh + ((size_t)k * 96 + wm * 48 + mi * 16) * 64 + ks * 16, 64);
            #pragma unroll
            for (int ni = 0; ni < 2; ni++)
                wmma::load_matrix_sync(bf[ni], &S[(wn * 32 + ni * 16) * SLDB + ks * 16], SLDB);
            #pragma unroll
            for (int mi = 0; mi < 3; mi++)
                #pragma unroll
                for (int ni = 0; ni < 2; ni++)
                    wmma::mma_sync(acc[mi][ni], af[mi], bf[ni], acc[mi][ni]);
        }
        __syncthreads();
    }
    #pragma unroll
    for (int mi = 0; mi < 3; mi++)
        #pragma unroll
        for (int ni = 0; ni < 2; ni++)
            wmma::store_matrix_sync(g_off + ((size_t)b * 96 + wm * 48 + mi * 16) * NPOS
                                    + n0 + wn * 32 + ni * 16,
                                    acc[mi][ni], NPOS, wmma::mem_row_major);
}

// ---------------- deformable conv via bf16 wmma ----------------
__global__ void __launch_bounds__(256) k_dcn_mma(const float* __restrict__ offb) {
    __shared__ __nv_bfloat16 S[128 * SLDB];
    int b = blockIdx.y;
    int n0 = blockIdx.x * 128;
    int t = threadIdx.x, warp = t >> 5;
    int wm = warp >> 2, wn = warp & 3;
    int p = t & 127, half = t >> 7;          // 2 threads per position, 32 ch each
    int n = n0 + p;
    int z = n >> 10, y = (n >> 5) & 31, x = n & 31;

    wmma::fragment<wmma::accumulator,16,16,16,float> acc[2][2];
    #pragma unroll
    for (int mi = 0; mi < 2; mi++)
        #pragma unroll
        for (int ni = 0; ni < 2; ni++) wmma::fill_fragment(acc[mi][ni], 0.f);

    const uint4* in4 = (const uint4*)g_bclh + (size_t)b * NPOS * 8;
    const float* offp = g_off + (size_t)b * 96 * NPOS + n;

    for (int k = 0; k < 27; k++) {
        float pz = (float)(z + k / 9 - 1)       + offp[(size_t)(k * 3 + 0) * NPOS] + offb[k * 3 + 0];
        float py = (float)(y + (k / 3) % 3 - 1) + offp[(size_t)(k * 3 + 1) * NPOS] + offb[k * 3 + 1];
        float px = (float)(x + k % 3 - 1)       + offp[(size_t)(k * 3 + 2) * NPOS] + offb[k * 3 + 2];
        float fz = floorf(pz), fy = floorf(py), fx = floorf(px);
        float wz = pz - fz, wy = py - fy, wx = px - fx;
        int iz = (int)fz, iy = (int)fy, ix = (int)fx;
        float cw[8]; int ci[8];
        #pragma unroll
        for (int m = 0; m < 8; m++) {
            int az = iz + (m >> 2), ay = iy + ((m >> 1) & 1), ax = ix + (m & 1);
            bool ok = ((unsigned)az < 32u) && ((unsigned)ay < 32u) && ((unsigned)ax < 32u);
            float w = ((m >> 2) ? wz : 1.f - wz) * (((m >> 1) & 1) ? wy : 1.f - wy)
                      * ((m & 1) ? wx : 1.f - wx);
            cw[m] = ok ? w : 0.f;
            ci[m] = (min(max(az,0),31) * 32 + min(max(ay,0),31)) * 32 + min(max(ax,0),31);
        }
        // gather this thread's 32 channels (4 uint4-groups of 8 bf16)
        #pragma unroll
        for (int q = 0; q < 4; q++) {
            float2 s0 = make_float2(0.f,0.f), s1 = make_float2(0.f,0.f);
            float2 s2 = make_float2(0.f,0.f), s3 = make_float2(0.f,0.f);
            #pragma unroll
            for (int m = 0; m < 8; m++) {
                uint4 v = in4[(size_t)ci[m] * 8 + half * 4 + q];
                float2 f0 = __bfloat1622float2(*(__nv_bfloat162*)&v.x);
                float2 f1 = __bfloat1622float2(*(__nv_bfloat162*)&v.y);
                float2 f2 = __bfloat1622float2(*(__nv_bfloat162*)&v.z);
                float2 f3 = __bfloat1622float2(*(__nv_bfloat162*)&v.w);
                float w = cw[m];
                s0.x += w * f0.x; s0.y += w * f0.y;
                s1.x += w * f1.x; s1.y += w * f1.y;
                s2.x += w * f2.x; s2.y += w * f2.y;
                s3.x += w * f3.x; s3.y += w * f3.y;
            }
            uint4 ov;
            __nv_bfloat162 o0 = __floats2bfloat162_rn(s0.x, s0.y);
            __nv_bfloat162 o1 = __floats2bfloat162_rn(s1.x, s1.y);
            __nv_bfloat162 o2 = __floats2bfloat162_rn(s2.x, s2.y);
            __nv_bfloat162 o3 = __floats2bfloat162_rn(s3.x, s3.y);
            ov.x = *(unsigned*)&o0; ov.y = *(unsigned*)&o1;
            ov.z = *(unsigned*)&o2; ov.w = *(unsigned*)&o3;
            *(uint4*)&S[p * SLDB + half * 32 + q * 8] = ov;
        }
        __syncthreads();
        #pragma unroll
        for (int ks = 0; ks < 4; ks++) {
            wmma::fragment<wmma::matrix_a,16,16,16,__nv_bfloat16,wmma::row_major> af[2];
            wmma::fragment<wmma::matrix_b,16,16,16,__nv_bfloat16,wmma::col_major> bf[2];
            #pragma unroll
            for (int mi = 0; mi < 2; mi++)
                wmma::load_matrix_sync(af[mi],
                    g_dcnWh + ((size_t)k * 64 + wm * 32 + mi * 16) * 64 + ks * 16, 64);
            #pragma unroll
            for (int ni = 0; ni < 2; ni++)
                wmma::load_matrix_sync(bf[ni], &S[(wn * 32 + ni * 16) * SLDB + ks * 16], SLDB);
            #pragma unroll
            for (int mi = 0; mi < 2; mi++)
                #pragma unroll
                for (int ni = 0; ni < 2; ni++)
                    wmma::mma_sync(acc[mi][ni], af[mi], bf[ni], acc[mi][ni]);
        }
        __syncthreads();
    }
    #pragma unroll
    for (int mi = 0; mi < 2; mi++)
        #pragma unroll
        for (int ni = 0; ni < 2; ni++)
            wmma::store_matrix_sync(g_a + ((size_t)b * 64 + wm * 32 + mi * 16) * NPOS
                                    + n0 + wn * 32 + ni * 16,
                                    acc[mi][ni], NPOS, wmma::mem_row_major);
}

// ---------------- fused: y2 = p2 @ ((c1 @ a) * u) + x5  -> g_xt ----------------
__global__ void __launch_bounds__(128) k_c1p2(const float* __restrict__ p2b) {
    int b = blockIdx.y;
    int n = blockIdx.x * 128 + threadIdx.x;
    const float* ap = g_a + (size_t)b * 64 * NPOS + n;
    float av[64];
    #pragma unroll
    for (int c = 0; c < 64; c++) av[c] = ap[(size_t)c * NPOS];
    float tv[64];
    #pragma unroll
    for (int o = 0; o < 64; o++) tv[o] = g_c1bf[o];
    #pragma unroll
    for (int c = 0; c < 64; c++) {
        float xc = av[c];
        const float4* w4 = (const float4*)(g_c1T + c * 64);
        #pragma unroll
        for (int q = 0; q < 16; q++) {
            float4 w = w4[q];
            tv[q*4+0] += w.x * xc; tv[q*4+1] += w.y * xc;
            tv[q*4+2] += w.z * xc; tv[q*4+3] += w.w * xc;
        }
    }
    const float* up = g_u + (size_t)b * 64 * NPOS + n;
    #pragma unroll
    for (int o = 0; o < 64; o++) tv[o] *= up[(size_t)o * NPOS];
    float acc[64];
    #pragma unroll
    for (int o = 0; o < 64; o++) acc[o] = p2b[o];
    #pragma unroll
    for (int c = 0; c < 64; c++) {
        float xc = tv[c];
        const float4* w4 = (const float4*)(g_p2T + c * 64);
        #pragma unroll
        for (int q = 0; q < 16; q++) {
            float4 w = w4[q];
            acc[q*4+0] += w.x * xc; acc[q*4+1] += w.y * xc;
            acc[q*4+2] += w.z * xc; acc[q*4+3] += w.w * xc;
        }
    }
    const float* sp = g_x5 + (size_t)b * 64 * NPOS + n;
    #pragma unroll
    for (int o = 0; o < 64; o++)
        g_xt[((size_t)b * 64 + o) * NPOS + n] = acc[o] + sp[(size_t)o * NPOS];
}

// ---------------- final: permuted gather + LN2 + out matvec ----------------
__global__ void __launch_bounds__(128) k_final(const float* __restrict__ w2,
        const float* __restrict__ b2, const float* __restrict__ ob,
        float* __restrict__ out) {
    int bc = blockIdx.y; int b = bc >> 6, c = bc & 63;
    int s = blockIdx.x * 128 + threadIdx.x;
    const float* yp = g_xt + (size_t)bc * NPOS;
    float r[64], mean = 0.f;
    #pragma unroll
    for (int j = 0; j < 64; j++) { r[j] = yp[j * 512 + s]; mean += r[j]; }
    mean *= (1.f / 64.f);
    float var = 0.f;
    #pragma unroll
    for (int j = 0; j < 64; j++) { float d = r[j] - mean; var += d * d; }
    float rs = rsqrtf(var * (1.f / 64.f) + 1e-5f);
    float acc[64];
    #pragma unroll
    for (int o = 0; o < 64; o++) acc[o] = ob[o];
    #pragma unroll 1
    for (int j = 0; j < 64; j++) {
        float v = (r[j] - mean) * rs * w2[j] + b2[j];
        const float4* w4 = (const float4*)(g_oT + j * 64);
        #pragma unroll
        for (int q = 0; q < 16; q++) {
            float4 w = w4[q];
            acc[q*4+0] += w.x * v; acc[q*4+1] += w.y * v;
            acc[q*4+2] += w.z * v; acc[q*4+3] += w.w * v;
        }
    }
    float4* op = (float4*)(out + ((size_t)b * NPOS + c + 64 * s) * 64);
    #pragma unroll
    for (int q = 0; q < 16; q++)
        op[q] = make_float4(acc[q*4], acc[q*4+1], acc[q*4+2], acc[q*4+3]);
}

// ---------------- launch ----------------
extern "C" void kernel_launch(void* const* d_in, const int* in_sizes, int n_in,
                              void* d_out, int out_size) {
    const float* x     = (const float*)d_in[0];
    const float* temp  = (const float*)d_in[1];
    const float* qkv_w = (const float*)d_in[2];
    const float* nw    = (const float*)d_in[3];
    const float* nb    = (const float*)d_in[4];
    const float* p1w   = (const float*)d_in[5];
    const float* p1b   = (const float*)d_in[6];
    const float* c0w   = (const float*)d_in[7];
    const float* c0b   = (const float*)d_in[8];
    const float* cspw  = (const float*)d_in[9];
    const float* cspb  = (const float*)d_in[10];
    const float* offw  = (const float*)d_in[11];
    const float* offb  = (const float*)d_in[12];
    const float* dcnw  = (const float*)d_in[13];
    const float* dcnb  = (const float*)d_in[14];
    const float* c1w   = (const float*)d_in[15];
    const float* c1b   = (const float*)d_in[16];
    const float* p2w   = (const float*)d_in[17];
    const float* p2b   = (const float*)d_in[18];
    const float* n2w   = (const float*)d_in[19];
    const float* n2b   = (const float*)d_in[20];
    const float* ow    = (const float*)d_in[21];
    const float* obias = (const float*)d_in[22];
    float* out = (float*)d_out;

    float *xt, *qkv, *u, *a, *bb;
    cudaGetSymbolAddress((void**)&xt,  g_xt);
    cudaGetSymbolAddress((void**)&qkv, g_qkv);
    cudaGetSymbolAddress((void**)&u,   g_u);
    cudaGetSymbolAddress((void**)&a,   g_a);
    cudaGetSymbolAddress((void**)&bb,  g_b);

    // 1: all weight prep in one kernel
    k_prep<<<1193, 256>>>(qkv_w, p1w, c1w, p2w, ow, offw, dcnw, c1b, dcnb);
    // 2: transpose x (+ zero attn/scale)
    k_transpose_x<<<dim3(512, NB), 256>>>(x);
    // 3: qkv projection
    k_qkv<<<dim3(256, NB), 128>>>(xt, qkv);
    // 4: gram + sumsq
    k_gram<<<dim3(128, NB * 4), 256>>>();
    // 5: softmax + attn@v + LN1 + proj1/gelu
    k_xca_ln_p1<<<dim3(256, NB), 128>>>(temp, nw, nb, p1b);
    // 6: depthwise 5^3
    k_dw5<<<dim3(16, NB * 64), 256>>>(u, c0w, c0b, a);
    // 7: depthwise 7^3 dil 3
    k_dw7<<<dim3(12, NB * 64), 256>>>(a, cspw, cspb, bb);
    // 8: channels-last bf16 copy
    k_to_cl<<<dim3(512, NB), 256>>>(bb);
    // 9-10: offsets conv + deformable conv (bf16 tensor cores, fp32 accum)
    k_offconv_mma<<<dim3(256, NB), 256>>>();
    k_dcn_mma<<<dim3(256, NB), 256>>>(offb);
    // 11: conv1*u then proj2+shortcut fused
    k_c1p2<<<dim3(256, NB), 128>>>(p2b);
    // 12: permute + LN2 + output projection
    k_final<<<dim3(4, NB * 64), 128>>>(n2w, n2b, obias, out);
}

// round 10
// speedup vs baseline: 2.6041x; 1.0366x over previous
#include <cuda_runtime.h>
#include <cuda_bf16.h>
#include <mma.h>
#include <math.h>

using namespace nvcuda;

#define NPOS 32768
#define NB 2

// ---------------- scratch (device globals) ----------------
__device__ __align__(16) float g_y2 [NB*64*NPOS];   // proj2+shortcut output
__device__ __align__(16) float g_qkv[NB*192*NPOS];
__device__ __align__(16) float g_x5 [NB*64*NPOS];   // shortcut
__device__ __align__(16) float g_u  [NB*64*NPOS];
__device__ __align__(16) float g_a  [NB*64*NPOS];
__device__ __align__(16) float g_b  [NB*64*NPOS];
__device__ __align__(16) __nv_bfloat16 g_bclh[NB*64*NPOS];  // channels-last bf16 of g_b
__device__ float g_scale[256];                      // RAW sum-of-squares
__device__ float g_attn[NB*4*16*16];                // RAW gram
__device__ __align__(16) float g_qkvT[64*192];
__device__ __align__(16) float g_p1T[64*64];
__device__ __align__(16) float g_c1T[64*64];
__device__ __align__(16) float g_p2T[64*64];
__device__ __align__(16) float g_oT [64*64];
__device__ __align__(16) __nv_bfloat16 g_offWh[27*96*64];   // bf16 [tap][o][c]
__device__ __align__(16) __nv_bfloat16 g_dcnWh[27*64*64];   // bf16 [tap][o][c]
__device__ float g_c1bf[64];

// ---------------- one mega prep kernel (+ zero attn/scale) ----------------
__global__ void k_prep(const float* __restrict__ qkvw, const float* __restrict__ p1w,
                       const float* __restrict__ c1w, const float* __restrict__ p2w,
                       const float* __restrict__ ow,  const float* __restrict__ offw,
                       const float* __restrict__ dcnw, const float* __restrict__ c1b,
                       const float* __restrict__ dcnb) {
    if (blockIdx.x == 0) {
        for (int i = threadIdx.x; i < 2048 + 256; i += 256) {
            if (i < 2048) g_attn[i] = 0.f; else g_scale[i - 2048] = 0.f;
        }
    }
    int i = blockIdx.x * 256 + threadIdx.x;
    if (i < 165888) {                      // offWh [27][96][64]
        int c = i & 63, o = (i >> 6) % 96, k = i / (96 * 64);
        g_offWh[i] = __float2bfloat16((o < 81) ? offw[(o * 64 + c) * 27 + k] : 0.f);
        return;
    }
    int j = i - 165888;
    if (j < 110592) {                      // dcnWh [27][64][64]
        int c = j & 63, o = (j >> 6) & 63, k = j >> 12;
        g_dcnWh[j] = __float2bfloat16(dcnw[(o * 64 + c) * 27 + k]);
        return;
    }
    j -= 110592;
    if (j < 12288) { int c = j / 192, o = j % 192; g_qkvT[j] = qkvw[o * 64 + c]; return; }
    j -= 12288;
    if (j < 4096) { int c = j >> 6, o = j & 63; g_p1T[j] = p1w[o * 64 + c]; return; }
    j -= 4096;
    if (j < 4096) { int c = j >> 6, o = j & 63; g_c1T[j] = c1w[o * 64 + c]; return; }
    j -= 4096;
    if (j < 4096) { int c = j >> 6, o = j & 63; g_p2T[j] = p2w[o * 64 + c]; return; }
    j -= 4096;
    if (j < 4096) { int c = j >> 6, o = j & 63; g_oT[j] = ow[o * 64 + c]; return; }
    j -= 4096;
    if (j < 64) {
        float s = c1b[j];
        for (int c = 0; c < 64; c++) s += c1w[j * 64 + c] * dcnb[c];
        g_c1bf[j] = s;
    }
}

// ---------------- transpose [B,64,N] -> channels-last bf16 [B,N,64] ----------------
__global__ void k_to_cl(const float* __restrict__ in) {
    __shared__ float tile[64][65];
    int b = blockIdx.y; int n0 = blockIdx.x * 64;
    #pragma unroll
    for (int it = 0; it < 16; it++) {
        int idx = it * 256 + threadIdx.x;
        int c = idx >> 6, r = idx & 63;
        tile[r][c] = in[((size_t)b * 64 + c) * NPOS + n0 + r];
    }
    __syncthreads();
    #pragma unroll
    for (int it = 0; it < 8; it++) {                 // bf16x2 writes
        int idx = it * 256 + threadIdx.x;
        int r = idx >> 5, c2 = idx & 31;
        __nv_bfloat162 v = __floats2bfloat162_rn(tile[r][c2 * 2], tile[r][c2 * 2 + 1]);
        *(__nv_bfloat162*)&g_bclh[((size_t)b * NPOS + n0 + r) * 64 + c2 * 2] = v;
    }
}

// ---------------- qkv pointwise: reads x [B,N,64] directly -> [B,192,N] ----------------
__global__ void __launch_bounds__(128) k_qkv(const float* __restrict__ x,
                                             float* __restrict__ out) {
    int b = blockIdx.y;
    int n = blockIdx.x * 128 + threadIdx.x;
    const float4* xp = (const float4*)(x + ((size_t)b * NPOS + n) * 64);
    float xv[64];
    #pragma unroll
    for (int q = 0; q < 16; q++) {
        float4 v = xp[q];
        xv[q*4+0] = v.x; xv[q*4+1] = v.y; xv[q*4+2] = v.z; xv[q*4+3] = v.w;
    }
    #pragma unroll 1
    for (int oc = 0; oc < 12; oc++) {
        float acc[16];
        #pragma unroll
        for (int j = 0; j < 16; j++) acc[j] = 0.f;
        #pragma unroll
        for (int c = 0; c < 64; c++) {
            float xc = xv[c];
            const float4* w4 = (const float4*)(g_qkvT + c * 192 + oc * 16);
            #pragma unroll
            for (int q = 0; q < 4; q++) {
                float4 w = w4[q];
                acc[q*4+0] += w.x * xc; acc[q*4+1] += w.y * xc;
                acc[q*4+2] += w.z * xc; acc[q*4+3] += w.w * xc;
            }
        }
        #pragma unroll
        for (int j = 0; j < 16; j++)
            out[((size_t)b * 192 + oc * 16 + j) * NPOS + n] = acc[j];
    }
}

// ---------------- gram q.k^T (2x2 register-blocked) + raw sumsq ----------------
__global__ void k_gram() {
    int bh = blockIdx.y; int b = bh >> 2, h = bh & 3;
    int n0 = blockIdx.x * 256;
    __shared__ float qt[16 * 257], kt[16 * 257];
    #pragma unroll
    for (int it = 0; it < 16; it++) {
        qt[it * 257 + threadIdx.x] =
            g_qkv[((size_t)b * 192 + h * 16 + it) * NPOS + n0 + threadIdx.x];
        kt[it * 257 + threadIdx.x] =
            g_qkv[((size_t)b * 192 + 64 + h * 16 + it) * NPOS + n0 + threadIdx.x];
    }
    __syncthreads();
    int t = threadIdx.x;
    // sumsq partials (all 256 threads): channel j, 16-element segment i
    {
        int i = t >> 4, j = t & 15;
        float sq = 0.f, sk = 0.f;
        #pragma unroll
        for (int m = 0; m < 16; m++) {
            float a = qt[j * 257 + i * 16 + m]; sq += a * a;
            float bb2 = kt[j * 257 + i * 16 + m]; sk += bb2 * bb2;
        }
        atomicAdd(&g_scale[b * 64 + h * 16 + j], sq);
        atomicAdd(&g_scale[128 + b * 64 + h * 16 + j], sk);
    }
    // gram: threads 0..127, each a 2x2 output tile over half the nn range
    if (t < 128) {
        int half = t >> 6, tile = t & 63;
        int i0 = (tile >> 3) * 2, j0 = (tile & 7) * 2;
        const float* q0p = qt + i0 * 257 + half * 128;
        const float* q1p = q0p + 257;
        const float* k0p = kt + j0 * 257 + half * 128;
        const float* k1p = k0p + 257;
        float a00 = 0.f, a01 = 0.f, a10 = 0.f, a11 = 0.f;
        #pragma unroll 8
        for (int nn = 0; nn < 128; nn++) {
            float q0 = q0p[nn], q1 = q1p[nn];
            float k0 = k0p[nn], k1 = k1p[nn];
            a00 += q0 * k0; a01 += q0 * k1;
            a10 += q1 * k0; a11 += q1 * k1;
        }
        atomicAdd(&g_attn[(bh * 16 + i0) * 16 + j0], a00);
        atomicAdd(&g_attn[(bh * 16 + i0) * 16 + j0 + 1], a01);
        atomicAdd(&g_attn[(bh * 16 + i0 + 1) * 16 + j0], a10);
        atomicAdd(&g_attn[(bh * 16 + i0 + 1) * 16 + j0 + 1], a11);
    }
}

// ---------------- softmax(inline) + attn@v + LN1 -> x5, then u=gelu(p1@x5) ----------------
__global__ void __launch_bounds__(128) k_xca_ln_p1(const float* __restrict__ temp,
        const float* __restrict__ nw, const float* __restrict__ nb,
        const float* __restrict__ p1b) {
    int b = blockIdx.y;
    __shared__ float asm_s[4 * 256];
    if (threadIdx.x < 64) {
        int h = threadIdx.x >> 4, i = threadIdx.x & 15;
        float sq = 1.f / fmaxf(sqrtf(g_scale[b * 64 + h * 16 + i]), 1e-12f);
        float tt = temp[h];
        float v[16], m = -1e30f;
        #pragma unroll
        for (int j = 0; j < 16; j++) {
            float sk = 1.f / fmaxf(sqrtf(g_scale[128 + b * 64 + h * 16 + j]), 1e-12f);
            v[j] = g_attn[(b * 4 + h) * 256 + i * 16 + j] * sq * sk * tt;
            m = fmaxf(m, v[j]);
        }
        float s = 0.f;
        #pragma unroll
        for (int j = 0; j < 16; j++) { v[j] = expf(v[j] - m); s += v[j]; }
        float inv = 1.f / s;
        #pragma unroll
        for (int j = 0; j < 16; j++) asm_s[h * 256 + i * 16 + j] = v[j] * inv;
    }
    __syncthreads();

    int n = blockIdx.x * 128 + threadIdx.x;
    float acc[64];
    #pragma unroll
    for (int c = 0; c < 64; c++) acc[c] = 0.f;
    #pragma unroll 1
    for (int h = 0; h < 4; h++) {
        const float* vb = g_qkv + ((size_t)b * 192 + 128 + h * 16) * NPOS + n;
        const float* ab = asm_s + h * 256;
        #pragma unroll 1
        for (int j = 0; j < 16; j++) {
            float vv = vb[(size_t)j * NPOS];
            #pragma unroll
            for (int i = 0; i < 16; i++) acc[h * 16 + i] += ab[i * 16 + j] * vv;
        }
    }
    float mean = 0.f;
    #pragma unroll
    for (int c = 0; c < 64; c++) mean += acc[c];
    mean *= (1.f / 64.f);
    float var = 0.f;
    #pragma unroll
    for (int c = 0; c < 64; c++) { float d = acc[c] - mean; var += d * d; }
    float rs = rsqrtf(var * (1.f / 64.f) + 1e-5f);
    #pragma unroll
    for (int c = 0; c < 64; c++) {
        acc[c] = (acc[c] - mean) * rs * nw[c] + nb[c];
        g_x5[((size_t)b * 64 + c) * NPOS + n] = acc[c];
    }
    #pragma unroll 1
    for (int oc = 0; oc < 4; oc++) {
        float a2[16];
        #pragma unroll
        for (int j = 0; j < 16; j++) a2[j] = p1b[oc * 16 + j];
        #pragma unroll
        for (int c = 0; c < 64; c++) {
            float xc = acc[c];
            const float4* w4 = (const float4*)(g_p1T + c * 64 + oc * 16);
            #pragma unroll
            for (int q = 0; q < 4; q++) {
                float4 w = w4[q];
                a2[q*4+0] += w.x * xc; a2[q*4+1] += w.y * xc;
                a2[q*4+2] += w.z * xc; a2[q*4+3] += w.w * xc;
            }
        }
        #pragma unroll
        for (int j = 0; j < 16; j++) {
            float v = a2[j];
            v = 0.5f * v * (1.f + erff(v * 0.70710678118654752f));
            g_u[((size_t)b * 64 + oc * 16 + j) * NPOS + n] = v;
        }
    }
}

// ---------------- dw5: k=5, dil=1, pad=2; 8 z-outputs per thread ----------------
__global__ void __launch_bounds__(256) k_dw5(const float* __restrict__ in,
        const float* __restrict__ w, const float* __restrict__ bias,
        float* __restrict__ out) {
    __shared__ float ws[125];
    int bc = blockIdx.y, c = bc & 63;
    for (int i = threadIdx.x; i < 125; i += 256) ws[i] = w[c * 125 + i];
    __syncthreads();
    int task = blockIdx.x * 256 + threadIdx.x;
    int g = task >> 10, yx = task & 1023;
    int y = yx >> 5, x = yx & 31;
    int z0 = g * 8;
    const float* inp = in + (size_t)bc * NPOS;
    float bv = bias[c];
    float acc[8];
    #pragma unroll
    for (int j = 0; j < 8; j++) acc[j] = bv;
    #pragma unroll 1
    for (int ky = 0; ky < 5; ky++) {
        int yy = y + ky - 2; if ((unsigned)yy >= 32u) continue;
        #pragma unroll 1
        for (int kx = 0; kx < 5; kx++) {
            int xx = x + kx - 2; if ((unsigned)xx >= 32u) continue;
            const float* col = inp + yy * 32 + xx;
            float vals[12];
            #pragma unroll
            for (int t = 0; t < 12; t++) {
                int zz = z0 + t - 2;
                vals[t] = ((unsigned)zz < 32u) ? col[zz * 1024] : 0.f;
            }
            float wc[5];
            #pragma unroll
            for (int kz = 0; kz < 5; kz++) wc[kz] = ws[(kz * 5 + ky) * 5 + kx];
            #pragma unroll
            for (int j = 0; j < 8; j++)
                #pragma unroll
                for (int kz = 0; kz < 5; kz++)
                    acc[j] += wc[kz] * vals[j + kz];
        }
    }
    #pragma unroll
    for (int j = 0; j < 8; j++)
        out[(size_t)bc * NPOS + (z0 + j) * 1024 + y * 32 + x] = acc[j];
}

// ---------------- dw7: k=7, dil=3, pad=9; mod-3 z-lattice column per thread ----------------
__global__ void __launch_bounds__(256) k_dw7(const float* __restrict__ in,
        const float* __restrict__ w, const float* __restrict__ bias,
        float* __restrict__ out) {
    __shared__ float ws[343];
    int bc = blockIdx.y, c = bc & 63;
    for (int i = threadIdx.x; i < 343; i += 256) ws[i] = w[c * 343 + i];
    __syncthreads();
    int task = blockIdx.x * 256 + threadIdx.x;
    int r = task >> 10, yx = task & 1023;
    int y = yx >> 5, x = yx & 31;
    int nz = (r == 2) ? 10 : 11;
    const float* inp = in + (size_t)bc * NPOS;
    float bv = bias[c];
    float acc[11];
    #pragma unroll
    for (int j = 0; j < 11; j++) acc[j] = bv;
    #pragma unroll 1
    for (int ky = 0; ky < 7; ky++) {
        int yy = y + ky * 3 - 9; if ((unsigned)yy >= 32u) continue;
        #pragma unroll 1
        for (int kx = 0; kx < 7; kx++) {
            int xx = x + kx * 3 - 9; if ((unsigned)xx >= 32u) continue;
            const float* col = inp + yy * 32 + xx;
            float vals[17];
            #pragma unroll
            for (int t = 0; t < 17; t++) {
                int m = t - 3;
                vals[t] = (m >= 0 && m < nz) ? col[(r + 3 * m) * 1024] : 0.f;
            }
            float wc[7];
            #pragma unroll
            for (int kz = 0; kz < 7; kz++) wc[kz] = ws[(kz * 7 + ky) * 7 + kx];
            #pragma unroll
            for (int j = 0; j < 11; j++)
                #pragma unroll
                for (int kz = 0; kz < 7; kz++)
                    acc[j] += wc[kz] * vals[j + kz];
        }
    }
    #pragma unroll
    for (int j = 0; j < 11; j++)
        if (j < nz) out[(size_t)bc * NPOS + (r + 3 * j) * 1024 + y * 32 + x] = acc[j];
}

// ================= fused offconv + dcn (bf16 wmma, offsets in smem) =================
#define SLDB 72    // bf16 elements per S row (64 + pad)
#define LDP  132   // bf16 elements per offsets row (128 + pad)

__global__ void __launch_bounds__(256) k_offdcn_mma(const float* __restrict__ offb) {
    // smem partition: S (gather/input tile, also fragment staging) + OFS (offsets)
    __shared__ __align__(16) char smem_raw[128 * SLDB * 2 + 96 * LDP * 2];
    __nv_bfloat16* S = (__nv_bfloat16*)smem_raw;
    __nv_bfloat16* OFS = (__nv_bfloat16*)(smem_raw + 128 * SLDB * 2);

    int b = blockIdx.y;
    int n0 = blockIdx.x * 128;
    int z0 = n0 >> 10, y0 = (n0 >> 5) & 31;
    int t = threadIdx.x, warp = t >> 5, lane = t & 31;
    int wm = warp >> 2, wn = warp & 3;

    const uint4* in4 = (const uint4*)g_bclh + (size_t)b * NPOS * 8;

    // ---------- phase 1: offsets conv (64 -> 96 rows, 81 real) ----------
    {
        wmma::fragment<wmma::accumulator,16,16,16,float> acc[3][2];
        #pragma unroll
        for (int mi = 0; mi < 3; mi++)
            #pragma unroll
            for (int ni = 0; ni < 2; ni++) wmma::fill_fragment(acc[mi][ni], 0.f);

        for (int k = 0; k < 27; k++) {
            int dz = k / 9 - 1, dy = (k / 3) % 3 - 1, dx = k % 3 - 1;
            #pragma unroll
            for (int it = 0; it < 4; it++) {
                int idx = it * 256 + t;             // 1024 uint4 = 128 pos x 8 groups
                int p = idx >> 3, g = idx & 7;
                int zz = z0 + dz, yy = y0 + (p >> 5) + dy, xx = (p & 31) + dx;
                uint4 v = make_uint4(0u, 0u, 0u, 0u);
                if ((unsigned)zz < 32u && (unsigned)yy < 32u && (unsigned)xx < 32u)
                    v = in4[((size_t)(zz * 1024 + yy * 32 + xx)) * 8 + g];
                *(uint4*)&S[p * SLDB + g * 8] = v;
            }
            __syncthreads();
            #pragma unroll
            for (int ks = 0; ks < 4; ks++) {
                wmma::fragment<wmma::matrix_a,16,16,16,__nv_bfloat16,wmma::row_major> af[3];
                wmma::fragment<wmma::matrix_b,16,16,16,__nv_bfloat16,wmma::col_major> bf[2];
                #pragma unroll
                for (int mi = 0; mi < 3; mi++)
                    wmma::load_matrix_sync(af[mi],
                        g_offWh + ((size_t)k * 96 + wm * 48 + mi * 16) * 64 + ks * 16, 64);
                #pragma unroll
                for (int ni = 0; ni < 2; ni++)
                    wmma::load_matrix_sync(bf[ni], &S[(wn * 32 + ni * 16) * SLDB + ks * 16], SLDB);
                #pragma unroll
                for (int mi = 0; mi < 3; mi++)
                    #pragma unroll
                    for (int ni = 0; ni < 2; ni++)
                        wmma::mma_sync(acc[mi][ni], af[mi], bf[ni], acc[mi][ni]);
            }
            __syncthreads();
        }
        // stage fragments through S region (per-warp 256-float scratch) -> OFS bf16
        float* stg = (float*)S + warp * 256;
        #pragma unroll
        for (int mi = 0; mi < 3; mi++) {
            #pragma unroll
            for (int ni = 0; ni < 2; ni++) {
                wmma::store_matrix_sync(stg, acc[mi][ni], 16, wmma::mem_row_major);
                __syncwarp();
                int row0 = wm * 48 + mi * 16, col0 = wn * 32 + ni * 16;
                #pragma unroll
                for (int e = 0; e < 8; e++) {
                    int idx = e * 32 + lane;
                    int rr = idx >> 4, cc = idx & 15;
                    OFS[(row0 + rr) * LDP + col0 + cc] = __float2bfloat16(stg[rr * 16 + cc]);
                }
                __syncwarp();
            }
        }
        __syncthreads();
    }

    // ---------- phase 2: deformable conv ----------
    {
        int p = t & 127, half = t >> 7;
        int n = n0 + p;
        int z = n >> 10, y = (n >> 5) & 31, x = n & 31;

        wmma::fragment<wmma::accumulator,16,16,16,float> acc[2][2];
        #pragma unroll
        for (int mi = 0; mi < 2; mi++)
            #pragma unroll
            for (int ni = 0; ni < 2; ni++) wmma::fill_fragment(acc[mi][ni], 0.f);

        for (int k = 0; k < 27; k++) {
            float pz = (float)(z + k / 9 - 1)
                     + __bfloat162float(OFS[(k * 3 + 0) * LDP + p]) + offb[k * 3 + 0];
            float py = (float)(y + (k / 3) % 3 - 1)
                     + __bfloat162float(OFS[(k * 3 + 1) * LDP + p]) + offb[k * 3 + 1];
            float px = (float)(x + k % 3 - 1)
                     + __bfloat162float(OFS[(k * 3 + 2) * LDP + p]) + offb[k * 3 + 2];
            float fz = floorf(pz), fy = floorf(py), fx = floorf(px);
            float wz = pz - fz, wy = py - fy, wx = px - fx;
            int iz = (int)fz, iy = (int)fy, ix = (int)fx;
            float cw[8]; int ci[8];
            #pragma unroll
            for (int m = 0; m < 8; m++) {
                int az = iz + (m >> 2), ay = iy + ((m >> 1) & 1), ax = ix + (m & 1);
                bool ok = ((unsigned)az < 32u) && ((unsigned)ay < 32u) && ((unsigned)ax < 32u);
                float w = ((m >> 2) ? wz : 1.f - wz) * (((m >> 1) & 1) ? wy : 1.f - wy)
                          * ((m & 1) ? wx : 1.f - wx);
                cw[m] = ok ? w : 0.f;
                ci[m] = (min(max(az,0),31) * 32 + min(max(ay,0),31)) * 32 + min(max(ax,0),31);
            }
            #pragma unroll
            for (int q = 0; q < 4; q++) {
                float2 s0 = make_float2(0.f,0.f), s1 = make_float2(0.f,0.f);
                float2 s2 = make_float2(0.f,0.f), s3 = make_float2(0.f,0.f);
                #pragma unroll
                for (int m = 0; m < 8; m++) {
                    uint4 v = in4[(size_t)ci[m] * 8 + half * 4 + q];
                    float2 f0 = __bfloat1622float2(*(__nv_bfloat162*)&v.x);
                    float2 f1 = __bfloat1622float2(*(__nv_bfloat162*)&v.y);
                    float2 f2 = __bfloat1622float2(*(__nv_bfloat162*)&v.z);
                    float2 f3 = __bfloat1622float2(*(__nv_bfloat162*)&v.w);
                    float w = cw[m];
                    s0.x += w * f0.x; s0.y += w * f0.y;
                    s1.x += w * f1.x; s1.y += w * f1.y;
                    s2.x += w * f2.x; s2.y += w * f2.y;
                    s3.x += w * f3.x; s3.y += w * f3.y;
                }
                uint4 ov;
                __nv_bfloat162 o0 = __floats2bfloat162_rn(s0.x, s0.y);
                __nv_bfloat162 o1 = __floats2bfloat162_rn(s1.x, s1.y);
                __nv_bfloat162 o2 = __floats2bfloat162_rn(s2.x, s2.y);
                __nv_bfloat162 o3 = __floats2bfloat162_rn(s3.x, s3.y);
                ov.x = *(unsigned*)&o0; ov.y = *(unsigned*)&o1;
                ov.z = *(unsigned*)&o2; ov.w = *(unsigned*)&o3;
                *(uint4*)&S[p * SLDB + half * 32 + q * 8] = ov;
            }
            __syncthreads();
            #pragma unroll
            for (int ks = 0; ks < 4; ks++) {
                wmma::fragment<wmma::matrix_a,16,16,16,__nv_bfloat16,wmma::row_major> af[2];
                wmma::fragment<wmma::matrix_b,16,16,16,__nv_bfloat16,wmma::col_major> bf[2];
                #pragma unroll
                for (int mi = 0; mi < 2; mi++)
                    wmma::load_matrix_sync(af[mi],
                        g_dcnWh + ((size_t)k * 64 + wm * 32 + mi * 16) * 64 + ks * 16, 64);
                #pragma unroll
                for (int ni = 0; ni < 2; ni++)
                    wmma::load_matrix_sync(bf[ni], &S[(wn * 32 + ni * 16) * SLDB + ks * 16], SLDB);
                #pragma unroll
                for (int mi = 0; mi < 2; mi++)
                    #pragma unroll
                    for (int ni = 0; ni < 2; ni++)
                        wmma::mma_sync(acc[mi][ni], af[mi], bf[ni], acc[mi][ni]);
            }
            __syncthreads();
        }
        #pragma unroll
        for (int mi = 0; mi < 2; mi++)
            #pragma unroll
            for (int ni = 0; ni < 2; ni++)
                wmma::store_matrix_sync(g_a + ((size_t)b * 64 + wm * 32 + mi * 16) * NPOS
                                        + n0 + wn * 32 + ni * 16,
                                        acc[mi][ni], NPOS, wmma::mem_row_major);
    }
}

// ---------------- fused: y2 = p2 @ ((c1 @ a) * u) + x5  -> g_y2 ----------------
__global__ void __launch_bounds__(128) k_c1p2(const float* __restrict__ p2b) {
    int b = blockIdx.y;
    int n = blockIdx.x * 128 + threadIdx.x;
    const float* ap = g_a + (size_t)b * 64 * NPOS + n;
    float av[64];
    #pragma unroll
    for (int c = 0; c < 64; c++) av[c] = ap[(size_t)c * NPOS];
    float tv[64];
    #pragma unroll
    for (int o = 0; o < 64; o++) tv[o] = g_c1bf[o];
    #pragma unroll
    for (int c = 0; c < 64; c++) {
        float xc = av[c];
        const float4* w4 = (const float4*)(g_c1T + c * 64);
        #pragma unroll
        for (int q = 0; q < 16; q++) {
            float4 w = w4[q];
            tv[q*4+0] += w.x * xc; tv[q*4+1] += w.y * xc;
            tv[q*4+2] += w.z * xc; tv[q*4+3] += w.w * xc;
        }
    }
    const float* up = g_u + (size_t)b * 64 * NPOS + n;
    #pragma unroll
    for (int o = 0; o < 64; o++) tv[o] *= up[(size_t)o * NPOS];
    float acc[64];
    #pragma unroll
    for (int o = 0; o < 64; o++) acc[o] = p2b[o];
    #pragma unroll
    for (int c = 0; c < 64; c++) {
        float xc = tv[c];
        const float4* w4 = (const float4*)(g_p2T + c * 64);
        #pragma unroll
        for (int q = 0; q < 16; q++) {
            float4 w = w4[q];
            acc[q*4+0] += w.x * xc; acc[q*4+1] += w.y * xc;
            acc[q*4+2] += w.z * xc; acc[q*4+3] += w.w * xc;
        }
    }
    const float* sp = g_x5 + (size_t)b * 64 * NPOS + n;
    #pragma unroll
    for (int o = 0; o < 64; o++)
        g_y2[((size_t)b * 64 + o) * NPOS + n] = acc[o] + sp[(size_t)o * NPOS];
}

// ---------------- final: permuted gather + LN2 + out matvec ----------------
__global__ void __launch_bounds__(128) k_final(const float* __restrict__ w2,
        const float* __restrict__ b2, const float* __restrict__ ob,
        float* __restrict__ out) {
    int bc = blockIdx.y; int b = bc >> 6, c = bc & 63;
    int s = blockIdx.x * 128 + threadIdx.x;
    const float* yp = g_y2 + (size_t)bc * NPOS;
    float r[64], mean = 0.f;
    #pragma unroll
    for (int j = 0; j < 64; j++) { r[j] = yp[j * 512 + s]; mean += r[j]; }
    mean *= (1.f / 64.f);
    float var = 0.f;
    #pragma unroll
    for (int j = 0; j < 64; j++) { float d = r[j] - mean; var += d * d; }
    float rs = rsqrtf(var * (1.f / 64.f) + 1e-5f);
    float acc[64];
    #pragma unroll
    for (int o = 0; o < 64; o++) acc[o] = ob[o];
    #pragma unroll 1
    for (int j = 0; j < 64; j++) {
        float v = (r[j] - mean) * rs * w2[j] + b2[j];
        const float4* w4 = (const float4*)(g_oT + j * 64);
        #pragma unroll
        for (int q = 0; q < 16; q++) {
            float4 w = w4[q];
            acc[q*4+0] += w.x * v; acc[q*4+1] += w.y * v;
            acc[q*4+2] += w.z * v; acc[q*4+3] += w.w * v;
        }
    }
    float4* op = (float4*)(out + ((size_t)b * NPOS + c + 64 * s) * 64);
    #pragma unroll
    for (int q = 0; q < 16; q++)
        op[q] = make_float4(acc[q*4], acc[q*4+1], acc[q*4+2], acc[q*4+3]);
}

// ---------------- launch ----------------
extern "C" void kernel_launch(void* const* d_in, const int* in_sizes, int n_in,
                              void* d_out, int out_size) {
    const float* x     = (const float*)d_in[0];
    const float* temp  = (const float*)d_in[1];
    const float* qkv_w = (const float*)d_in[2];
    const float* nw    = (const float*)d_in[3];
    const float* nb    = (const float*)d_in[4];
    const float* p1w   = (const float*)d_in[5];
    const float* p1b   = (const float*)d_in[6];
    const float* c0w   = (const float*)d_in[7];
    const float* c0b   = (const float*)d_in[8];
    const float* cspw  = (const float*)d_in[9];
    const float* cspb  = (const float*)d_in[10];
    const float* offw  = (const float*)d_in[11];
    const float* offb  = (const float*)d_in[12];
    const float* dcnw  = (const float*)d_in[13];
    const float* dcnb  = (const float*)d_in[14];
    const float* c1w   = (const float*)d_in[15];
    const float* c1b   = (const float*)d_in[16];
    const float* p2w   = (const float*)d_in[17];
    const float* p2b   = (const float*)d_in[18];
    const float* n2w   = (const float*)d_in[19];
    const float* n2b   = (const float*)d_in[20];
    const float* ow    = (const float*)d_in[21];
    const float* obias = (const float*)d_in[22];
    float* out = (float*)d_out;

    float *qkv, *u, *a, *bb;
    cudaGetSymbolAddress((void**)&qkv, g_qkv);
    cudaGetSymbolAddress((void**)&u,   g_u);
    cudaGetSymbolAddress((void**)&a,   g_a);
    cudaGetSymbolAddress((void**)&bb,  g_b);

    // 1: weight prep + zero attn/scale
    k_prep<<<1193, 256>>>(qkv_w, p1w, c1w, p2w, ow, offw, dcnw, c1b, dcnb);
    // 2: qkv projection (reads x channels-last directly)
    k_qkv<<<dim3(256, NB), 128>>>(x, qkv);
    // 3: gram + sumsq
    k_gram<<<dim3(128, NB * 4), 256>>>();
    // 4: softmax + attn@v + LN1 + proj1/gelu
    k_xca_ln_p1<<<dim3(256, NB), 128>>>(temp, nw, nb, p1b);
    // 5: depthwise 5^3
    k_dw5<<<dim3(16, NB * 64), 256>>>(u, c0w, c0b, a);
    // 6: depthwise 7^3 dil 3
    k_dw7<<<dim3(12, NB * 64), 256>>>(a, cspw, cspb, bb);
    // 7: channels-last bf16 copy
    k_to_cl<<<dim3(512, NB), 256>>>(bb);
    // 8: fused offsets conv + deformable conv (bf16 tensor cores)
    k_offdcn_mma<<<dim3(256, NB), 256>>>(offb);
    // 9: conv1*u then proj2+shortcut fused
    k_c1p2<<<dim3(256, NB), 128>>>(p2b);
    // 10: permute + LN2 + output projection
    k_final<<<dim3(4, NB * 64), 128>>>(n2w, n2b, obias, out);
}

// round 12
// speedup vs baseline: 2.7941x; 1.0730x over previous
#include <cuda_runtime.h>
#include <cuda_bf16.h>
#include <mma.h>
#include <math.h>

using namespace nvcuda;

#define NPOS 32768
#define NB 2

// ---------------- scratch (device globals) ----------------
__device__ __align__(16) float g_y2 [NB*64*NPOS];   // proj2+shortcut output
__device__ __align__(16) float g_qkv[NB*192*NPOS];
__device__ __align__(16) float g_x5 [NB*64*NPOS];   // shortcut
__device__ __align__(16) float g_u  [NB*64*NPOS];
__device__ __align__(16) float g_a  [NB*64*NPOS];
__device__ __align__(16) float g_b  [NB*64*NPOS];
__device__ __align__(16) __nv_bfloat16 g_bclh[NB*64*NPOS];  // channels-last bf16 of g_b
__device__ float g_scale[256];                      // RAW sum-of-squares
__device__ float g_attn[NB*4*16*16];                // RAW gram
__device__ __align__(16) float g_qkvT[64*192];
__device__ __align__(16) float g_p1T[64*64];
__device__ __align__(16) float g_c1T[64*64];
__device__ __align__(16) float g_p2T[64*64];
__device__ __align__(16) float g_oT [64*64];
__device__ __align__(16) __nv_bfloat16 g_offWh[27*96*64];   // bf16 [tap][o][c]
__device__ __align__(16) __nv_bfloat16 g_dcnWh[27*64*64];   // bf16 [tap][o][c]
__device__ float g_c1bf[64];

// ---------------- one mega prep kernel (+ zero attn/scale) ----------------
__global__ void k_prep(const float* __restrict__ qkvw, const float* __restrict__ p1w,
                       const float* __restrict__ c1w, const float* __restrict__ p2w,
                       const float* __restrict__ ow,  const float* __restrict__ offw,
                       const float* __restrict__ dcnw, const float* __restrict__ c1b,
                       const float* __restrict__ dcnb) {
    if (blockIdx.x == 0) {
        for (int i = threadIdx.x; i < 2048 + 256; i += 256) {
            if (i < 2048) g_attn[i] = 0.f; else g_scale[i - 2048] = 0.f;
        }
    }
    int i = blockIdx.x * 256 + threadIdx.x;
    if (i < 165888) {                      // offWh [27][96][64]
        int c = i & 63, o = (i >> 6) % 96, k = i / (96 * 64);
        g_offWh[i] = __float2bfloat16((o < 81) ? offw[(o * 64 + c) * 27 + k] : 0.f);
        return;
    }
    int j = i - 165888;
    if (j < 110592) {                      // dcnWh [27][64][64]
        int c = j & 63, o = (j >> 6) & 63, k = j >> 12;
        g_dcnWh[j] = __float2bfloat16(dcnw[(o * 64 + c) * 27 + k]);
        return;
    }
    j -= 110592;
    if (j < 12288) { int c = j / 192, o = j % 192; g_qkvT[j] = qkvw[o * 64 + c]; return; }
    j -= 12288;
    if (j < 4096) { int c = j >> 6, o = j & 63; g_p1T[j] = p1w[o * 64 + c]; return; }
    j -= 4096;
    if (j < 4096) { int c = j >> 6, o = j & 63; g_c1T[j] = c1w[o * 64 + c]; return; }
    j -= 4096;
    if (j < 4096) { int c = j >> 6, o = j & 63; g_p2T[j] = p2w[o * 64 + c]; return; }
    j -= 4096;
    if (j < 4096) { int c = j >> 6, o = j & 63; g_oT[j] = ow[o * 64 + c]; return; }
    j -= 4096;
    if (j < 64) {
        float s = c1b[j];
        for (int c = 0; c < 64; c++) s += c1w[j * 64 + c] * dcnb[c];
        g_c1bf[j] = s;
    }
}

// ---------------- transpose [B,64,N] -> channels-last bf16 [B,N,64] ----------------
__global__ void k_to_cl(const float* __restrict__ in) {
    __shared__ float tile[64][65];
    int b = blockIdx.y; int n0 = blockIdx.x * 64;
    #pragma unroll
    for (int it = 0; it < 16; it++) {
        int idx = it * 256 + threadIdx.x;
        int c = idx >> 6, r = idx & 63;
        tile[r][c] = in[((size_t)b * 64 + c) * NPOS + n0 + r];
    }
    __syncthreads();
    #pragma unroll
    for (int it = 0; it < 8; it++) {                 // bf16x2 writes
        int idx = it * 256 + threadIdx.x;
        int r = idx >> 5, c2 = idx & 31;
        __nv_bfloat162 v = __floats2bfloat162_rn(tile[r][c2 * 2], tile[r][c2 * 2 + 1]);
        *(__nv_bfloat162*)&g_bclh[((size_t)b * NPOS + n0 + r) * 64 + c2 * 2] = v;
    }
}

// ---------------- qkv: 2 halves per position; each thread 96 of 192 outputs ----------------
__global__ void __launch_bounds__(256) k_qkv(const float* __restrict__ x,
                                             float* __restrict__ out) {
    int b = blockIdx.y;
    int p = threadIdx.x & 127, half = threadIdx.x >> 7;
    int n = blockIdx.x * 128 + p;
    const float4* xp = (const float4*)(x + ((size_t)b * NPOS + n) * 64);
    float xv[64];
    #pragma unroll
    for (int q = 0; q < 16; q++) {
        float4 v = xp[q];
        xv[q*4+0] = v.x; xv[q*4+1] = v.y; xv[q*4+2] = v.z; xv[q*4+3] = v.w;
    }
    #pragma unroll 1
    for (int g = 0; g < 6; g++) {
        int oc = half * 6 + g;
        float acc[16];
        #pragma unroll
        for (int j = 0; j < 16; j++) acc[j] = 0.f;
        #pragma unroll
        for (int c = 0; c < 64; c++) {
            float xc = xv[c];
            const float4* w4 = (const float4*)(g_qkvT + c * 192 + oc * 16);
            #pragma unroll
            for (int q = 0; q < 4; q++) {
                float4 w = w4[q];
                acc[q*4+0] += w.x * xc; acc[q*4+1] += w.y * xc;
                acc[q*4+2] += w.z * xc; acc[q*4+3] += w.w * xc;
            }
        }
        #pragma unroll
        for (int j = 0; j < 16; j++)
            out[((size_t)b * 192 + oc * 16 + j) * NPOS + n] = acc[j];
    }
}

// ---------------- gram q.k^T (2x2 register-blocked) + raw sumsq ----------------
__global__ void k_gram() {
    int bh = blockIdx.y; int b = bh >> 2, h = bh & 3;
    int n0 = blockIdx.x * 256;
    __shared__ float qt[16 * 257], kt[16 * 257];
    #pragma unroll
    for (int it = 0; it < 16; it++) {
        qt[it * 257 + threadIdx.x] =
            g_qkv[((size_t)b * 192 + h * 16 + it) * NPOS + n0 + threadIdx.x];
        kt[it * 257 + threadIdx.x] =
            g_qkv[((size_t)b * 192 + 64 + h * 16 + it) * NPOS + n0 + threadIdx.x];
    }
    __syncthreads();
    int t = threadIdx.x;
    {
        int i = t >> 4, j = t & 15;
        float sq = 0.f, sk = 0.f;
        #pragma unroll
        for (int m = 0; m < 16; m++) {
            float a = qt[j * 257 + i * 16 + m]; sq += a * a;
            float bb2 = kt[j * 257 + i * 16 + m]; sk += bb2 * bb2;
        }
        atomicAdd(&g_scale[b * 64 + h * 16 + j], sq);
        atomicAdd(&g_scale[128 + b * 64 + h * 16 + j], sk);
    }
    if (t < 128) {
        int half = t >> 6, tile = t & 63;
        int i0 = (tile >> 3) * 2, j0 = (tile & 7) * 2;
        const float* q0p = qt + i0 * 257 + half * 128;
        const float* q1p = q0p + 257;
        const float* k0p = kt + j0 * 257 + half * 128;
        const float* k1p = k0p + 257;
        float a00 = 0.f, a01 = 0.f, a10 = 0.f, a11 = 0.f;
        #pragma unroll 8
        for (int nn = 0; nn < 128; nn++) {
            float q0 = q0p[nn], q1 = q1p[nn];
            float k0 = k0p[nn], k1 = k1p[nn];
            a00 += q0 * k0; a01 += q0 * k1;
            a10 += q1 * k0; a11 += q1 * k1;
        }
        atomicAdd(&g_attn[(bh * 16 + i0) * 16 + j0], a00);
        atomicAdd(&g_attn[(bh * 16 + i0) * 16 + j0 + 1], a01);
        atomicAdd(&g_attn[(bh * 16 + i0 + 1) * 16 + j0], a10);
        atomicAdd(&g_attn[(bh * 16 + i0 + 1) * 16 + j0 + 1], a11);
    }
}

// ---------------- softmax + attn@v + LN1 + proj1/gelu; 2 halves per position ----------------
__global__ void __launch_bounds__(256) k_xca_ln_p1(const float* __restrict__ temp,
        const float* __restrict__ nw, const float* __restrict__ nb,
        const float* __restrict__ p1b) {
    int b = blockIdx.y;
    __shared__ float asm_s[4 * 256];
    __shared__ float red1[256], red2[256];
    __shared__ float X[128 * 65];                    // normalized x5 tile [p][c]
    if (threadIdx.x < 64) {
        int h = threadIdx.x >> 4, i = threadIdx.x & 15;
        float sq = 1.f / fmaxf(sqrtf(g_scale[b * 64 + h * 16 + i]), 1e-12f);
        float tt = temp[h];
        float v[16], m = -1e30f;
        #pragma unroll
        for (int j = 0; j < 16; j++) {
            float sk = 1.f / fmaxf(sqrtf(g_scale[128 + b * 64 + h * 16 + j]), 1e-12f);
            v[j] = g_attn[(b * 4 + h) * 256 + i * 16 + j] * sq * sk * tt;
            m = fmaxf(m, v[j]);
        }
        float s = 0.f;
        #pragma unroll
        for (int j = 0; j < 16; j++) { v[j] = expf(v[j] - m); s += v[j]; }
        float inv = 1.f / s;
        #pragma unroll
        for (int j = 0; j < 16; j++) asm_s[h * 256 + i * 16 + j] = v[j] * inv;
    }
    __syncthreads();

    int p = threadIdx.x & 127, half = threadIdx.x >> 7;
    int n = blockIdx.x * 128 + p;
    float acc[32];
    #pragma unroll
    for (int c = 0; c < 32; c++) acc[c] = 0.f;
    // my half covers heads half*2 and half*2+1
    #pragma unroll
    for (int hh = 0; hh < 2; hh++) {
        int h = half * 2 + hh;
        const float* vb = g_qkv + ((size_t)b * 192 + 128 + h * 16) * NPOS + n;
        const float* ab = asm_s + h * 256;
        #pragma unroll
        for (int j = 0; j < 16; j++) {
            float vv = vb[(size_t)j * NPOS];
            #pragma unroll
            for (int i = 0; i < 16; i++) acc[hh * 16 + i] += ab[i * 16 + j] * vv;
        }
    }
    // two-pass LN across the two halves
    float s1 = 0.f;
    #pragma unroll
    for (int c = 0; c < 32; c++) s1 += acc[c];
    red1[p * 2 + half] = s1;
    __syncthreads();
    float mean = (red1[p * 2] + red1[p * 2 + 1]) * (1.f / 64.f);
    float s2 = 0.f;
    #pragma unroll
    for (int c = 0; c < 32; c++) { float d = acc[c] - mean; s2 += d * d; }
    red2[p * 2 + half] = s2;
    __syncthreads();
    float rs = rsqrtf((red2[p * 2] + red2[p * 2 + 1]) * (1.f / 64.f) + 1e-5f);
    #pragma unroll
    for (int c = 0; c < 32; c++) {
        int cg = half * 32 + c;
        float v = (acc[c] - mean) * rs * nw[cg] + nb[cg];
        acc[c] = v;
        X[p * 65 + cg] = v;
        g_x5[((size_t)b * 64 + cg) * NPOS + n] = v;
    }
    __syncthreads();
    // u = gelu(p1 @ x5): this thread computes outputs half*32 .. half*32+32
    float a2[32];
    #pragma unroll
    for (int j = 0; j < 32; j++) a2[j] = p1b[half * 32 + j];
    #pragma unroll
    for (int c = 0; c < 64; c++) {
        float xc = X[p * 65 + c];
        const float4* w4 = (const float4*)(g_p1T + c * 64 + half * 32);
        #pragma unroll
        for (int q = 0; q < 8; q++) {
            float4 w = w4[q];
            a2[q*4+0] += w.x * xc; a2[q*4+1] += w.y * xc;
            a2[q*4+2] += w.z * xc; a2[q*4+3] += w.w * xc;
        }
    }
    #pragma unroll
    for (int j = 0; j < 32; j++) {
        float v = a2[j];
        v = 0.5f * v * (1.f + erff(v * 0.70710678118654752f));
        g_u[((size_t)b * 64 + half * 32 + j) * NPOS + n] = v;
    }
}

// ---------------- dw5: k=5, dil=1, pad=2; 8 z-outputs per thread ----------------
__global__ void __launch_bounds__(256) k_dw5(const float* __restrict__ in,
        const float* __restrict__ w, const float* __restrict__ bias,
        float* __restrict__ out) {
    __shared__ float ws[125];
    int bc = blockIdx.y, c = bc & 63;
    for (int i = threadIdx.x; i < 125; i += 256) ws[i] = w[c * 125 + i];
    __syncthreads();
    int task = blockIdx.x * 256 + threadIdx.x;
    int g = task >> 10, yx = task & 1023;
    int y = yx >> 5, x = yx & 31;
    int z0 = g * 8;
    const float* inp = in + (size_t)bc * NPOS;
    float bv = bias[c];
    float acc[8];
    #pragma unroll
    for (int j = 0; j < 8; j++) acc[j] = bv;
    #pragma unroll 1
    for (int ky = 0; ky < 5; ky++) {
        int yy = y + ky - 2; if ((unsigned)yy >= 32u) continue;
        #pragma unroll 1
        for (int kx = 0; kx < 5; kx++) {
            int xx = x + kx - 2; if ((unsigned)xx >= 32u) continue;
            const float* col = inp + yy * 32 + xx;
            float vals[12];
            #pragma unroll
            for (int t = 0; t < 12; t++) {
                int zz = z0 + t - 2;
                vals[t] = ((unsigned)zz < 32u) ? col[zz * 1024] : 0.f;
            }
            float wc[5];
            #pragma unroll
            for (int kz = 0; kz < 5; kz++) wc[kz] = ws[(kz * 5 + ky) * 5 + kx];
            #pragma unroll
            for (int j = 0; j < 8; j++)
                #pragma unroll
                for (int kz = 0; kz < 5; kz++)
                    acc[j] += wc[kz] * vals[j + kz];
        }
    }
    #pragma unroll
    for (int j = 0; j < 8; j++)
        out[(size_t)bc * NPOS + (z0 + j) * 1024 + y * 32 + x] = acc[j];
}

// ---------------- dw7: k=7, dil=3, pad=9; mod-3 z-lattice column per thread ----------------
__global__ void __launch_bounds__(256) k_dw7(const float* __restrict__ in,
        const float* __restrict__ w, const float* __restrict__ bias,
        float* __restrict__ out) {
    __shared__ float ws[343];
    int bc = blockIdx.y, c = bc & 63;
    for (int i = threadIdx.x; i < 343; i += 256) ws[i] = w[c * 343 + i];
    __syncthreads();
    int task = blockIdx.x * 256 + threadIdx.x;
    int r = task >> 10, yx = task & 1023;
    int y = yx >> 5, x = yx & 31;
    int nz = (r == 2) ? 10 : 11;
    const float* inp = in + (size_t)bc * NPOS;
    float bv = bias[c];
    float acc[11];
    #pragma unroll
    for (int j = 0; j < 11; j++) acc[j] = bv;
    #pragma unroll 1
    for (int ky = 0; ky < 7; ky++) {
        int yy = y + ky * 3 - 9; if ((unsigned)yy >= 32u) continue;
        #pragma unroll 1
        for (int kx = 0; kx < 7; kx++) {
            int xx = x + kx * 3 - 9; if ((unsigned)xx >= 32u) continue;
            const float* col = inp + yy * 32 + xx;
            float vals[17];
            #pragma unroll
            for (int t = 0; t < 17; t++) {
                int m = t - 3;
                vals[t] = (m >= 0 && m < nz) ? col[(r + 3 * m) * 1024] : 0.f;
            }
            float wc[7];
            #pragma unroll
            for (int kz = 0; kz < 7; kz++) wc[kz] = ws[(kz * 7 + ky) * 7 + kx];
            #pragma unroll
            for (int j = 0; j < 11; j++)
                #pragma unroll
                for (int kz = 0; kz < 7; kz++)
                    acc[j] += wc[kz] * vals[j + kz];
        }
    }
    #pragma unroll
    for (int j = 0; j < 11; j++)
        if (j < nz) out[(size_t)bc * NPOS + (r + 3 * j) * 1024 + y * 32 + x] = acc[j];
}

// ================= fused offconv + dcn (bf16 wmma, offsets in smem) =================
#define SLDB 72    // bf16 elements per S row (64 + pad)
#define LDP  132   // bf16 elements per offsets row (128 + pad)

__global__ void __launch_bounds__(256) k_offdcn_mma(const float* __restrict__ offb) {
    __shared__ __align__(16) char smem_raw[128 * SLDB * 2 + 96 * LDP * 2];
    __nv_bfloat16* S = (__nv_bfloat16*)smem_raw;
    __nv_bfloat16* OFS = (__nv_bfloat16*)(smem_raw + 128 * SLDB * 2);

    int b = blockIdx.y;
    int n0 = blockIdx.x * 128;
    int z0 = n0 >> 10, y0 = (n0 >> 5) & 31;
    int t = threadIdx.x, warp = t >> 5, lane = t & 31;
    int wm = warp >> 2, wn = warp & 3;

    const uint4* in4 = (const uint4*)g_bclh + (size_t)b * NPOS * 8;

    // ---------- phase 1: offsets conv (64 -> 96 rows, 81 real) ----------
    {
        wmma::fragment<wmma::accumulator,16,16,16,float> acc[3][2];
        #pragma unroll
        for (int mi = 0; mi < 3; mi++)
            #pragma unroll
            for (int ni = 0; ni < 2; ni++) wmma::fill_fragment(acc[mi][ni], 0.f);

        for (int k = 0; k < 27; k++) {
            int dz = k / 9 - 1, dy = (k / 3) % 3 - 1, dx = k % 3 - 1;
            #pragma unroll
            for (int it = 0; it < 4; it++) {
                int idx = it * 256 + t;
                int p = idx >> 3, g = idx & 7;
                int zz = z0 + dz, yy = y0 + (p >> 5) + dy, xx = (p & 31) + dx;
                uint4 v = make_uint4(0u, 0u, 0u, 0u);
                if ((unsigned)zz < 32u && (unsigned)yy < 32u && (unsigned)xx < 32u)
                    v = in4[((size_t)(zz * 1024 + yy * 32 + xx)) * 8 + g];
                *(uint4*)&S[p * SLDB + g * 8] = v;
            }
            __syncthreads();
            #pragma unroll
            for (int ks = 0; ks < 4; ks++) {
                wmma::fragment<wmma::matrix_a,16,16,16,__nv_bfloat16,wmma::row_major> af[3];
                wmma::fragment<wmma::matrix_b,16,16,16,__nv_bfloat16,wmma::col_major> bf[2];
                #pragma unroll
                for (int mi = 0; mi < 3; mi++)
                    wmma::load_matrix_sync(af[mi],
                        g_offWh + ((size_t)k * 96 + wm * 48 + mi * 16) * 64 + ks * 16, 64);
                #pragma unroll
                for (int ni = 0; ni < 2; ni++)
                    wmma::load_matrix_sync(bf[ni], &S[(wn * 32 + ni * 16) * SLDB + ks * 16], SLDB);
                #pragma unroll
                for (int mi = 0; mi < 3; mi++)
                    #pragma unroll
                    for (int ni = 0; ni < 2; ni++)
                        wmma::mma_sync(acc[mi][ni], af[mi], bf[ni], acc[mi][ni]);
            }
            __syncthreads();
        }
        float* stg = (float*)S + warp * 256;
        #pragma unroll
        for (int mi = 0; mi < 3; mi++) {
            #pragma unroll
            for (int ni = 0; ni < 2; ni++) {
                wmma::store_matrix_sync(stg, acc[mi][ni], 16, wmma::mem_row_major);
                __syncwarp();
                int row0 = wm * 48 + mi * 16, col0 = wn * 32 + ni * 16;
                #pragma unroll
                for (int e = 0; e < 8; e++) {
                    int idx = e * 32 + lane;
                    int rr = idx >> 4, cc = idx & 15;
                    OFS[(row0 + rr) * LDP + col0 + cc] = __float2bfloat16(stg[rr * 16 + cc]);
                }
                __syncwarp();
            }
        }
        __syncthreads();
    }

    // ---------- phase 2: deformable conv ----------
    {
        int p = t & 127, half = t >> 7;
        int n = n0 + p;
        int z = n >> 10, y = (n >> 5) & 31, x = n & 31;

        wmma::fragment<wmma::accumulator,16,16,16,float> acc[2][2];
        #pragma unroll
        for (int mi = 0; mi < 2; mi++)
            #pragma unroll
            for (int ni = 0; ni < 2; ni++) wmma::fill_fragment(acc[mi][ni], 0.f);

        for (int k = 0; k < 27; k++) {
            float pz = (float)(z + k / 9 - 1)
                     + __bfloat162float(OFS[(k * 3 + 0) * LDP + p]) + offb[k * 3 + 0];
            float py = (float)(y + (k / 3) % 3 - 1)
                     + __bfloat162float(OFS[(k * 3 + 1) * LDP + p]) + offb[k * 3 + 1];
            float px = (float)(x + k % 3 - 1)
                     + __bfloat162float(OFS[(k * 3 + 2) * LDP + p]) + offb[k * 3 + 2];
            float fz = floorf(pz), fy = floorf(py), fx = floorf(px);
            float wz = pz - fz, wy = py - fy, wx = px - fx;
            int iz = (int)fz, iy = (int)fy, ix = (int)fx;
            float cw[8]; int ci[8];
            #pragma unroll
            for (int m = 0; m < 8; m++) {
                int az = iz + (m >> 2), ay = iy + ((m >> 1) & 1), ax = ix + (m & 1);
                bool ok = ((unsigned)az < 32u) && ((unsigned)ay < 32u) && ((unsigned)ax < 32u);
                float w = ((m >> 2) ? wz : 1.f - wz) * (((m >> 1) & 1) ? wy : 1.f - wy)
                          * ((m & 1) ? wx : 1.f - wx);
                cw[m] = ok ? w : 0.f;
                ci[m] = (min(max(az,0),31) * 32 + min(max(ay,0),31)) * 32 + min(max(ax,0),31);
            }
            #pragma unroll
            for (int q = 0; q < 4; q++) {
                float2 s0 = make_float2(0.f,0.f), s1 = make_float2(0.f,0.f);
                float2 s2 = make_float2(0.f,0.f), s3 = make_float2(0.f,0.f);
                #pragma unroll
                for (int m = 0; m < 8; m++) {
                    uint4 v = in4[(size_t)ci[m] * 8 + half * 4 + q];
                    float2 f0 = __bfloat1622float2(*(__nv_bfloat162*)&v.x);
                    float2 f1 = __bfloat1622float2(*(__nv_bfloat162*)&v.y);
                    float2 f2 = __bfloat1622float2(*(__nv_bfloat162*)&v.z);
                    float2 f3 = __bfloat1622float2(*(__nv_bfloat162*)&v.w);
                    float w = cw[m];
                    s0.x += w * f0.x; s0.y += w * f0.y;
                    s1.x += w * f1.x; s1.y += w * f1.y;
                    s2.x += w * f2.x; s2.y += w * f2.y;
                    s3.x += w * f3.x; s3.y += w * f3.y;
                }
                uint4 ov;
                __nv_bfloat162 o0 = __floats2bfloat162_rn(s0.x, s0.y);
                __nv_bfloat162 o1 = __floats2bfloat162_rn(s1.x, s1.y);
                __nv_bfloat162 o2 = __floats2bfloat162_rn(s2.x, s2.y);
                __nv_bfloat162 o3 = __floats2bfloat162_rn(s3.x, s3.y);
                ov.x = *(unsigned*)&o0; ov.y = *(unsigned*)&o1;
                ov.z = *(unsigned*)&o2; ov.w = *(unsigned*)&o3;
                *(uint4*)&S[p * SLDB + half * 32 + q * 8] = ov;
            }
            __syncthreads();
            #pragma unroll
            for (int ks = 0; ks < 4; ks++) {
                wmma::fragment<wmma::matrix_a,16,16,16,__nv_bfloat16,wmma::row_major> af[2];
                wmma::fragment<wmma::matrix_b,16,16,16,__nv_bfloat16,wmma::col_major> bf[2];
                #pragma unroll
                for (int mi = 0; mi < 2; mi++)
                    wmma::load_matrix_sync(af[mi],
                        g_dcnWh + ((size_t)k * 64 + wm * 32 + mi * 16) * 64 + ks * 16, 64);
                #pragma unroll
                for (int ni = 0; ni < 2; ni++)
                    wmma::load_matrix_sync(bf[ni], &S[(wn * 32 + ni * 16) * SLDB + ks * 16], SLDB);
                #pragma unroll
                for (int mi = 0; mi < 2; mi++)
                    #pragma unroll
                    for (int ni = 0; ni < 2; ni++)
                        wmma::mma_sync(acc[mi][ni], af[mi], bf[ni], acc[mi][ni]);
            }
            __syncthreads();
        }
        #pragma unroll
        for (int mi = 0; mi < 2; mi++)
            #pragma unroll
            for (int ni = 0; ni < 2; ni++)
                wmma::store_matrix_sync(g_a + ((size_t)b * 64 + wm * 32 + mi * 16) * NPOS
                                        + n0 + wn * 32 + ni * 16,
                                        acc[mi][ni], NPOS, wmma::mem_row_major);
    }
}

// ---------------- fused c1*u + proj2 + shortcut; 2 halves per position ----------------
__global__ void __launch_bounds__(256) k_c1p2(const float* __restrict__ p2b) {
    __shared__ float TV[128 * 65];
    int b = blockIdx.y;
    int p = threadIdx.x & 127, half = threadIdx.x >> 7;
    int n = blockIdx.x * 128 + p;
    const float* ap = g_a + (size_t)b * 64 * NPOS + n;
    float av[64];
    #pragma unroll
    for (int c = 0; c < 64; c++) av[c] = ap[(size_t)c * NPOS];
    float tv[32];
    #pragma unroll
    for (int o = 0; o < 32; o++) tv[o] = g_c1bf[half * 32 + o];
    #pragma unroll
    for (int c = 0; c < 64; c++) {
        float xc = av[c];
        const float4* w4 = (const float4*)(g_c1T + c * 64 + half * 32);
        #pragma unroll
        for (int q = 0; q < 8; q++) {
            float4 w = w4[q];
            tv[q*4+0] += w.x * xc; tv[q*4+1] += w.y * xc;
            tv[q*4+2] += w.z * xc; tv[q*4+3] += w.w * xc;
        }
    }
    const float* up = g_u + (size_t)b * 64 * NPOS + n;
    #pragma unroll
    for (int o = 0; o < 32; o++) {
        tv[o] *= up[(size_t)(half * 32 + o) * NPOS];
        TV[p * 65 + half * 32 + o] = tv[o];
    }
    __syncthreads();
    float acc[32];
    #pragma unroll
    for (int o = 0; o < 32; o++) acc[o] = p2b[half * 32 + o];
    #pragma unroll
    for (int c = 0; c < 64; c++) {
        float xc = TV[p * 65 + c];
        const float4* w4 = (const float4*)(g_p2T + c * 64 + half * 32);
        #pragma unroll
        for (int q = 0; q < 8; q++) {
            float4 w = w4[q];
            acc[q*4+0] += w.x * xc; acc[q*4+1] += w.y * xc;
            acc[q*4+2] += w.z * xc; acc[q*4+3] += w.w * xc;
        }
    }
    const float* sp = g_x5 + (size_t)b * 64 * NPOS + n;
    #pragma unroll
    for (int o = 0; o < 32; o++) {
        int og = half * 32 + o;
        g_y2[((size_t)b * 64 + og) * NPOS + n] = acc[o] + sp[(size_t)og * NPOS];
    }
}

// ---------------- final: permuted gather + LN2 + out matvec; 2 halves ----------------
__global__ void __launch_bounds__(256) k_final(const float* __restrict__ w2,
        const float* __restrict__ b2, const float* __restrict__ ob,
        float* __restrict__ out) {
    int bc = blockIdx.y; int b = bc >> 6, c = bc & 63;
    int s = blockIdx.x * 128 + (threadIdx.x & 127);
    int half = threadIdx.x >> 7;
    const float* yp = g_y2 + (size_t)bc * NPOS;
    float r[64], mean = 0.f;
    #pragma unroll
    for (int j = 0; j < 64; j++) { r[j] = yp[j * 512 + s]; mean += r[j]; }
    mean *= (1.f / 64.f);
    float var = 0.f;
    #pragma unroll
    for (int j = 0; j < 64; j++) { float d = r[j] - mean; var += d * d; }
    float rs = rsqrtf(var * (1.f / 64.f) + 1e-5f);
    float acc[32];
    #pragma unroll
    for (int o = 0; o < 32; o++) acc[o] = ob[half * 32 + o];
    #pragma unroll 1
    for (int j = 0; j < 64; j++) {
        float v = (r[j] - mean) * rs * w2[j] + b2[j];
        const float4* w4 = (const float4*)(g_oT + j * 64 + half * 32);
        #pragma unroll
        for (int q = 0; q < 8; q++) {
            float4 w = w4[q];
            acc[q*4+0] += w.x * v; acc[q*4+1] += w.y * v;
            acc[q*4+2] += w.z * v; acc[q*4+3] += w.w * v;
        }
    }
    float4* op = (float4*)(out + ((size_t)b * NPOS + c + 64 * s) * 64 + half * 32);
    #pragma unroll
    for (int q = 0; q < 8; q++)
        op[q] = make_float4(acc[q*4], acc[q*4+1], acc[q*4+2], acc[q*4+3]);
}

// ---------------- launch ----------------
extern "C" void kernel_launch(void* const* d_in, const int* in_sizes, int n_in,
                              void* d_out, int out_size) {
    const float* x     = (const float*)d_in[0];
    const float* temp  = (const float*)d_in[1];
    const float* qkv_w = (const float*)d_in[2];
    const float* nw    = (const float*)d_in[3];
    const float* nb    = (const float*)d_in[4];
    const float* p1w   = (const float*)d_in[5];
    const float* p1b   = (const float*)d_in[6];
    const float* c0w   = (const float*)d_in[7];
    const float* c0b   = (const float*)d_in[8];
    const float* cspw  = (const float*)d_in[9];
    const float* cspb  = (const float*)d_in[10];
    const float* offw  = (const float*)d_in[11];
    const float* offb  = (const float*)d_in[12];
    const float* dcnw  = (const float*)d_in[13];
    const float* dcnb  = (const float*)d_in[14];
    const float* c1w   = (const float*)d_in[15];
    const float* c1b   = (const float*)d_in[16];
    const float* p2w   = (const float*)d_in[17];
    const float* p2b   = (const float*)d_in[18];
    const float* n2w   = (const float*)d_in[19];
    const float* n2b   = (const float*)d_in[20];
    const float* ow    = (const float*)d_in[21];
    const float* obias = (const float*)d_in[22];
    float* out = (float*)d_out;

    float *qkv, *u, *a, *bb;
    cudaGetSymbolAddress((void**)&qkv, g_qkv);
    cudaGetSymbolAddress((void**)&u,   g_u);
    cudaGetSymbolAddress((void**)&a,   g_a);
    cudaGetSymbolAddress((void**)&bb,  g_b);

    // 1: weight prep + zero attn/scale
    k_prep<<<1193, 256>>>(qkv_w, p1w, c1w, p2w, ow, offw, dcnw, c1b, dcnb);
    // 2: qkv projection (channel-split, 2 halves)
    k_qkv<<<dim3(256, NB), 256>>>(x, qkv);
    // 3: gram + sumsq
    k_gram<<<dim3(128, NB * 4), 256>>>();
    // 4: softmax + attn@v + LN1 + proj1/gelu (channel-split)
    k_xca_ln_p1<<<dim3(256, NB), 256>>>(temp, nw, nb, p1b);
    // 5: depthwise 5^3
    k_dw5<<<dim3(16, NB * 64), 256>>>(u, c0w, c0b, a);
    // 6: depthwise 7^3 dil 3
    k_dw7<<<dim3(12, NB * 64), 256>>>(a, cspw, cspb, bb);
    // 7: channels-last bf16 copy
    k_to_cl<<<dim3(512, NB), 256>>>(bb);
    // 8: fused offsets conv + deformable conv (bf16 tensor cores)
    k_offdcn_mma<<<dim3(256, NB), 256>>>(offb);
    // 9: conv1*u then proj2+shortcut (channel-split)
    k_c1p2<<<dim3(256, NB), 256>>>(p2b);
    // 10: permute + LN2 + output projection (channel-split)
    k_final<<<dim3(4, NB * 64), 256>>>(n2w, n2b, obias, out);
}

// round 14
// speedup vs baseline: 3.1338x; 1.1216x over previous
#include <cuda_runtime.h>
#include <cuda_bf16.h>
#include <mma.h>
#include <math.h>

using namespace nvcuda;

#define NPOS 32768
#define NB 2

// ---------------- scratch (device globals) ----------------
__device__ __align__(16) float g_y2 [NB*64*NPOS];   // proj2+shortcut output
__device__ __align__(16) float g_qkv[NB*192*NPOS];
__device__ __align__(16) float g_x5 [NB*64*NPOS];   // shortcut
__device__ __align__(16) float g_u  [NB*64*NPOS];
__device__ __align__(16) float g_a  [NB*64*NPOS];
__device__ __align__(16) float g_b  [NB*64*NPOS];
__device__ __align__(16) __nv_bfloat16 g_bclh[NB*64*NPOS];  // channels-last bf16 of g_b
__device__ float g_scale[256];                      // RAW sum-of-squares
__device__ float g_attn[NB*4*16*16];                // RAW gram
__device__ __align__(16) float g_qkvT[64*192];
__device__ __align__(16) float g_p1T[64*64];
__device__ __align__(16) float g_c1T[64*64];
__device__ __align__(16) float g_p2T[64*64];
__device__ __align__(16) float g_oT [64*64];
__device__ __align__(16) __nv_bfloat16 g_offWh[27*96*64];   // bf16 [tap][o][c]
__device__ __align__(16) __nv_bfloat16 g_dcnWh[27*64*64];   // bf16 [tap][o][c]
__device__ float g_c1bf[64];

// ---------------- one mega prep kernel (+ zero attn/scale) ----------------
__global__ void k_prep(const float* __restrict__ qkvw, const float* __restrict__ p1w,
                       const float* __restrict__ c1w, const float* __restrict__ p2w,
                       const float* __restrict__ ow,  const float* __restrict__ offw,
                       const float* __restrict__ dcnw, const float* __restrict__ c1b,
                       const float* __restrict__ dcnb) {
    if (blockIdx.x == 0) {
        for (int i = threadIdx.x; i < 2048 + 256; i += 256) {
            if (i < 2048) g_attn[i] = 0.f; else g_scale[i - 2048] = 0.f;
        }
    }
    int i = blockIdx.x * 256 + threadIdx.x;
    if (i < 165888) {                      // offWh [27][96][64]
        int c = i & 63, o = (i >> 6) % 96, k = i / (96 * 64);
        g_offWh[i] = __float2bfloat16((o < 81) ? offw[(o * 64 + c) * 27 + k] : 0.f);
        return;
    }
    int j = i - 165888;
    if (j < 110592) {                      // dcnWh [27][64][64]
        int c = j & 63, o = (j >> 6) & 63, k = j >> 12;
        g_dcnWh[j] = __float2bfloat16(dcnw[(o * 64 + c) * 27 + k]);
        return;
    }
    j -= 110592;
    if (j < 12288) { int c = j / 192, o = j % 192; g_qkvT[j] = qkvw[o * 64 + c]; return; }
    j -= 12288;
    if (j < 4096) { int c = j >> 6, o = j & 63; g_p1T[j] = p1w[o * 64 + c]; return; }
    j -= 4096;
    if (j < 4096) { int c = j >> 6, o = j & 63; g_c1T[j] = c1w[o * 64 + c]; return; }
    j -= 4096;
    if (j < 4096) { int c = j >> 6, o = j & 63; g_p2T[j] = p2w[o * 64 + c]; return; }
    j -= 4096;
    if (j < 4096) { int c = j >> 6, o = j & 63; g_oT[j] = ow[o * 64 + c]; return; }
    j -= 4096;
    if (j < 64) {
        float s = c1b[j];
        for (int c = 0; c < 64; c++) s += c1w[j * 64 + c] * dcnb[c];
        g_c1bf[j] = s;
    }
}

// ---------------- transpose [B,64,N] -> channels-last bf16 [B,N,64] ----------------
__global__ void k_to_cl(const float* __restrict__ in) {
    __shared__ float tile[64][65];
    int b = blockIdx.y; int n0 = blockIdx.x * 64;
    #pragma unroll
    for (int it = 0; it < 16; it++) {
        int idx = it * 256 + threadIdx.x;
        int c = idx >> 6, r = idx & 63;
        tile[r][c] = in[((size_t)b * 64 + c) * NPOS + n0 + r];
    }
    __syncthreads();
    #pragma unroll
    for (int it = 0; it < 8; it++) {                 // bf16x2 writes
        int idx = it * 256 + threadIdx.x;
        int r = idx >> 5, c2 = idx & 31;
        __nv_bfloat162 v = __floats2bfloat162_rn(tile[r][c2 * 2], tile[r][c2 * 2 + 1]);
        *(__nv_bfloat162*)&g_bclh[((size_t)b * NPOS + n0 + r) * 64 + c2 * 2] = v;
    }
}

// ---------------- qkv: 2 halves per position; each thread 96 of 192 outputs ----------------
__global__ void __launch_bounds__(256) k_qkv(const float* __restrict__ x,
                                             float* __restrict__ out) {
    int b = blockIdx.y;
    int p = threadIdx.x & 127, half = threadIdx.x >> 7;
    int n = blockIdx.x * 128 + p;
    const float4* xp = (const float4*)(x + ((size_t)b * NPOS + n) * 64);
    float xv[64];
    #pragma unroll
    for (int q = 0; q < 16; q++) {
        float4 v = xp[q];
        xv[q*4+0] = v.x; xv[q*4+1] = v.y; xv[q*4+2] = v.z; xv[q*4+3] = v.w;
    }
    #pragma unroll 1
    for (int g = 0; g < 6; g++) {
        int oc = half * 6 + g;
        float acc[16];
        #pragma unroll
        for (int j = 0; j < 16; j++) acc[j] = 0.f;
        #pragma unroll
        for (int c = 0; c < 64; c++) {
            float xc = xv[c];
            const float4* w4 = (const float4*)(g_qkvT + c * 192 + oc * 16);
            #pragma unroll
            for (int q = 0; q < 4; q++) {
                float4 w = w4[q];
                acc[q*4+0] += w.x * xc; acc[q*4+1] += w.y * xc;
                acc[q*4+2] += w.z * xc; acc[q*4+3] += w.w * xc;
            }
        }
        #pragma unroll
        for (int j = 0; j < 16; j++)
            out[((size_t)b * 192 + oc * 16 + j) * NPOS + n] = acc[j];
    }
}

// ---------------- gram q.k^T (2x2 register-blocked) + raw sumsq ----------------
__global__ void k_gram() {
    int bh = blockIdx.y; int b = bh >> 2, h = bh & 3;
    int n0 = blockIdx.x * 256;
    __shared__ float qt[16 * 257], kt[16 * 257];
    #pragma unroll
    for (int it = 0; it < 16; it++) {
        qt[it * 257 + threadIdx.x] =
            g_qkv[((size_t)b * 192 + h * 16 + it) * NPOS + n0 + threadIdx.x];
        kt[it * 257 + threadIdx.x] =
            g_qkv[((size_t)b * 192 + 64 + h * 16 + it) * NPOS + n0 + threadIdx.x];
    }
    __syncthreads();
    int t = threadIdx.x;
    {
        int i = t >> 4, j = t & 15;
        float sq = 0.f, sk = 0.f;
        #pragma unroll
        for (int m = 0; m < 16; m++) {
            float a = qt[j * 257 + i * 16 + m]; sq += a * a;
            float bb2 = kt[j * 257 + i * 16 + m]; sk += bb2 * bb2;
        }
        atomicAdd(&g_scale[b * 64 + h * 16 + j], sq);
        atomicAdd(&g_scale[128 + b * 64 + h * 16 + j], sk);
    }
    if (t < 128) {
        int half = t >> 6, tile = t & 63;
        int i0 = (tile >> 3) * 2, j0 = (tile & 7) * 2;
        const float* q0p = qt + i0 * 257 + half * 128;
        const float* q1p = q0p + 257;
        const float* k0p = kt + j0 * 257 + half * 128;
        const float* k1p = k0p + 257;
        float a00 = 0.f, a01 = 0.f, a10 = 0.f, a11 = 0.f;
        #pragma unroll 8
        for (int nn = 0; nn < 128; nn++) {
            float q0 = q0p[nn], q1 = q1p[nn];
            float k0 = k0p[nn], k1 = k1p[nn];
            a00 += q0 * k0; a01 += q0 * k1;
            a10 += q1 * k0; a11 += q1 * k1;
        }
        atomicAdd(&g_attn[(bh * 16 + i0) * 16 + j0], a00);
        atomicAdd(&g_attn[(bh * 16 + i0) * 16 + j0 + 1], a01);
        atomicAdd(&g_attn[(bh * 16 + i0 + 1) * 16 + j0], a10);
        atomicAdd(&g_attn[(bh * 16 + i0 + 1) * 16 + j0 + 1], a11);
    }
}

// ---------------- softmax + attn@v + LN1 + proj1/gelu; 2 halves per position ----------------
__global__ void __launch_bounds__(256) k_xca_ln_p1(const float* __restrict__ temp,
        const float* __restrict__ nw, const float* __restrict__ nb,
        const float* __restrict__ p1b) {
    int b = blockIdx.y;
    __shared__ float asm_s[4 * 256];
    __shared__ float red1[256], red2[256];
    __shared__ float X[128 * 65];                    // normalized x5 tile [p][c]
    if (threadIdx.x < 64) {
        int h = threadIdx.x >> 4, i = threadIdx.x & 15;
        float sq = 1.f / fmaxf(sqrtf(g_scale[b * 64 + h * 16 + i]), 1e-12f);
        float tt = temp[h];
        float v[16], m = -1e30f;
        #pragma unroll
        for (int j = 0; j < 16; j++) {
            float sk = 1.f / fmaxf(sqrtf(g_scale[128 + b * 64 + h * 16 + j]), 1e-12f);
            v[j] = g_attn[(b * 4 + h) * 256 + i * 16 + j] * sq * sk * tt;
            m = fmaxf(m, v[j]);
        }
        float s = 0.f;
        #pragma unroll
        for (int j = 0; j < 16; j++) { v[j] = expf(v[j] - m); s += v[j]; }
        float inv = 1.f / s;
        #pragma unroll
        for (int j = 0; j < 16; j++) asm_s[h * 256 + i * 16 + j] = v[j] * inv;
    }
    __syncthreads();

    int p = threadIdx.x & 127, half = threadIdx.x >> 7;
    int n = blockIdx.x * 128 + p;
    float acc[32];
    #pragma unroll
    for (int c = 0; c < 32; c++) acc[c] = 0.f;
    #pragma unroll
    for (int hh = 0; hh < 2; hh++) {
        int h = half * 2 + hh;
        const float* vb = g_qkv + ((size_t)b * 192 + 128 + h * 16) * NPOS + n;
        const float* ab = asm_s + h * 256;
        #pragma unroll
        for (int j = 0; j < 16; j++) {
            float vv = vb[(size_t)j * NPOS];
            #pragma unroll
            for (int i = 0; i < 16; i++) acc[hh * 16 + i] += ab[i * 16 + j] * vv;
        }
    }
    float s1 = 0.f;
    #pragma unroll
    for (int c = 0; c < 32; c++) s1 += acc[c];
    red1[p * 2 + half] = s1;
    __syncthreads();
    float mean = (red1[p * 2] + red1[p * 2 + 1]) * (1.f / 64.f);
    float s2 = 0.f;
    #pragma unroll
    for (int c = 0; c < 32; c++) { float d = acc[c] - mean; s2 += d * d; }
    red2[p * 2 + half] = s2;
    __syncthreads();
    float rs = rsqrtf((red2[p * 2] + red2[p * 2 + 1]) * (1.f / 64.f) + 1e-5f);
    #pragma unroll
    for (int c = 0; c < 32; c++) {
        int cg = half * 32 + c;
        float v = (acc[c] - mean) * rs * nw[cg] + nb[cg];
        acc[c] = v;
        X[p * 65 + cg] = v;
        g_x5[((size_t)b * 64 + cg) * NPOS + n] = v;
    }
    __syncthreads();
    float a2[32];
    #pragma unroll
    for (int j = 0; j < 32; j++) a2[j] = p1b[half * 32 + j];
    #pragma unroll
    for (int c = 0; c < 64; c++) {
        float xc = X[p * 65 + c];
        const float4* w4 = (const float4*)(g_p1T + c * 64 + half * 32);
        #pragma unroll
        for (int q = 0; q < 8; q++) {
            float4 w = w4[q];
            a2[q*4+0] += w.x * xc; a2[q*4+1] += w.y * xc;
            a2[q*4+2] += w.z * xc; a2[q*4+3] += w.w * xc;
        }
    }
    #pragma unroll
    for (int j = 0; j < 32; j++) {
        float v = a2[j];
        v = 0.5f * v * (1.f + erff(v * 0.70710678118654752f));
        g_u[((size_t)b * 64 + half * 32 + j) * NPOS + n] = v;
    }
}

// ---------------- dw5: k=5, dil=1, pad=2; 8 z-outputs per thread ----------------
__global__ void __launch_bounds__(256) k_dw5(const float* __restrict__ in,
        const float* __restrict__ w, const float* __restrict__ bias,
        float* __restrict__ out) {
    __shared__ float ws[125];
    int bc = blockIdx.y, c = bc & 63;
    for (int i = threadIdx.x; i < 125; i += 256) ws[i] = w[c * 125 + i];
    __syncthreads();
    int task = blockIdx.x * 256 + threadIdx.x;
    int g = task >> 10, yx = task & 1023;
    int y = yx >> 5, x = yx & 31;
    int z0 = g * 8;
    const float* inp = in + (size_t)bc * NPOS;
    float bv = bias[c];
    float acc[8];
    #pragma unroll
    for (int j = 0; j < 8; j++) acc[j] = bv;
    #pragma unroll 1
    for (int ky = 0; ky < 5; ky++) {
        int yy = y + ky - 2; if ((unsigned)yy >= 32u) continue;
        #pragma unroll 1
        for (int kx = 0; kx < 5; kx++) {
            int xx = x + kx - 2; if ((unsigned)xx >= 32u) continue;
            const float* col = inp + yy * 32 + xx;
            float vals[12];
            #pragma unroll
            for (int t = 0; t < 12; t++) {
                int zz = z0 + t - 2;
                vals[t] = ((unsigned)zz < 32u) ? col[zz * 1024] : 0.f;
            }
            float wc[5];
            #pragma unroll
            for (int kz = 0; kz < 5; kz++) wc[kz] = ws[(kz * 5 + ky) * 5 + kx];
            #pragma unroll
            for (int j = 0; j < 8; j++)
                #pragma unroll
                for (int kz = 0; kz < 5; kz++)
                    acc[j] += wc[kz] * vals[j + kz];
        }
    }
    #pragma unroll
    for (int j = 0; j < 8; j++)
        out[(size_t)bc * NPOS + (z0 + j) * 1024 + y * 32 + x] = acc[j];
}

// ---------------- dw7: k=7, dil=3, pad=9; mod-3 z-lattice column per thread ----------------
__global__ void __launch_bounds__(256) k_dw7(const float* __restrict__ in,
        const float* __restrict__ w, const float* __restrict__ bias,
        float* __restrict__ out) {
    __shared__ float ws[343];
    int bc = blockIdx.y, c = bc & 63;
    for (int i = threadIdx.x; i < 343; i += 256) ws[i] = w[c * 343 + i];
    __syncthreads();
    int task = blockIdx.x * 256 + threadIdx.x;
    int r = task >> 10, yx = task & 1023;
    int y = yx >> 5, x = yx & 31;
    int nz = (r == 2) ? 10 : 11;
    const float* inp = in + (size_t)bc * NPOS;
    float bv = bias[c];
    float acc[11];
    #pragma unroll
    for (int j = 0; j < 11; j++) acc[j] = bv;
    #pragma unroll 1
    for (int ky = 0; ky < 7; ky++) {
        int yy = y + ky * 3 - 9; if ((unsigned)yy >= 32u) continue;
        #pragma unroll 1
        for (int kx = 0; kx < 7; kx++) {
            int xx = x + kx * 3 - 9; if ((unsigned)xx >= 32u) continue;
            const float* col = inp + yy * 32 + xx;
            float vals[17];
            #pragma unroll
            for (int t = 0; t < 17; t++) {
                int m = t - 3;
                vals[t] = (m >= 0 && m < nz) ? col[(r + 3 * m) * 1024] : 0.f;
            }
            float wc[7];
            #pragma unroll
            for (int kz = 0; kz < 7; kz++) wc[kz] = ws[(kz * 7 + ky) * 7 + kx];
            #pragma unroll
            for (int j = 0; j < 11; j++)
                #pragma unroll
                for (int kz = 0; kz < 7; kz++)
                    acc[j] += wc[kz] * vals[j + kz];
        }
    }
    #pragma unroll
    for (int j = 0; j < 11; j++)
        if (j < nz) out[(size_t)bc * NPOS + (r + 3 * j) * 1024 + y * 32 + x] = acc[j];
}

// ================= fused offconv + dcn (bf16 wmma, offsets in smem) =================
#define SLDB 72    // bf16 elements per S row (64 + pad)
#define LDP  132   // bf16 elements per offsets row (128 + pad)

__global__ void __launch_bounds__(256) k_offdcn_mma(const float* __restrict__ offb) {
    __shared__ __align__(16) char smem_raw[128 * SLDB * 2 + 96 * LDP * 2];
    __shared__ __nv_bfloat16 CW[128 * 8];            // trilinear corner weights
    __shared__ unsigned short CI[128 * 8];           // corner spatial indices
    __nv_bfloat16* S = (__nv_bfloat16*)smem_raw;
    __nv_bfloat16* OFS = (__nv_bfloat16*)(smem_raw + 128 * SLDB * 2);

    int b = blockIdx.y;
    int n0 = blockIdx.x * 128;
    int z0 = n0 >> 10, y0 = (n0 >> 5) & 31;
    int t = threadIdx.x, warp = t >> 5, lane = t & 31;
    int wm = warp >> 2, wn = warp & 3;

    const uint4* in4 = (const uint4*)g_bclh + (size_t)b * NPOS * 8;

    // ---------- phase 1: offsets conv (64 -> 96 rows, 81 real) ----------
    {
        wmma::fragment<wmma::accumulator,16,16,16,float> acc[3][2];
        #pragma unroll
        for (int mi = 0; mi < 3; mi++)
            #pragma unroll
            for (int ni = 0; ni < 2; ni++) wmma::fill_fragment(acc[mi][ni], 0.f);

        for (int k = 0; k < 27; k++) {
            int dz = k / 9 - 1, dy = (k / 3) % 3 - 1, dx = k % 3 - 1;
            #pragma unroll
            for (int it = 0; it < 4; it++) {
                int idx = it * 256 + t;
                int p = idx >> 3, g = idx & 7;
                int zz = z0 + dz, yy = y0 + (p >> 5) + dy, xx = (p & 31) + dx;
                uint4 v = make_uint4(0u, 0u, 0u, 0u);
                if ((unsigned)zz < 32u && (unsigned)yy < 32u && (unsigned)xx < 32u)
                    v = in4[((size_t)(zz * 1024 + yy * 32 + xx)) * 8 + g];
                *(uint4*)&S[p * SLDB + g * 8] = v;
            }
            __syncthreads();
            #pragma unroll
            for (int ks = 0; ks < 4; ks++) {
                wmma::fragment<wmma::matrix_a,16,16,16,__nv_bfloat16,wmma::row_major> af[3];
                wmma::fragment<wmma::matrix_b,16,16,16,__nv_bfloat16,wmma::col_major> bf[2];
                #pragma unroll
                for (int mi = 0; mi < 3; mi++)
                    wmma::load_matrix_sync(af[mi],
                        g_offWh + ((size_t)k * 96 + wm * 48 + mi * 16) * 64 + ks * 16, 64);
                #pragma unroll
                for (int ni = 0; ni < 2; ni++)
                    wmma::load_matrix_sync(bf[ni], &S[(wn * 32 + ni * 16) * SLDB + ks * 16], SLDB);
                #pragma unroll
                for (int mi = 0; mi < 3; mi++)
                    #pragma unroll
                    for (int ni = 0; ni < 2; ni++)
                        wmma::mma_sync(acc[mi][ni], af[mi], bf[ni], acc[mi][ni]);
            }
            __syncthreads();
        }
        float* stg = (float*)S + warp * 256;
        #pragma unroll
        for (int mi = 0; mi < 3; mi++) {
            #pragma unroll
            for (int ni = 0; ni < 2; ni++) {
                wmma::store_matrix_sync(stg, acc[mi][ni], 16, wmma::mem_row_major);
                __syncwarp();
                int row0 = wm * 48 + mi * 16, col0 = wn * 32 + ni * 16;
                #pragma unroll
                for (int e = 0; e < 8; e++) {
                    int idx = e * 32 + lane;
                    int rr = idx >> 4, cc = idx & 15;
                    OFS[(row0 + rr) * LDP + col0 + cc] = __float2bfloat16(stg[rr * 16 + cc]);
                }
                __syncwarp();
            }
        }
        __syncthreads();
    }

    // ---------- phase 2: deformable conv ----------
    {
        int p = t & 127, half = t >> 7;
        int pg = t >> 3, gg = t & 7;                 // gather mapping: 8 threads/position

        wmma::fragment<wmma::accumulator,16,16,16,float> acc[2][2];
        #pragma unroll
        for (int mi = 0; mi < 2; mi++)
            #pragma unroll
            for (int ni = 0; ni < 2; ni++) wmma::fill_fragment(acc[mi][ni], 0.f);

        int np = n0 + p;
        int z = np >> 10, y = (np >> 5) & 31, x = np & 31;

        for (int k = 0; k < 27; k++) {
            // corner setup: 2 threads per position; each writes 4 corners to smem
            {
                float pz = (float)(z + k / 9 - 1)
                         + __bfloat162float(OFS[(k * 3 + 0) * LDP + p]) + offb[k * 3 + 0];
                float py = (float)(y + (k / 3) % 3 - 1)
                         + __bfloat162float(OFS[(k * 3 + 1) * LDP + p]) + offb[k * 3 + 1];
                float px = (float)(x + k % 3 - 1)
                         + __bfloat162float(OFS[(k * 3 + 2) * LDP + p]) + offb[k * 3 + 2];
                float fz = floorf(pz), fy = floorf(py), fx = floorf(px);
                float wz = pz - fz, wy = py - fy, wx = px - fx;
                int iz = (int)fz, iy = (int)fy, ix = (int)fx;
                #pragma unroll
                for (int mm = 0; mm < 4; mm++) {
                    int m = half * 4 + mm;
                    int az = iz + (m >> 2), ay = iy + ((m >> 1) & 1), ax = ix + (m & 1);
                    bool ok = ((unsigned)az < 32u) && ((unsigned)ay < 32u) && ((unsigned)ax < 32u);
                    float w = ((m >> 2) ? wz : 1.f - wz) * (((m >> 1) & 1) ? wy : 1.f - wy)
                              * ((m & 1) ? wx : 1.f - wx);
                    CW[p * 8 + m] = __float2bfloat16(ok ? w : 0.f);
                    CI[p * 8 + m] = (unsigned short)((min(max(az,0),31) * 32
                                   + min(max(ay,0),31)) * 32 + min(max(ax,0),31));
                }
            }
            __syncthreads();
            // coalesced gather: thread (pg_pass, gg) handles 16B chunk gg of one position
            #pragma unroll
            for (int pass = 0; pass < 4; pass++) {
                int pp = pass * 32 + pg;
                float2 s0 = make_float2(0.f,0.f), s1 = make_float2(0.f,0.f);
                float2 s2 = make_float2(0.f,0.f), s3 = make_float2(0.f,0.f);
                #pragma unroll
                for (int m = 0; m < 8; m++) {
                    float w = __bfloat162float(CW[pp * 8 + m]);
                    int idx = CI[pp * 8 + m];
                    uint4 v = in4[(size_t)idx * 8 + gg];
                    float2 f0 = __bfloat1622float2(*(__nv_bfloat162*)&v.x);
                    float2 f1 = __bfloat1622float2(*(__nv_bfloat162*)&v.y);
                    float2 f2 = __bfloat1622float2(*(__nv_bfloat162*)&v.z);
                    float2 f3 = __bfloat1622float2(*(__nv_bfloat162*)&v.w);
                    s0.x += w * f0.x; s0.y += w * f0.y;
                    s1.x += w * f1.x; s1.y += w * f1.y;
                    s2.x += w * f2.x; s2.y += w * f2.y;
                    s3.x += w * f3.x; s3.y += w * f3.y;
                }
                uint4 ov;
                __nv_bfloat162 o0 = __floats2bfloat162_rn(s0.x, s0.y);
                __nv_bfloat162 o1 = __floats2bfloat162_rn(s1.x, s1.y);
                __nv_bfloat162 o2 = __floats2bfloat162_rn(s2.x, s2.y);
                __nv_bfloat162 o3 = __floats2bfloat162_rn(s3.x, s3.y);
                ov.x = *(unsigned*)&o0; ov.y = *(unsigned*)&o1;
                ov.z = *(unsigned*)&o2; ov.w = *(unsigned*)&o3;
                *(uint4*)&S[pp * SLDB + gg * 8] = ov;
            }
            __syncthreads();
            #pragma unroll
            for (int ks = 0; ks < 4; ks++) {
                wmma::fragment<wmma::matrix_a,16,16,16,__nv_bfloat16,wmma::row_major> af[2];
                wmma::fragment<wmma::matrix_b,16,16,16,__nv_bfloat16,wmma::col_major> bf[2];
                #pragma unroll
                for (int mi = 0; mi < 2; mi++)
                    wmma::load_matrix_sync(af[mi],
                        g_dcnWh + ((size_t)k * 64 + wm * 32 + mi * 16) * 64 + ks * 16, 64);
                #pragma unroll
                for (int ni = 0; ni < 2; ni++)
                    wmma::load_matrix_sync(bf[ni], &S[(wn * 32 + ni * 16) * SLDB + ks * 16], SLDB);
                #pragma unroll
                for (int mi = 0; mi < 2; mi++)
                    #pragma unroll
                    for (int ni = 0; ni < 2; ni++)
                        wmma::mma_sync(acc[mi][ni], af[mi], bf[ni], acc[mi][ni]);
            }
            __syncthreads();
        }
        #pragma unroll
        for (int mi = 0; mi < 2; mi++)
            #pragma unroll
            for (int ni = 0; ni < 2; ni++)
                wmma::store_matrix_sync(g_a + ((size_t)b * 64 + wm * 32 + mi * 16) * NPOS
                                        + n0 + wn * 32 + ni * 16,
                                        acc[mi][ni], NPOS, wmma::mem_row_major);
    }
}

// ---------------- fused c1*u + proj2 + shortcut; 2 halves per position ----------------
__global__ void __launch_bounds__(256) k_c1p2(const float* __restrict__ p2b) {
    __shared__ float TV[128 * 65];
    int b = blockIdx.y;
    int p = threadIdx.x & 127, half = threadIdx.x >> 7;
    int n = blockIdx.x * 128 + p;
    const float* ap = g_a + (size_t)b * 64 * NPOS + n;
    float av[64];
    #pragma unroll
    for (int c = 0; c < 64; c++) av[c] = ap[(size_t)c * NPOS];
    float tv[32];
    #pragma unroll
    for (int o = 0; o < 32; o++) tv[o] = g_c1bf[half * 32 + o];
    #pragma unroll
    for (int c = 0; c < 64; c++) {
        float xc = av[c];
        const float4* w4 = (const float4*)(g_c1T + c * 64 + half * 32);
        #pragma unroll
        for (int q = 0; q < 8; q++) {
            float4 w = w4[q];
            tv[q*4+0] += w.x * xc; tv[q*4+1] += w.y * xc;
            tv[q*4+2] += w.z * xc; tv[q*4+3] += w.w * xc;
        }
    }
    const float* up = g_u + (size_t)b * 64 * NPOS + n;
    #pragma unroll
    for (int o = 0; o < 32; o++) {
        tv[o] *= up[(size_t)(half * 32 + o) * NPOS];
        TV[p * 65 + half * 32 + o] = tv[o];
    }
    __syncthreads();
    float acc[32];
    #pragma unroll
    for (int o = 0; o < 32; o++) acc[o] = p2b[half * 32 + o];
    #pragma unroll
    for (int c = 0; c < 64; c++) {
        float xc = TV[p * 65 + c];
        const float4* w4 = (const float4*)(g_p2T + c * 64 + half * 32);
        #pragma unroll
        for (int q = 0; q < 8; q++) {
            float4 w = w4[q];
            acc[q*4+0] += w.x * xc; acc[q*4+1] += w.y * xc;
            acc[q*4+2] += w.z * xc; acc[q*4+3] += w.w * xc;
        }
    }
    const float* sp = g_x5 + (size_t)b * 64 * NPOS + n;
    #pragma unroll
    for (int o = 0; o < 32; o++) {
        int og = half * 32 + o;
        g_y2[((size_t)b * 64 + og) * NPOS + n] = acc[o] + sp[(size_t)og * NPOS];
    }
}

// ---------------- final: permuted gather + LN2 + out matvec; 2 halves ----------------
__global__ void __launch_bounds__(256) k_final(const float* __restrict__ w2,
        const float* __restrict__ b2, const float* __restrict__ ob,
        float* __restrict__ out) {
    int bc = blockIdx.y; int b = bc >> 6, c = bc & 63;
    int s = blockIdx.x * 128 + (threadIdx.x & 127);
    int half = threadIdx.x >> 7;
    const float* yp = g_y2 + (size_t)bc * NPOS;
    float r[64], mean = 0.f;
    #pragma unroll
    for (int j = 0; j < 64; j++) { r[j] = yp[j * 512 + s]; mean += r[j]; }
    mean *= (1.f / 64.f);
    float var = 0.f;
    #pragma unroll
    for (int j = 0; j < 64; j++) { float d = r[j] - mean; var += d * d; }
    float rs = rsqrtf(var * (1.f / 64.f) + 1e-5f);
    float acc[32];
    #pragma unroll
    for (int o = 0; o < 32; o++) acc[o] = ob[half * 32 + o];
    #pragma unroll 1
    for (int j = 0; j < 64; j++) {
        float v = (r[j] - mean) * rs * w2[j] + b2[j];
        const float4* w4 = (const float4*)(g_oT + j * 64 + half * 32);
        #pragma unroll
        for (int q = 0; q < 8; q++) {
            float4 w = w4[q];
            acc[q*4+0] += w.x * v; acc[q*4+1] += w.y * v;
            acc[q*4+2] += w.z * v; acc[q*4+3] += w.w * v;
        }
    }
    float4* op = (float4*)(out + ((size_t)b * NPOS + c + 64 * s) * 64 + half * 32);
    #pragma unroll
    for (int q = 0; q < 8; q++)
        op[q] = make_float4(acc[q*4], acc[q*4+1], acc[q*4+2], acc[q*4+3]);
}

// ---------------- launch ----------------
extern "C" void kernel_launch(void* const* d_in, const int* in_sizes, int n_in,
                              void* d_out, int out_size) {
    const float* x     = (const float*)d_in[0];
    const float* temp  = (const float*)d_in[1];
    const float* qkv_w = (const float*)d_in[2];
    const float* nw    = (const float*)d_in[3];
    const float* nb    = (const float*)d_in[4];
    const float* p1w   = (const float*)d_in[5];
    const float* p1b   = (const float*)d_in[6];
    const float* c0w   = (const float*)d_in[7];
    const float* c0b   = (const float*)d_in[8];
    const float* cspw  = (const float*)d_in[9];
    const float* cspb  = (const float*)d_in[10];
    const float* offw  = (const float*)d_in[11];
    const float* offb  = (const float*)d_in[12];
    const float* dcnw  = (const float*)d_in[13];
    const float* dcnb  = (const float*)d_in[14];
    const float* c1w   = (const float*)d_in[15];
    const float* c1b   = (const float*)d_in[16];
    const float* p2w   = (const float*)d_in[17];
    const float* p2b   = (const float*)d_in[18];
    const float* n2w   = (const float*)d_in[19];
    const float* n2b   = (const float*)d_in[20];
    const float* ow    = (const float*)d_in[21];
    const float* obias = (const float*)d_in[22];
    float* out = (float*)d_out;

    float *qkv, *u, *a, *bb;
    cudaGetSymbolAddress((void**)&qkv, g_qkv);
    cudaGetSymbolAddress((void**)&u,   g_u);
    cudaGetSymbolAddress((void**)&a,   g_a);
    cudaGetSymbolAddress((void**)&bb,  g_b);

    // 1: weight prep + zero attn/scale
    k_prep<<<1193, 256>>>(qkv_w, p1w, c1w, p2w, ow, offw, dcnw, c1b, dcnb);
    // 2: qkv projection (channel-split, 2 halves)
    k_qkv<<<dim3(256, NB), 256>>>(x, qkv);
    // 3: gram + sumsq
    k_gram<<<dim3(128, NB * 4), 256>>>();
    // 4: softmax + attn@v + LN1 + proj1/gelu (channel-split)
    k_xca_ln_p1<<<dim3(256, NB), 256>>>(temp, nw, nb, p1b);
    // 5: depthwise 5^3
    k_dw5<<<dim3(16, NB * 64), 256>>>(u, c0w, c0b, a);
    // 6: depthwise 7^3 dil 3
    k_dw7<<<dim3(12, NB * 64), 256>>>(a, cspw, cspb, bb);
    // 7: channels-last bf16 copy
    k_to_cl<<<dim3(512, NB), 256>>>(bb);
    // 8: fused offsets conv + deformable conv (coalesced gather + bf16 tensor cores)
    k_offdcn_mma<<<dim3(256, NB), 256>>>(offb);
    // 9: conv1*u then proj2+shortcut (channel-split)
    k_c1p2<<<dim3(256, NB), 256>>>(p2b);
    // 10: permute + LN2 + output projection (channel-split)
    k_final<<<dim3(4, NB * 64), 256>>>(n2w, n2b, obias, out);
}